// round 12
// baseline (speedup 1.0000x reference)
#include <cuda_runtime.h>
#include <cuda_fp16.h>
#include <math.h>
#include <stdint.h>

#define H 512
#define BB 32
#define SS 128
#define TT 512
#define NHEAD 8
#define DHD 64
#define NL 4
#define FF 2048
#define NOUT 102
#define NJ 50

// ---------------- scratch ----------------
__device__ __half g_memh[BB * SS * H];
__device__ __half g_m[BB * SS * H];
__device__ __half g_mem[BB * TT * H];
__device__ float  g_x[BB * TT * H];
__device__ __half g_xh[BB * TT * H];
__device__ __half g_h[BB * TT * H];
__device__ __half g_qkv[BB * TT * 3 * H];
__device__ __half g_att[BB * TT * H];
__device__ __half g_ff[BB * TT * FF];
__device__ float  g_head[BB * TT * NOUT];
__device__ float  g_pe[TT * H];
__device__ __half g_convTh[4 * H * H];
__device__ __half g_inwh[H * H];
__device__ __half g_outwh[NOUT * H];
__device__ __half g_wth[16777216];

#define WOFF_SAIN  0
#define WOFF_SAOUT 3145728
#define WOFF_CAIN  4194304
#define WOFF_CAOUT 7340032
#define WOFF_FF1   8388608
#define WOFF_FF2   12582912

__constant__ int PAR[NJ] = {
    -1, 0, 1, 2, 3, 1, 5, 6, 1,
    4, 9, 10, 11,  4, 13, 14, 15,  4, 17, 18, 19,  4, 21, 22, 23,  4, 25, 26, 27,
    7, 29, 30, 31, 7, 33, 34, 35,  7, 37, 38, 39,  7, 41, 42, 43,  7, 45, 46, 47,
    8
};

#define EPI_BIAS 2
#define EPI_BIAS_RES 3
#define EPI_BIAS_GELU 4
#define EPI_CONV 5

// ---------------- ptx helpers ----------------
__device__ __forceinline__ void cp16(uint32_t dst, const void* src)
{
    asm volatile("cp.async.cg.shared.global [%0], [%1], 16;\n" :: "r"(dst), "l"(src));
}
__device__ __forceinline__ void cp16z(uint32_t dst, const void* src, bool p)
{
    int sz = p ? 16 : 0;
    asm volatile("cp.async.cg.shared.global [%0], [%1], 16, %2;\n"
                 :: "r"(dst), "l"(src), "r"(sz));
}
__device__ __forceinline__ void cpcommit()
{
    asm volatile("cp.async.commit_group;\n" ::: "memory");
}
template <int W>
__device__ __forceinline__ void cpwait()
{
    asm volatile("cp.async.wait_group %0;\n" :: "n"(W) : "memory");
}
__device__ __forceinline__ void mma16(float* d, const uint32_t* a, const uint32_t* b)
{
    asm volatile(
        "mma.sync.aligned.m16n8k16.row.col.f32.f16.f16.f32 "
        "{%0,%1,%2,%3}, {%4,%5,%6,%7}, {%8,%9}, {%0,%1,%2,%3};\n"
        : "+f"(d[0]), "+f"(d[1]), "+f"(d[2]), "+f"(d[3])
        : "r"(a[0]), "r"(a[1]), "r"(a[2]), "r"(a[3]), "r"(b[0]), "r"(b[1]));
}
__device__ __forceinline__ void ldsm4(uint32_t* r, uint32_t addr)
{
    asm volatile("ldmatrix.sync.aligned.m8n8.x4.shared.b16 {%0,%1,%2,%3}, [%4];\n"
                 : "=r"(r[0]), "=r"(r[1]), "=r"(r[2]), "=r"(r[3]) : "r"(addr));
}
__device__ __forceinline__ void ldsm2t(uint32_t* r, uint32_t addr)
{
    asm volatile("ldmatrix.sync.aligned.m8n8.x2.trans.shared.b16 {%0,%1}, [%2];\n"
                 : "=r"(r[0]), "=r"(r[1]) : "r"(addr));
}

// ---------------- fp16 tensor-core GEMM: 128 threads, warp tile 64x64 ----------------
// C[r,c] = sum_k A[r,k] * B[c,k]; QS: scale cols < H by 1/8 (q projections).
template <int EPI, bool HOUT, bool QS>
__global__ void __launch_bounds__(128, 2) gemm10(
    const __half* __restrict__ A, const __half* __restrict__ Bm,
    const float* __restrict__ bias, const float* __restrict__ resid,
    void* __restrict__ C,
    int M, int N, int K, int lda, int ldb, int ldc,
    long sBh, int nh)
{
    constexpr int BM = 128, BN_ = 128, BK = 32;
    constexpr int LDE = BK + 8;               // 40 halves pitch
    constexpr int STGH = BM * LDE * 2;        // halves per stage (A+B)
    constexpr int CH = BM * BK / 8 / 128;     // 4 chunks per thread per operand

    extern __shared__ char smc[];
    const uint32_t smu = (uint32_t)__cvta_generic_to_shared(smc);

    const int z = blockIdx.z;
    const int hh = z % nh;
    Bm += (long)hh * sBh;

    const int row0 = blockIdx.y * BM;
    const int col0 = blockIdx.x * BN_;
    const int tid = threadIdx.x;
    const int warp = tid >> 5;                // 0..3
    const int lane = tid & 31;
    const int wm = warp >> 1;                 // 0..1
    const int wn = warp & 1;                  // 0..1
    const int gid = lane >> 2;
    const int tig = lane & 3;
    const int l15 = lane & 15;
    const int ah = (lane >> 4) << 3;          // 0 or 8 halves (k-half select)

    float acc[4][8][4];
#pragma unroll
    for (int i = 0; i < 4; i++)
#pragma unroll
        for (int j = 0; j < 8; j++)
#pragma unroll
            for (int q = 0; q < 4; q++) acc[i][j][q] = 0.f;

    auto cpTile = [&](int k0, int st) {
        uint32_t abase = smu + (uint32_t)(st * STGH) * 2;
#pragma unroll
        for (int l = 0; l < CH; l++) {
            int idx = l * 128 + tid;
            int r = idx >> 2;
            int cq = (idx & 3) * 8;
            cp16(abase + (uint32_t)(r * LDE + cq) * 2,
                 A + (long)(row0 + r) * lda + k0 + cq);
        }
        uint32_t bbase = abase + (uint32_t)(BM * LDE) * 2;
#pragma unroll
        for (int l = 0; l < CH; l++) {
            int idx = l * 128 + tid;
            int n = idx >> 2;
            int cq = (idx & 3) * 8;
            cp16z(bbase + (uint32_t)(n * LDE + cq) * 2,
                  Bm + (long)(col0 + n) * ldb + k0 + cq,
                  (col0 + n) < N);
        }
        cpcommit();
    };

    auto compute = [&](int st) {
        const uint32_t pAu = smu + (uint32_t)(st * STGH) * 2;
        const uint32_t pBu = pAu + (uint32_t)(BM * LDE) * 2;
#pragma unroll
        for (int ks = 0; ks < 2; ks++) {
            const int k = ks * 16;
            uint32_t af[4][4], bf[8][2];
#pragma unroll
            for (int mi = 0; mi < 4; mi++) {
                int r0 = wm * 64 + mi * 16 + l15;
                ldsm4(af[mi], pAu + (uint32_t)(r0 * LDE + k + ah) * 2);
            }
#pragma unroll
            for (int pb = 0; pb < 4; pb++) {
                uint32_t q[4];
                int n0 = wn * 64 + pb * 16 + l15;
                ldsm4(q, pBu + (uint32_t)(n0 * LDE + k + ah) * 2);
                bf[pb * 2][0] = q[0];     bf[pb * 2][1] = q[2];
                bf[pb * 2 + 1][0] = q[1]; bf[pb * 2 + 1][1] = q[3];
            }
#pragma unroll
            for (int mi = 0; mi < 4; mi++)
#pragma unroll
                for (int ni = 0; ni < 8; ni++)
                    mma16(acc[mi][ni], af[mi], bf[ni]);
        }
    };

    const int nt = K / BK;
    cpTile(0, 0);
    cpTile(BK, 1);
    int st = 0;
    for (int t = 0; t < nt; t++) {
        if (t < nt - 1) cpwait<1>(); else cpwait<0>();
        __syncthreads();
        if (t + 2 < nt) {
            int st2 = st + 2; if (st2 >= 3) st2 -= 3;
            cpTile((t + 2) * BK, st2);
        }
        compute(st);
        if (++st == 3) st = 0;
    }

    auto emit2 = [&](int r, int c, float v0, float v1) {
        v0 += bias[c];
        v1 += bias[c + 1];
        if (QS && c < H) { v0 *= 0.125f; v1 *= 0.125f; }
        if (EPI == EPI_BIAS_GELU) {
            v0 = 0.5f * v0 * (1.f + erff(v0 * 0.70710678118654752f));
            v1 = 0.5f * v1 * (1.f + erff(v1 * 0.70710678118654752f));
        }
        long idx;
        if (EPI == EPI_CONV) {
            int b_ = r >> 7;
            int s_ = r & 127;
            int t_ = s_ * 4 + hh;
            float2 rv = *(const float2*)&resid[t_ * H + c];
            v0 += rv.x; v1 += rv.y;
            idx = ((long)b_ * TT + t_) * ldc + c;
        } else {
            idx = (long)r * ldc + c;
            if (EPI == EPI_BIAS_RES) {
                float2 rv = *(const float2*)&resid[idx];
                v0 += rv.x; v1 += rv.y;
            }
        }
        if (HOUT) *(__half2*)((__half*)C + idx) = __floats2half2_rn(v0, v1);
        else      *(float2*)((float*)C + idx) = make_float2(v0, v1);
    };

#pragma unroll
    for (int mi = 0; mi < 4; mi++) {
        int r0 = row0 + wm * 64 + mi * 16 + gid;
#pragma unroll
        for (int ni = 0; ni < 8; ni++) {
            int c0 = col0 + wn * 64 + ni * 8 + tig * 2;
            if (c0 < N) {
                emit2(r0,     c0, acc[mi][ni][0], acc[mi][ni][1]);
                emit2(r0 + 8, c0, acc[mi][ni][2], acc[mi][ni][3]);
            }
        }
    }
}

// ---------------- fused flash attention (fp16 MMA, KV double-buffered) ----------------
#define FAB_Q 0
#define FAB_K0 18432
#define FAB_V0 55296
#define FAB_KVS 18432
#define FAB_P 92160
#define FAB_RED 126976
#define FAB_M 129024
#define FAB_L 129536
#define FAB_AL 130048
#define FA_BYTES 130560

__global__ void __launch_bounds__(256, 1) fattn_k(
    const __half* __restrict__ qkv, __half* __restrict__ att)
{
    extern __shared__ char smc[];
    __half* sP = (__half*)(smc + FAB_P);
    float* sRed = (float*)(smc + FAB_RED);
    float* sM = (float*)(smc + FAB_M);
    float* sL = (float*)(smc + FAB_L);
    float* sAl = (float*)(smc + FAB_AL);
    const uint32_t smu = (uint32_t)__cvta_generic_to_shared(smc);

    const int z = blockIdx.y;
    const int bb = z >> 3, hh = z & 7;
    const int q0 = blockIdx.x * 128;
    const long base = (long)bb * TT * 3 * H + (long)hh * DHD;

    const int tid = threadIdx.x;
    const int warp = tid >> 5, lane = tid & 31;
    const int wm = warp >> 2, wn = warp & 3;
    const int gid = lane >> 2, tig = lane & 3;
    const int l15 = lane & 15;
    const int ah = (lane >> 4) << 3;

#pragma unroll
    for (int l = 0; l < 4; l++) {
        int idx = l * 256 + tid;
        int r = idx >> 3, c8 = (idx & 7) * 8;
        cp16(smu + FAB_Q + (uint32_t)(r * 72 + c8) * 2,
             qkv + base + (long)(q0 + r) * (3 * H) + c8);
    }
    cpcommit();
#pragma unroll
    for (int l = 0; l < 4; l++) {
        int idx = l * 256 + tid;
        int r = idx >> 3, c8 = (idx & 7) * 8;
        long row = (long)r * (3 * H);
        cp16(smu + FAB_K0 + (uint32_t)(r * 72 + c8) * 2, qkv + base + H + row + c8);
        cp16(smu + FAB_V0 + (uint32_t)(r * 72 + c8) * 2, qkv + base + 2 * H + row + c8);
    }
    cpcommit();
    cpwait<1>();

    if (tid < 128) { sM[tid] = -1e30f; sL[tid] = 0.f; }

    float oacc[4][2][4];
#pragma unroll
    for (int mi = 0; mi < 4; mi++)
#pragma unroll
        for (int ni = 0; ni < 2; ni++)
#pragma unroll
            for (int q = 0; q < 4; q++) oacc[mi][ni][q] = 0.f;

    for (int j = 0; j < 4; j++) {
        __syncthreads();
        if (j < 3) {
            const uint32_t dK = smu + FAB_K0 + (uint32_t)(((j + 1) & 1) * FAB_KVS);
            const uint32_t dV = smu + FAB_V0 + (uint32_t)(((j + 1) & 1) * FAB_KVS);
#pragma unroll
            for (int l = 0; l < 4; l++) {
                int idx = l * 256 + tid;
                int r = idx >> 3, c8 = (idx & 7) * 8;
                long row = (long)((j + 1) * 128 + r) * (3 * H);
                cp16(dK + (uint32_t)(r * 72 + c8) * 2, qkv + base + H + row + c8);
                cp16(dV + (uint32_t)(r * 72 + c8) * 2, qkv + base + 2 * H + row + c8);
            }
            cpcommit();
            cpwait<1>();
        } else {
            cpwait<0>();
        }
        __syncthreads();

        const uint32_t KB = smu + FAB_K0 + (uint32_t)((j & 1) * FAB_KVS);
        const uint32_t VB = smu + FAB_V0 + (uint32_t)((j & 1) * FAB_KVS);

        float sacc[4][4][4];
#pragma unroll
        for (int mi = 0; mi < 4; mi++)
#pragma unroll
            for (int ni = 0; ni < 4; ni++)
#pragma unroll
                for (int q = 0; q < 4; q++) sacc[mi][ni][q] = 0.f;
#pragma unroll
        for (int ks = 0; ks < 4; ks++) {
            const int k = ks * 16;
            uint32_t af[4][4], bf[4][2];
#pragma unroll
            for (int mi = 0; mi < 4; mi++) {
                int r0 = wm * 64 + mi * 16 + l15;
                ldsm4(af[mi], smu + FAB_Q + (uint32_t)(r0 * 72 + k + ah) * 2);
            }
#pragma unroll
            for (int pb = 0; pb < 2; pb++) {
                uint32_t q[4];
                int n0 = wn * 32 + pb * 16 + l15;
                ldsm4(q, KB + (uint32_t)(n0 * 72 + k + ah) * 2);
                bf[pb * 2][0] = q[0];     bf[pb * 2][1] = q[2];
                bf[pb * 2 + 1][0] = q[1]; bf[pb * 2 + 1][1] = q[3];
            }
#pragma unroll
            for (int mi = 0; mi < 4; mi++)
#pragma unroll
                for (int ni = 0; ni < 4; ni++)
                    mma16(sacc[mi][ni], af[mi], bf[ni]);
        }

#pragma unroll
        for (int mi = 0; mi < 4; mi++) {
            float r0m = -1e30f, r1m = -1e30f;
#pragma unroll
            for (int ni = 0; ni < 4; ni++) {
                r0m = fmaxf(r0m, fmaxf(sacc[mi][ni][0], sacc[mi][ni][1]));
                r1m = fmaxf(r1m, fmaxf(sacc[mi][ni][2], sacc[mi][ni][3]));
            }
            r0m = fmaxf(r0m, __shfl_xor_sync(0xffffffffu, r0m, 1));
            r0m = fmaxf(r0m, __shfl_xor_sync(0xffffffffu, r0m, 2));
            r1m = fmaxf(r1m, __shfl_xor_sync(0xffffffffu, r1m, 1));
            r1m = fmaxf(r1m, __shfl_xor_sync(0xffffffffu, r1m, 2));
            if (tig == 0) {
                int r0 = wm * 64 + mi * 16 + gid;
                sRed[wn * 128 + r0] = r0m;
                sRed[wn * 128 + r0 + 8] = r1m;
            }
        }
        __syncthreads();
        if (tid < 128) {
            float mt = fmaxf(fmaxf(sRed[tid], sRed[128 + tid]),
                             fmaxf(sRed[256 + tid], sRed[384 + tid]));
            float mo = sM[tid];
            float mn = fmaxf(mo, mt);
            sAl[tid] = __expf(mo - mn);
            sM[tid] = mn;
        }
        __syncthreads();

#pragma unroll
        for (int mi = 0; mi < 4; mi++) {
            int r0 = wm * 64 + mi * 16 + gid;
            float m0 = sM[r0], m1 = sM[r0 + 8];
            float rs0 = 0.f, rs1 = 0.f;
#pragma unroll
            for (int ni = 0; ni < 4; ni++) {
                int c0 = wn * 32 + ni * 8 + tig * 2;
                float p00 = __expf(sacc[mi][ni][0] - m0);
                float p01 = __expf(sacc[mi][ni][1] - m0);
                float p10 = __expf(sacc[mi][ni][2] - m1);
                float p11 = __expf(sacc[mi][ni][3] - m1);
                rs0 += p00 + p01;
                rs1 += p10 + p11;
                *(__half2*)&sP[r0 * 136 + c0] = __floats2half2_rn(p00, p01);
                *(__half2*)&sP[(r0 + 8) * 136 + c0] = __floats2half2_rn(p10, p11);
            }
            rs0 += __shfl_xor_sync(0xffffffffu, rs0, 1);
            rs0 += __shfl_xor_sync(0xffffffffu, rs0, 2);
            rs1 += __shfl_xor_sync(0xffffffffu, rs1, 1);
            rs1 += __shfl_xor_sync(0xffffffffu, rs1, 2);
            if (tig == 0) {
                sRed[wn * 128 + r0] = rs0;
                sRed[wn * 128 + r0 + 8] = rs1;
            }
        }
        __syncthreads();
        if (tid < 128) {
            sL[tid] = sL[tid] * sAl[tid] +
                      (sRed[tid] + sRed[128 + tid]) + (sRed[256 + tid] + sRed[384 + tid]);
        }

#pragma unroll
        for (int mi = 0; mi < 4; mi++) {
            int r0 = wm * 64 + mi * 16 + gid;
            float a0 = sAl[r0], a1 = sAl[r0 + 8];
#pragma unroll
            for (int ni = 0; ni < 2; ni++) {
                oacc[mi][ni][0] *= a0;
                oacc[mi][ni][1] *= a0;
                oacc[mi][ni][2] *= a1;
                oacc[mi][ni][3] *= a1;
            }
        }

#pragma unroll
        for (int ks = 0; ks < 8; ks++) {
            const int k = ks * 16;
            uint32_t af[4][4], bf[2][2];
#pragma unroll
            for (int mi = 0; mi < 4; mi++) {
                int r0 = wm * 64 + mi * 16 + l15;
                ldsm4(af[mi], smu + FAB_P + (uint32_t)(r0 * 136 + k + ah) * 2);
            }
#pragma unroll
            for (int ni = 0; ni < 2; ni++) {
                int n0 = wn * 16 + ni * 8;
                ldsm2t(bf[ni], VB + (uint32_t)((k + l15) * 72 + n0) * 2);
            }
#pragma unroll
            for (int mi = 0; mi < 4; mi++)
#pragma unroll
                for (int ni = 0; ni < 2; ni++)
                    mma16(oacc[mi][ni], af[mi], bf[ni]);
        }
    }
    __syncthreads();

#pragma unroll
    for (int mi = 0; mi < 4; mi++) {
        int r0 = wm * 64 + mi * 16 + gid;
        float i0 = 1.f / sL[r0], i1 = 1.f / sL[r0 + 8];
        long o0 = ((long)bb * TT + q0 + r0) * H + hh * DHD;
        long o1 = ((long)bb * TT + q0 + r0 + 8) * H + hh * DHD;
#pragma unroll
        for (int ni = 0; ni < 2; ni++) {
            int c0 = wn * 16 + ni * 8 + tig * 2;
            *(__half2*)&att[o0 + c0] = __floats2half2_rn(oacc[mi][ni][0] * i0, oacc[mi][ni][1] * i0);
            *(__half2*)&att[o1 + c0] = __floats2half2_rn(oacc[mi][ni][2] * i1, oacc[mi][ni][3] * i1);
        }
    }
}

// ---------------- LayerNorm: fp32 in, fp16 out ----------------
__global__ void ln_k(const float* __restrict__ x, const float* __restrict__ g,
                     const float* __restrict__ b, __half* __restrict__ o)
{
    long row = blockIdx.x;
    int t = threadIdx.x;
    float4 v = ((const float4*)(x + row * H))[t];
    float s = v.x + v.y + v.z + v.w;
    float ss = v.x * v.x + v.y * v.y + v.z * v.z + v.w * v.w;
#pragma unroll
    for (int off = 16; off; off >>= 1) {
        s += __shfl_xor_sync(0xffffffffu, s, off);
        ss += __shfl_xor_sync(0xffffffffu, ss, off);
    }
    __shared__ float sm0[4], sm1[4];
    int w = t >> 5;
    if ((t & 31) == 0) { sm0[w] = s; sm1[w] = ss; }
    __syncthreads();
    s = sm0[0] + sm0[1] + sm0[2] + sm0[3];
    ss = sm1[0] + sm1[1] + sm1[2] + sm1[3];
    float mean = s * (1.f / H);
    float var = ss * (1.f / H) - mean * mean;
    float rstd = rsqrtf(var + 1e-5f);
    float4 gg = ((const float4*)g)[t];
    float4 bb4 = ((const float4*)b)[t];
    __half2* op = (__half2*)(o + row * H);
    op[t * 2]     = __floats2half2_rn((v.x - mean) * rstd * gg.x + bb4.x,
                                      (v.y - mean) * rstd * gg.y + bb4.y);
    op[t * 2 + 1] = __floats2half2_rn((v.z - mean) * rstd * gg.z + bb4.z,
                                      (v.w - mean) * rstd * gg.w + bb4.w);
}

// ---------------- misc kernels ----------------
__global__ void cvth_k(const float* __restrict__ in, __half* __restrict__ out, int n4)
{
    int i = blockIdx.x * blockDim.x + threadIdx.x;
    if (i >= n4) return;
    float4 v = ((const float4*)in)[i];
    ((__half2*)out)[i * 2]     = __floats2half2_rn(v.x, v.y);
    ((__half2*)out)[i * 2 + 1] = __floats2half2_rn(v.z, v.w);
}

__global__ void pe_k(float* __restrict__ pe)
{
    int t = blockIdx.x;
    int i = threadIdx.x;
    float div = expf(-(float)(2 * i) * (logf(10000.f) / (float)H));
    float a = (float)t * div;
    pe[t * H + 2 * i] = sinf(a);
    pe[t * H + 2 * i + 1] = cosf(a);
}

__global__ void convT_k(const float* __restrict__ w, __half* __restrict__ o)
{
    int idx = blockIdx.x * blockDim.x + threadIdx.x;
    if (idx >= 4 * H * H) return;
    int k = idx / (H * H);
    int d = (idx / H) % H;
    int c = idx % H;
    o[idx] = __float2half_rn(w[c * H * 4 + d * 4 + k]);
}

__global__ void xinit_k(const float* __restrict__ qe, const float* __restrict__ pe,
                        float* __restrict__ x)
{
    long i = blockIdx.x * (long)blockDim.x + threadIdx.x;
    if (i >= (long)BB * TT * H) return;
    int td = (int)(i % (TT * H));
    x[i] = qe[td] + pe[td];
}

__global__ void kin_k(const float* __restrict__ ho, float* __restrict__ out)
{
    int row = blockIdx.x * blockDim.x + threadIdx.x;
    if (row >= BB * TT) return;
    const float* r = ho + (long)row * NOUT;
    float* o = out + (long)row * (3 * NJ);
    float gx[NJ], px[NJ], py[NJ];
    gx[0] = 0.f;
    px[0] = r[100];
    py[0] = r[101];
    o[0] = px[0]; o[1] = py[0]; o[2] = 1.f;
    for (int j = 1; j < NJ; j++) {
        int pa = PAR[j];
        float gg = gx[pa] + r[j];
        gx[j] = gg;
        float s = r[50 + j];
        float sn, cs;
        sincosf(gg, &sn, &cs);
        px[j] = px[pa] + cs * s;
        py[j] = py[pa] + sn * s;
        o[j * 3 + 0] = px[j];
        o[j * 3 + 1] = py[j];
        o[j * 3 + 2] = 1.f;
    }
}

// ---------------- launcher ----------------
static inline dim3 gg128(int M, int N, int bz = 1)
{
    return dim3((N + 127) / 128, (M + 127) / 128, bz);
}

#define SMEM_G8 61440

extern "C" void kernel_launch(void* const* d_in, const int* in_sizes, int n_in,
                              void* d_out, int out_size)
{
    const float* memory   = (const float*)d_in[0];
    const float* in_w     = (const float*)d_in[1];
    const float* in_b     = (const float*)d_in[2];
    const float* conv_w   = (const float*)d_in[3];
    const float* conv_b   = (const float*)d_in[4];
    const float* qemb     = (const float*)d_in[5];
    const float* sa_in_w  = (const float*)d_in[6];
    const float* sa_in_b  = (const float*)d_in[7];
    const float* sa_out_w = (const float*)d_in[8];
    const float* sa_out_b = (const float*)d_in[9];
    const float* ca_in_w  = (const float*)d_in[10];
    const float* ca_in_b  = (const float*)d_in[11];
    const float* ca_out_w = (const float*)d_in[12];
    const float* ca_out_b = (const float*)d_in[13];
    const float* ln1_g    = (const float*)d_in[14];
    const float* ln1_b    = (const float*)d_in[15];
    const float* ln2_g    = (const float*)d_in[16];
    const float* ln2_b    = (const float*)d_in[17];
    const float* ln3_g    = (const float*)d_in[18];
    const float* ln3_b    = (const float*)d_in[19];
    const float* ff1_w    = (const float*)d_in[20];
    const float* ff1_b    = (const float*)d_in[21];
    const float* ff2_w    = (const float*)d_in[22];
    const float* ff2_b    = (const float*)d_in[23];
    const float* out_w    = (const float*)d_in[24];
    const float* out_b    = (const float*)d_in[25];

    __half *memh_, *m_, *mem_, *xh_, *h_, *qkv_, *att_, *ff_, *cT_, *inwh_, *outwh_, *wt_;
    float *x_, *ho_, *pe_;
    cudaGetSymbolAddress((void**)&memh_, g_memh);
    cudaGetSymbolAddress((void**)&m_,    g_m);
    cudaGetSymbolAddress((void**)&mem_,  g_mem);
    cudaGetSymbolAddress((void**)&x_,    g_x);
    cudaGetSymbolAddress((void**)&xh_,   g_xh);
    cudaGetSymbolAddress((void**)&h_,    g_h);
    cudaGetSymbolAddress((void**)&qkv_,  g_qkv);
    cudaGetSymbolAddress((void**)&att_,  g_att);
    cudaGetSymbolAddress((void**)&ff_,   g_ff);
    cudaGetSymbolAddress((void**)&ho_,   g_head);
    cudaGetSymbolAddress((void**)&pe_,   g_pe);
    cudaGetSymbolAddress((void**)&cT_,   g_convTh);
    cudaGetSymbolAddress((void**)&inwh_, g_inwh);
    cudaGetSymbolAddress((void**)&outwh_,g_outwh);
    cudaGetSymbolAddress((void**)&wt_,   g_wth);

    cudaFuncSetAttribute(gemm10<EPI_BIAS,      true,  true >, cudaFuncAttributeMaxDynamicSharedMemorySize, SMEM_G8);
    cudaFuncSetAttribute(gemm10<EPI_BIAS,      true,  false>, cudaFuncAttributeMaxDynamicSharedMemorySize, SMEM_G8);
    cudaFuncSetAttribute(gemm10<EPI_CONV,      true,  false>, cudaFuncAttributeMaxDynamicSharedMemorySize, SMEM_G8);
    cudaFuncSetAttribute(gemm10<EPI_BIAS_RES,  false, false>, cudaFuncAttributeMaxDynamicSharedMemorySize, SMEM_G8);
    cudaFuncSetAttribute(gemm10<EPI_BIAS_GELU, true,  false>, cudaFuncAttributeMaxDynamicSharedMemorySize, SMEM_G8);
    cudaFuncSetAttribute(gemm10<EPI_BIAS,      false, false>, cudaFuncAttributeMaxDynamicSharedMemorySize, SMEM_G8);
    cudaFuncSetAttribute(fattn_k, cudaFuncAttributeMaxDynamicSharedMemorySize, FA_BYTES);

    // prep
    pe_k<<<TT, 256>>>(pe_);
    convT_k<<<(4 * H * H + 255) / 256, 256>>>(conv_w, cT_);
    cvth_k<<<(2097152 / 4 + 255) / 256, 256>>>(memory,   memh_,  2097152 / 4);
    cvth_k<<<(262144 / 4 + 255) / 256, 256>>>(in_w,      inwh_,  262144 / 4);
    cvth_k<<<(52224 / 4 + 255) / 256, 256>>>(out_w,      outwh_, 52224 / 4);
    cvth_k<<<(3145728 / 4 + 255) / 256, 256>>>(sa_in_w,  wt_ + WOFF_SAIN,  3145728 / 4);
    cvth_k<<<(1048576 / 4 + 255) / 256, 256>>>(sa_out_w, wt_ + WOFF_SAOUT, 1048576 / 4);
    cvth_k<<<(3145728 / 4 + 255) / 256, 256>>>(ca_in_w,  wt_ + WOFF_CAIN,  3145728 / 4);
    cvth_k<<<(1048576 / 4 + 255) / 256, 256>>>(ca_out_w, wt_ + WOFF_CAOUT, 1048576 / 4);
    cvth_k<<<(4194304 / 4 + 255) / 256, 256>>>(ff1_w,    wt_ + WOFF_FF1,   4194304 / 4);
    cvth_k<<<(4194304 / 4 + 255) / 256, 256>>>(ff2_w,    wt_ + WOFF_FF2,   4194304 / 4);

    // m = memory @ in_w^T + in_b
    gemm10<EPI_BIAS, true, false><<<gg128(BB * SS, H), 128, SMEM_G8>>>(
        memh_, inwh_, in_b, nullptr, m_,
        BB * SS, H, H, H, H, H, 0L, 1);

    // conv upsample (4 taps batched over z; tap = hh)
    gemm10<EPI_CONV, true, false><<<gg128(BB * SS, H, 4), 128, SMEM_G8>>>(
        m_, cT_, conv_b, pe_, mem_,
        BB * SS, H, H, H, H, H, (long)H * H, 4);

    xinit_k<<<(BB * TT * H + 255) / 256, 256>>>(qemb, pe_, x_);

    const dim3 fa_grid(TT / 128, BB * NHEAD);

    for (int l = 0; l < NL; l++) {
        // ======== self-attention ========
        ln_k<<<BB * TT, 128>>>(x_, ln1_g + l * H, ln1_b + l * H, h_);
        gemm10<EPI_BIAS, true, true><<<gg128(BB * TT, 3 * H), 128, SMEM_G8>>>(
            h_, wt_ + WOFF_SAIN + (long)l * 3 * H * H, sa_in_b + (long)l * 3 * H, nullptr, qkv_,
            BB * TT, 3 * H, H, H, H, 3 * H, 0L, 1);
        fattn_k<<<fa_grid, 256, FA_BYTES>>>(qkv_, att_);
        gemm10<EPI_BIAS_RES, false, false><<<gg128(BB * TT, H), 128, SMEM_G8>>>(
            att_, wt_ + WOFF_SAOUT + (long)l * H * H, sa_out_b + (long)l * H, x_, x_,
            BB * TT, H, H, H, H, H, 0L, 1);

        // ======== cross-attention ========
        ln_k<<<BB * TT, 128>>>(x_, ln2_g + l * H, ln2_b + l * H, h_);
        gemm10<EPI_BIAS, true, true><<<gg128(BB * TT, H), 128, SMEM_G8>>>(
            h_, wt_ + WOFF_CAIN + (long)l * 3 * H * H, ca_in_b + (long)l * 3 * H, nullptr, qkv_,
            BB * TT, H, H, H, H, 3 * H, 0L, 1);
        gemm10<EPI_BIAS, true, false><<<gg128(BB * TT, 2 * H), 128, SMEM_G8>>>(
            mem_, wt_ + WOFF_CAIN + (long)l * 3 * H * H + (long)H * H,
            ca_in_b + (long)l * 3 * H + H, nullptr, qkv_ + H,
            BB * TT, 2 * H, H, H, H, 3 * H, 0L, 1);
        fattn_k<<<fa_grid, 256, FA_BYTES>>>(qkv_, att_);
        gemm10<EPI_BIAS_RES, false, false><<<gg128(BB * TT, H), 128, SMEM_G8>>>(
            att_, wt_ + WOFF_CAOUT + (long)l * H * H, ca_out_b + (long)l * H, x_, x_,
            BB * TT, H, H, H, H, H, 0L, 1);

        // ======== FFN ========
        ln_k<<<BB * TT, 128>>>(x_, ln3_g + l * H, ln3_b + l * H, h_);
        gemm10<EPI_BIAS_GELU, true, false><<<gg128(BB * TT, FF), 128, SMEM_G8>>>(
            h_, wt_ + WOFF_FF1 + (long)l * FF * H, ff1_b + (long)l * FF, nullptr, ff_,
            BB * TT, FF, H, H, H, FF, 0L, 1);
        gemm10<EPI_BIAS_RES, false, false><<<gg128(BB * TT, H), 128, SMEM_G8>>>(
            ff_, wt_ + WOFF_FF2 + (long)l * H * FF, ff2_b + (long)l * H, x_, x_,
            BB * TT, H, FF, FF, FF, H, 0L, 1);
    }

    // head
    cvth_k<<<(16777216 / 4 + 255) / 256, 256>>>(x_, xh_, 16777216 / 4);
    gemm10<EPI_BIAS, false, false><<<gg128(BB * TT, NOUT), 128, SMEM_G8>>>(
        xh_, outwh_, out_b, nullptr, ho_,
        BB * TT, NOUT, H, H, H, NOUT, 0L, 1);

    kin_k<<<(BB * TT + 255) / 256, 256>>>(ho_, (float*)d_out);
}

// round 13
// speedup vs baseline: 1.0318x; 1.0318x over previous
#include <cuda_runtime.h>
#include <cuda_fp16.h>
#include <math.h>
#include <stdint.h>

#define H 512
#define BB 32
#define SS 128
#define TT 512
#define NHEAD 8
#define DHD 64
#define NL 4
#define FF 2048
#define NOUT 102
#define NJ 50

// ---------------- scratch ----------------
__device__ __half g_memh[BB * SS * H];
__device__ __half g_m[BB * SS * H];
__device__ __half g_mem[BB * TT * H];
__device__ float  g_x[BB * TT * H];
__device__ __half g_xh[BB * TT * H];
__device__ __half g_h[BB * TT * H];
__device__ __half g_qkv[BB * TT * 3 * H];
__device__ __half g_att[BB * TT * H];
__device__ __half g_ff[BB * TT * FF];
__device__ float  g_head[BB * TT * NOUT];
__device__ float  g_pe[TT * H];
__device__ __half g_convTh[4 * H * H];
__device__ __half g_inwh[H * H];
__device__ __half g_outwh[NOUT * H];
__device__ __half g_wth[16777216];

#define WOFF_SAIN  0
#define WOFF_SAOUT 3145728
#define WOFF_CAIN  4194304
#define WOFF_CAOUT 7340032
#define WOFF_FF1   8388608
#define WOFF_FF2   12582912

__constant__ int PAR[NJ] = {
    -1, 0, 1, 2, 3, 1, 5, 6, 1,
    4, 9, 10, 11,  4, 13, 14, 15,  4, 17, 18, 19,  4, 21, 22, 23,  4, 25, 26, 27,
    7, 29, 30, 31, 7, 33, 34, 35,  7, 37, 38, 39,  7, 41, 42, 43,  7, 45, 46, 47,
    8
};

#define EPI_BIAS 2
#define EPI_BIAS_RES 3
#define EPI_BIAS_GELU 4
#define EPI_CONV 5

// ---------------- ptx helpers ----------------
__device__ __forceinline__ void cp16(uint32_t dst, const void* src)
{
    asm volatile("cp.async.cg.shared.global [%0], [%1], 16;\n" :: "r"(dst), "l"(src));
}
__device__ __forceinline__ void cp16z(uint32_t dst, const void* src, bool p)
{
    int sz = p ? 16 : 0;
    asm volatile("cp.async.cg.shared.global [%0], [%1], 16, %2;\n"
                 :: "r"(dst), "l"(src), "r"(sz));
}
__device__ __forceinline__ void cpcommit()
{
    asm volatile("cp.async.commit_group;\n" ::: "memory");
}
template <int W>
__device__ __forceinline__ void cpwait()
{
    asm volatile("cp.async.wait_group %0;\n" :: "n"(W) : "memory");
}
__device__ __forceinline__ void mma16(float* d, const uint32_t* a, const uint32_t* b)
{
    asm volatile(
        "mma.sync.aligned.m16n8k16.row.col.f32.f16.f16.f32 "
        "{%0,%1,%2,%3}, {%4,%5,%6,%7}, {%8,%9}, {%0,%1,%2,%3};\n"
        : "+f"(d[0]), "+f"(d[1]), "+f"(d[2]), "+f"(d[3])
        : "r"(a[0]), "r"(a[1]), "r"(a[2]), "r"(a[3]), "r"(b[0]), "r"(b[1]));
}
__device__ __forceinline__ void ldsm4(uint32_t* r, uint32_t addr)
{
    asm volatile("ldmatrix.sync.aligned.m8n8.x4.shared.b16 {%0,%1,%2,%3}, [%4];\n"
                 : "=r"(r[0]), "=r"(r[1]), "=r"(r[2]), "=r"(r[3]) : "r"(addr));
}
__device__ __forceinline__ void ldsm2t(uint32_t* r, uint32_t addr)
{
    asm volatile("ldmatrix.sync.aligned.m8n8.x2.trans.shared.b16 {%0,%1}, [%2];\n"
                 : "=r"(r[0]), "=r"(r[1]) : "r"(addr));
}

// ---------------- fp16 tensor-core GEMM: 3-stage, m16n8k16, 256 thr (round-11 layout) ----------------
// C[r,c] = sum_k A[r,k] * B[c,k]; QS: scale cols < H by 1/8 (q projections).
// DUAL: additionally write fp16 copy to C2 (for BIAS_RES feeding head).
template <int EPI, bool HOUT, bool QS, bool DUAL>
__global__ void __launch_bounds__(256, 2) gemm8(
    const __half* __restrict__ A, const __half* __restrict__ Bm,
    const float* __restrict__ bias, const float* __restrict__ resid,
    void* __restrict__ C, __half* __restrict__ C2,
    int M, int N, int K, int lda, int ldb, int ldc,
    long sBh, int nh)
{
    constexpr int BM = 128, BN_ = 128, BK = 32;
    constexpr int LDE = BK + 8;
    constexpr int STGH = BM * LDE * 2;
    constexpr int CH = BM * BK / 8 / 256;

    extern __shared__ char smc[];
    const uint32_t smu = (uint32_t)__cvta_generic_to_shared(smc);

    const int z = blockIdx.z;
    const int hh = z % nh;
    Bm += (long)hh * sBh;

    const int row0 = blockIdx.y * BM;
    const int col0 = blockIdx.x * BN_;
    const int tid = threadIdx.x;
    const int warp = tid >> 5;
    const int lane = tid & 31;
    const int wm = warp >> 2;
    const int wn = warp & 3;
    const int gid = lane >> 2;
    const int tig = lane & 3;
    const int l15 = lane & 15;
    const int ah = (lane >> 4) << 3;

    float acc[4][4][4];
#pragma unroll
    for (int i = 0; i < 4; i++)
#pragma unroll
        for (int j = 0; j < 4; j++)
#pragma unroll
            for (int q = 0; q < 4; q++) acc[i][j][q] = 0.f;

    auto cpTile = [&](int k0, int st) {
        uint32_t abase = smu + (uint32_t)(st * STGH) * 2;
#pragma unroll
        for (int l = 0; l < CH; l++) {
            int idx = l * 256 + tid;
            int r = idx >> 2;
            int cq = (idx & 3) * 8;
            cp16(abase + (uint32_t)(r * LDE + cq) * 2,
                 A + (long)(row0 + r) * lda + k0 + cq);
        }
        uint32_t bbase = abase + (uint32_t)(BM * LDE) * 2;
#pragma unroll
        for (int l = 0; l < CH; l++) {
            int idx = l * 256 + tid;
            int n = idx >> 2;
            int cq = (idx & 3) * 8;
            cp16z(bbase + (uint32_t)(n * LDE + cq) * 2,
                  Bm + (long)(col0 + n) * ldb + k0 + cq,
                  (col0 + n) < N);
        }
        cpcommit();
    };

    auto compute = [&](int st) {
        const uint32_t pAu = smu + (uint32_t)(st * STGH) * 2;
        const uint32_t pBu = pAu + (uint32_t)(BM * LDE) * 2;
#pragma unroll
        for (int ks = 0; ks < 2; ks++) {
            const int k = ks * 16;
            uint32_t af[4][4], bf[4][2];
#pragma unroll
            for (int mi = 0; mi < 4; mi++) {
                int r0 = wm * 64 + mi * 16 + l15;
                ldsm4(af[mi], pAu + (uint32_t)(r0 * LDE + k + ah) * 2);
            }
#pragma unroll
            for (int pb = 0; pb < 2; pb++) {
                uint32_t q[4];
                int n0 = wn * 32 + pb * 16 + l15;
                ldsm4(q, pBu + (uint32_t)(n0 * LDE + k + ah) * 2);
                bf[pb * 2][0] = q[0];     bf[pb * 2][1] = q[2];
                bf[pb * 2 + 1][0] = q[1]; bf[pb * 2 + 1][1] = q[3];
            }
#pragma unroll
            for (int mi = 0; mi < 4; mi++)
#pragma unroll
                for (int ni = 0; ni < 4; ni++)
                    mma16(acc[mi][ni], af[mi], bf[ni]);
        }
    };

    const int nt = K / BK;
    cpTile(0, 0);
    cpTile(BK, 1);
    int st = 0;
    for (int t = 0; t < nt; t++) {
        if (t < nt - 1) cpwait<1>(); else cpwait<0>();
        __syncthreads();
        if (t + 2 < nt) {
            int st2 = st + 2; if (st2 >= 3) st2 -= 3;
            cpTile((t + 2) * BK, st2);
        }
        compute(st);
        if (++st == 3) st = 0;
    }

    auto emit2 = [&](int r, int c, float v0, float v1) {
        v0 += bias[c];
        v1 += bias[c + 1];
        if (QS && c < H) { v0 *= 0.125f; v1 *= 0.125f; }
        if (EPI == EPI_BIAS_GELU) {
            v0 = 0.5f * v0 * (1.f + erff(v0 * 0.70710678118654752f));
            v1 = 0.5f * v1 * (1.f + erff(v1 * 0.70710678118654752f));
        }
        long idx;
        if (EPI == EPI_CONV) {
            int b_ = r >> 7;
            int s_ = r & 127;
            int t_ = s_ * 4 + hh;
            float2 rv = *(const float2*)&resid[t_ * H + c];
            v0 += rv.x; v1 += rv.y;
            idx = ((long)b_ * TT + t_) * ldc + c;
        } else {
            idx = (long)r * ldc + c;
            if (EPI == EPI_BIAS_RES) {
                float2 rv = *(const float2*)&resid[idx];
                v0 += rv.x; v1 += rv.y;
            }
        }
        if (HOUT) *(__half2*)((__half*)C + idx) = __floats2half2_rn(v0, v1);
        else      *(float2*)((float*)C + idx) = make_float2(v0, v1);
        if (DUAL) *(__half2*)(C2 + idx) = __floats2half2_rn(v0, v1);
    };

#pragma unroll
    for (int mi = 0; mi < 4; mi++) {
        int r0 = row0 + wm * 64 + mi * 16 + gid;
#pragma unroll
        for (int ni = 0; ni < 4; ni++) {
            int c0 = col0 + wn * 32 + ni * 8 + tig * 2;
            if (c0 < N) {
                emit2(r0,     c0, acc[mi][ni][0], acc[mi][ni][1]);
                emit2(r0 + 8, c0, acc[mi][ni][2], acc[mi][ni][3]);
            }
        }
    }
}

// ---------------- fused flash attention (fp16 MMA, KV double-buffered) ----------------
#define FAB_Q 0
#define FAB_K0 18432
#define FAB_V0 55296
#define FAB_KVS 18432
#define FAB_P 92160
#define FAB_RED 126976
#define FAB_M 129024
#define FAB_L 129536
#define FAB_AL 130048
#define FA_BYTES 130560

__global__ void __launch_bounds__(256, 1) fattn_k(
    const __half* __restrict__ qkv, __half* __restrict__ att)
{
    extern __shared__ char smc[];
    __half* sP = (__half*)(smc + FAB_P);
    float* sRed = (float*)(smc + FAB_RED);
    float* sM = (float*)(smc + FAB_M);
    float* sL = (float*)(smc + FAB_L);
    float* sAl = (float*)(smc + FAB_AL);
    const uint32_t smu = (uint32_t)__cvta_generic_to_shared(smc);

    const int z = blockIdx.y;
    const int bb = z >> 3, hh = z & 7;
    const int q0 = blockIdx.x * 128;
    const long base = (long)bb * TT * 3 * H + (long)hh * DHD;

    const int tid = threadIdx.x;
    const int warp = tid >> 5, lane = tid & 31;
    const int wm = warp >> 2, wn = warp & 3;
    const int gid = lane >> 2, tig = lane & 3;
    const int l15 = lane & 15;
    const int ah = (lane >> 4) << 3;

#pragma unroll
    for (int l = 0; l < 4; l++) {
        int idx = l * 256 + tid;
        int r = idx >> 3, c8 = (idx & 7) * 8;
        cp16(smu + FAB_Q + (uint32_t)(r * 72 + c8) * 2,
             qkv + base + (long)(q0 + r) * (3 * H) + c8);
    }
    cpcommit();
#pragma unroll
    for (int l = 0; l < 4; l++) {
        int idx = l * 256 + tid;
        int r = idx >> 3, c8 = (idx & 7) * 8;
        long row = (long)r * (3 * H);
        cp16(smu + FAB_K0 + (uint32_t)(r * 72 + c8) * 2, qkv + base + H + row + c8);
        cp16(smu + FAB_V0 + (uint32_t)(r * 72 + c8) * 2, qkv + base + 2 * H + row + c8);
    }
    cpcommit();
    cpwait<1>();

    if (tid < 128) { sM[tid] = -1e30f; sL[tid] = 0.f; }

    float oacc[4][2][4];
#pragma unroll
    for (int mi = 0; mi < 4; mi++)
#pragma unroll
        for (int ni = 0; ni < 2; ni++)
#pragma unroll
            for (int q = 0; q < 4; q++) oacc[mi][ni][q] = 0.f;

    for (int j = 0; j < 4; j++) {
        __syncthreads();
        if (j < 3) {
            const uint32_t dK = smu + FAB_K0 + (uint32_t)(((j + 1) & 1) * FAB_KVS);
            const uint32_t dV = smu + FAB_V0 + (uint32_t)(((j + 1) & 1) * FAB_KVS);
#pragma unroll
            for (int l = 0; l < 4; l++) {
                int idx = l * 256 + tid;
                int r = idx >> 3, c8 = (idx & 7) * 8;
                long row = (long)((j + 1) * 128 + r) * (3 * H);
                cp16(dK + (uint32_t)(r * 72 + c8) * 2, qkv + base + H + row + c8);
                cp16(dV + (uint32_t)(r * 72 + c8) * 2, qkv + base + 2 * H + row + c8);
            }
            cpcommit();
            cpwait<1>();
        } else {
            cpwait<0>();
        }
        __syncthreads();

        const uint32_t KB = smu + FAB_K0 + (uint32_t)((j & 1) * FAB_KVS);
        const uint32_t VB = smu + FAB_V0 + (uint32_t)((j & 1) * FAB_KVS);

        float sacc[4][4][4];
#pragma unroll
        for (int mi = 0; mi < 4; mi++)
#pragma unroll
            for (int ni = 0; ni < 4; ni++)
#pragma unroll
                for (int q = 0; q < 4; q++) sacc[mi][ni][q] = 0.f;
#pragma unroll
        for (int ks = 0; ks < 4; ks++) {
            const int k = ks * 16;
            uint32_t af[4][4], bf[4][2];
#pragma unroll
            for (int mi = 0; mi < 4; mi++) {
                int r0 = wm * 64 + mi * 16 + l15;
                ldsm4(af[mi], smu + FAB_Q + (uint32_t)(r0 * 72 + k + ah) * 2);
            }
#pragma unroll
            for (int pb = 0; pb < 2; pb++) {
                uint32_t q[4];
                int n0 = wn * 32 + pb * 16 + l15;
                ldsm4(q, KB + (uint32_t)(n0 * 72 + k + ah) * 2);
                bf[pb * 2][0] = q[0];     bf[pb * 2][1] = q[2];
                bf[pb * 2 + 1][0] = q[1]; bf[pb * 2 + 1][1] = q[3];
            }
#pragma unroll
            for (int mi = 0; mi < 4; mi++)
#pragma unroll
                for (int ni = 0; ni < 4; ni++)
                    mma16(sacc[mi][ni], af[mi], bf[ni]);
        }

#pragma unroll
        for (int mi = 0; mi < 4; mi++) {
            float r0m = -1e30f, r1m = -1e30f;
#pragma unroll
            for (int ni = 0; ni < 4; ni++) {
                r0m = fmaxf(r0m, fmaxf(sacc[mi][ni][0], sacc[mi][ni][1]));
                r1m = fmaxf(r1m, fmaxf(sacc[mi][ni][2], sacc[mi][ni][3]));
            }
            r0m = fmaxf(r0m, __shfl_xor_sync(0xffffffffu, r0m, 1));
            r0m = fmaxf(r0m, __shfl_xor_sync(0xffffffffu, r0m, 2));
            r1m = fmaxf(r1m, __shfl_xor_sync(0xffffffffu, r1m, 1));
            r1m = fmaxf(r1m, __shfl_xor_sync(0xffffffffu, r1m, 2));
            if (tig == 0) {
                int r0 = wm * 64 + mi * 16 + gid;
                sRed[wn * 128 + r0] = r0m;
                sRed[wn * 128 + r0 + 8] = r1m;
            }
        }
        __syncthreads();
        if (tid < 128) {
            float mt = fmaxf(fmaxf(sRed[tid], sRed[128 + tid]),
                             fmaxf(sRed[256 + tid], sRed[384 + tid]));
            float mo = sM[tid];
            float mn = fmaxf(mo, mt);
            sAl[tid] = __expf(mo - mn);
            sM[tid] = mn;
        }
        __syncthreads();

#pragma unroll
        for (int mi = 0; mi < 4; mi++) {
            int r0 = wm * 64 + mi * 16 + gid;
            float m0 = sM[r0], m1 = sM[r0 + 8];
            float rs0 = 0.f, rs1 = 0.f;
#pragma unroll
            for (int ni = 0; ni < 4; ni++) {
                int c0 = wn * 32 + ni * 8 + tig * 2;
                float p00 = __expf(sacc[mi][ni][0] - m0);
                float p01 = __expf(sacc[mi][ni][1] - m0);
                float p10 = __expf(sacc[mi][ni][2] - m1);
                float p11 = __expf(sacc[mi][ni][3] - m1);
                rs0 += p00 + p01;
                rs1 += p10 + p11;
                *(__half2*)&sP[r0 * 136 + c0] = __floats2half2_rn(p00, p01);
                *(__half2*)&sP[(r0 + 8) * 136 + c0] = __floats2half2_rn(p10, p11);
            }
            rs0 += __shfl_xor_sync(0xffffffffu, rs0, 1);
            rs0 += __shfl_xor_sync(0xffffffffu, rs0, 2);
            rs1 += __shfl_xor_sync(0xffffffffu, rs1, 1);
            rs1 += __shfl_xor_sync(0xffffffffu, rs1, 2);
            if (tig == 0) {
                sRed[wn * 128 + r0] = rs0;
                sRed[wn * 128 + r0 + 8] = rs1;
            }
        }
        __syncthreads();
        if (tid < 128) {
            sL[tid] = sL[tid] * sAl[tid] +
                      (sRed[tid] + sRed[128 + tid]) + (sRed[256 + tid] + sRed[384 + tid]);
        }

#pragma unroll
        for (int mi = 0; mi < 4; mi++) {
            int r0 = wm * 64 + mi * 16 + gid;
            float a0 = sAl[r0], a1 = sAl[r0 + 8];
#pragma unroll
            for (int ni = 0; ni < 2; ni++) {
                oacc[mi][ni][0] *= a0;
                oacc[mi][ni][1] *= a0;
                oacc[mi][ni][2] *= a1;
                oacc[mi][ni][3] *= a1;
            }
        }

#pragma unroll
        for (int ks = 0; ks < 8; ks++) {
            const int k = ks * 16;
            uint32_t af[4][4], bf[2][2];
#pragma unroll
            for (int mi = 0; mi < 4; mi++) {
                int r0 = wm * 64 + mi * 16 + l15;
                ldsm4(af[mi], smu + FAB_P + (uint32_t)(r0 * 136 + k + ah) * 2);
            }
#pragma unroll
            for (int ni = 0; ni < 2; ni++) {
                int n0 = wn * 16 + ni * 8;
                ldsm2t(bf[ni], VB + (uint32_t)((k + l15) * 72 + n0) * 2);
            }
#pragma unroll
            for (int mi = 0; mi < 4; mi++)
#pragma unroll
                for (int ni = 0; ni < 2; ni++)
                    mma16(oacc[mi][ni], af[mi], bf[ni]);
        }
    }
    __syncthreads();

#pragma unroll
    for (int mi = 0; mi < 4; mi++) {
        int r0 = wm * 64 + mi * 16 + gid;
        float i0 = 1.f / sL[r0], i1 = 1.f / sL[r0 + 8];
        long o0 = ((long)bb * TT + q0 + r0) * H + hh * DHD;
        long o1 = ((long)bb * TT + q0 + r0 + 8) * H + hh * DHD;
#pragma unroll
        for (int ni = 0; ni < 2; ni++) {
            int c0 = wn * 16 + ni * 8 + tig * 2;
            *(__half2*)&att[o0 + c0] = __floats2half2_rn(oacc[mi][ni][0] * i0, oacc[mi][ni][1] * i0);
            *(__half2*)&att[o1 + c0] = __floats2half2_rn(oacc[mi][ni][2] * i1, oacc[mi][ni][3] * i1);
        }
    }
}

// ---------------- LayerNorm: fp32 in, fp16 out ----------------
__global__ void ln_k(const float* __restrict__ x, const float* __restrict__ g,
                     const float* __restrict__ b, __half* __restrict__ o)
{
    long row = blockIdx.x;
    int t = threadIdx.x;
    float4 v = ((const float4*)(x + row * H))[t];
    float s = v.x + v.y + v.z + v.w;
    float ss = v.x * v.x + v.y * v.y + v.z * v.z + v.w * v.w;
#pragma unroll
    for (int off = 16; off; off >>= 1) {
        s += __shfl_xor_sync(0xffffffffu, s, off);
        ss += __shfl_xor_sync(0xffffffffu, ss, off);
    }
    __shared__ float sm0[4], sm1[4];
    int w = t >> 5;
    if ((t & 31) == 0) { sm0[w] = s; sm1[w] = ss; }
    __syncthreads();
    s = sm0[0] + sm0[1] + sm0[2] + sm0[3];
    ss = sm1[0] + sm1[1] + sm1[2] + sm1[3];
    float mean = s * (1.f / H);
    float var = ss * (1.f / H) - mean * mean;
    float rstd = rsqrtf(var + 1e-5f);
    float4 gg = ((const float4*)g)[t];
    float4 bb4 = ((const float4*)b)[t];
    __half2* op = (__half2*)(o + row * H);
    op[t * 2]     = __floats2half2_rn((v.x - mean) * rstd * gg.x + bb4.x,
                                      (v.y - mean) * rstd * gg.y + bb4.y);
    op[t * 2 + 1] = __floats2half2_rn((v.z - mean) * rstd * gg.z + bb4.z,
                                      (v.w - mean) * rstd * gg.w + bb4.w);
}

// ---------------- misc kernels ----------------
__global__ void cvth_k(const float* __restrict__ in, __half* __restrict__ out, int n4)
{
    int stride = gridDim.x * blockDim.x;
    for (int i = blockIdx.x * blockDim.x + threadIdx.x; i < n4; i += stride) {
        float4 v = ((const float4*)in)[i];
        ((__half2*)out)[i * 2]     = __floats2half2_rn(v.x, v.y);
        ((__half2*)out)[i * 2 + 1] = __floats2half2_rn(v.z, v.w);
    }
}

__global__ void pe_k(float* __restrict__ pe)
{
    int t = blockIdx.x;
    int i = threadIdx.x;
    float div = expf(-(float)(2 * i) * (logf(10000.f) / (float)H));
    float a = (float)t * div;
    pe[t * H + 2 * i] = sinf(a);
    pe[t * H + 2 * i + 1] = cosf(a);
}

__global__ void convT_k(const float* __restrict__ w, __half* __restrict__ o)
{
    int idx = blockIdx.x * blockDim.x + threadIdx.x;
    if (idx >= 4 * H * H) return;
    int k = idx / (H * H);
    int d = (idx / H) % H;
    int c = idx % H;
    o[idx] = __float2half_rn(w[c * H * 4 + d * 4 + k]);
}

__global__ void xinit_k(const float* __restrict__ qe, const float* __restrict__ pe,
                        float* __restrict__ x)
{
    long i = blockIdx.x * (long)blockDim.x + threadIdx.x;
    if (i >= (long)BB * TT * H) return;
    int td = (int)(i % (TT * H));
    x[i] = qe[td] + pe[td];
}

__global__ void kin_k(const float* __restrict__ ho, float* __restrict__ out)
{
    int row = blockIdx.x * blockDim.x + threadIdx.x;
    if (row >= BB * TT) return;
    const float* r = ho + (long)row * NOUT;
    float* o = out + (long)row * (3 * NJ);
    float gx[NJ], px[NJ], py[NJ];
    gx[0] = 0.f;
    px[0] = r[100];
    py[0] = r[101];
    o[0] = px[0]; o[1] = py[0]; o[2] = 1.f;
    for (int j = 1; j < NJ; j++) {
        int pa = PAR[j];
        float gg = gx[pa] + r[j];
        gx[j] = gg;
        float s = r[50 + j];
        float sn, cs;
        sincosf(gg, &sn, &cs);
        px[j] = px[pa] + cs * s;
        py[j] = py[pa] + sn * s;
        o[j * 3 + 0] = px[j];
        o[j * 3 + 1] = py[j];
        o[j * 3 + 2] = 1.f;
    }
}

// ---------------- launcher ----------------
static inline dim3 gg128(int M, int N, int bz = 1)
{
    return dim3((N + 127) / 128, (M + 127) / 128, bz);
}

#define SMEM_G8 61440

extern "C" void kernel_launch(void* const* d_in, const int* in_sizes, int n_in,
                              void* d_out, int out_size)
{
    const float* memory   = (const float*)d_in[0];
    const float* in_w     = (const float*)d_in[1];
    const float* in_b     = (const float*)d_in[2];
    const float* conv_w   = (const float*)d_in[3];
    const float* conv_b   = (const float*)d_in[4];
    const float* qemb     = (const float*)d_in[5];
    const float* sa_in_w  = (const float*)d_in[6];
    const float* sa_in_b  = (const float*)d_in[7];
    const float* sa_out_w = (const float*)d_in[8];
    const float* sa_out_b = (const float*)d_in[9];
    const float* ca_in_w  = (const float*)d_in[10];
    const float* ca_in_b  = (const float*)d_in[11];
    const float* ca_out_w = (const float*)d_in[12];
    const float* ca_out_b = (const float*)d_in[13];
    const float* ln1_g    = (const float*)d_in[14];
    const float* ln1_b    = (const float*)d_in[15];
    const float* ln2_g    = (const float*)d_in[16];
    const float* ln2_b    = (const float*)d_in[17];
    const float* ln3_g    = (const float*)d_in[18];
    const float* ln3_b    = (const float*)d_in[19];
    const float* ff1_w    = (const float*)d_in[20];
    const float* ff1_b    = (const float*)d_in[21];
    const float* ff2_w    = (const float*)d_in[22];
    const float* ff2_b    = (const float*)d_in[23];
    const float* out_w    = (const float*)d_in[24];
    const float* out_b    = (const float*)d_in[25];

    __half *memh_, *m_, *mem_, *xh_, *h_, *qkv_, *att_, *ff_, *cT_, *inwh_, *outwh_, *wt_;
    float *x_, *ho_, *pe_;
    cudaGetSymbolAddress((void**)&memh_, g_memh);
    cudaGetSymbolAddress((void**)&m_,    g_m);
    cudaGetSymbolAddress((void**)&mem_,  g_mem);
    cudaGetSymbolAddress((void**)&x_,    g_x);
    cudaGetSymbolAddress((void**)&xh_,   g_xh);
    cudaGetSymbolAddress((void**)&h_,    g_h);
    cudaGetSymbolAddress((void**)&qkv_,  g_qkv);
    cudaGetSymbolAddress((void**)&att_,  g_att);
    cudaGetSymbolAddress((void**)&ff_,   g_ff);
    cudaGetSymbolAddress((void**)&ho_,   g_head);
    cudaGetSymbolAddress((void**)&pe_,   g_pe);
    cudaGetSymbolAddress((void**)&cT_,   g_convTh);
    cudaGetSymbolAddress((void**)&inwh_, g_inwh);
    cudaGetSymbolAddress((void**)&outwh_,g_outwh);
    cudaGetSymbolAddress((void**)&wt_,   g_wth);

    cudaFuncSetAttribute(gemm8<EPI_BIAS,      true,  true,  false>, cudaFuncAttributeMaxDynamicSharedMemorySize, SMEM_G8);
    cudaFuncSetAttribute(gemm8<EPI_BIAS,      true,  false, false>, cudaFuncAttributeMaxDynamicSharedMemorySize, SMEM_G8);
    cudaFuncSetAttribute(gemm8<EPI_CONV,      true,  false, false>, cudaFuncAttributeMaxDynamicSharedMemorySize, SMEM_G8);
    cudaFuncSetAttribute(gemm8<EPI_BIAS_RES,  false, false, false>, cudaFuncAttributeMaxDynamicSharedMemorySize, SMEM_G8);
    cudaFuncSetAttribute(gemm8<EPI_BIAS_RES,  false, false, true >, cudaFuncAttributeMaxDynamicSharedMemorySize, SMEM_G8);
    cudaFuncSetAttribute(gemm8<EPI_BIAS_GELU, true,  false, false>, cudaFuncAttributeMaxDynamicSharedMemorySize, SMEM_G8);
    cudaFuncSetAttribute(gemm8<EPI_BIAS,      false, false, false>, cudaFuncAttributeMaxDynamicSharedMemorySize, SMEM_G8);
    cudaFuncSetAttribute(fattn_k, cudaFuncAttributeMaxDynamicSharedMemorySize, FA_BYTES);

    // prep
    pe_k<<<TT, 256>>>(pe_);
    convT_k<<<(4 * H * H + 255) / 256, 256>>>(conv_w, cT_);
    cvth_k<<<1024, 512>>>(memory,   memh_,  2097152 / 4);
    cvth_k<<<512, 512>>>(in_w,      inwh_,  262144 / 4);
    cvth_k<<<32, 512>>>(out_w,      outwh_, 52224 / 4);
    cvth_k<<<1536, 512>>>(sa_in_w,  wt_ + WOFF_SAIN,  3145728 / 4);
    cvth_k<<<512, 512>>>(sa_out_w,  wt_ + WOFF_SAOUT, 1048576 / 4);
    cvth_k<<<1536, 512>>>(ca_in_w,  wt_ + WOFF_CAIN,  3145728 / 4);
    cvth_k<<<512, 512>>>(ca_out_w,  wt_ + WOFF_CAOUT, 1048576 / 4);
    cvth_k<<<2048, 512>>>(ff1_w,    wt_ + WOFF_FF1,   4194304 / 4);
    cvth_k<<<2048, 512>>>(ff2_w,    wt_ + WOFF_FF2,   4194304 / 4);

    // m = memory @ in_w^T + in_b
    gemm8<EPI_BIAS, true, false, false><<<gg128(BB * SS, H), 256, SMEM_G8>>>(
        memh_, inwh_, in_b, nullptr, m_, nullptr,
        BB * SS, H, H, H, H, H, 0L, 1);

    // conv upsample (4 taps batched over z; tap = hh)
    gemm8<EPI_CONV, true, false, false><<<gg128(BB * SS, H, 4), 256, SMEM_G8>>>(
        m_, cT_, conv_b, pe_, mem_, nullptr,
        BB * SS, H, H, H, H, H, (long)H * H, 4);

    xinit_k<<<(BB * TT * H + 255) / 256, 256>>>(qemb, pe_, x_);

    const dim3 fa_grid(TT / 128, BB * NHEAD);

    for (int l = 0; l < NL; l++) {
        // ======== self-attention ========
        ln_k<<<BB * TT, 128>>>(x_, ln1_g + l * H, ln1_b + l * H, h_);
        gemm8<EPI_BIAS, true, true, false><<<gg128(BB * TT, 3 * H), 256, SMEM_G8>>>(
            h_, wt_ + WOFF_SAIN + (long)l * 3 * H * H, sa_in_b + (long)l * 3 * H, nullptr, qkv_, nullptr,
            BB * TT, 3 * H, H, H, H, 3 * H, 0L, 1);
        fattn_k<<<fa_grid, 256, FA_BYTES>>>(qkv_, att_);
        gemm8<EPI_BIAS_RES, false, false, false><<<gg128(BB * TT, H), 256, SMEM_G8>>>(
            att_, wt_ + WOFF_SAOUT + (long)l * H * H, sa_out_b + (long)l * H, x_, x_, nullptr,
            BB * TT, H, H, H, H, H, 0L, 1);

        // ======== cross-attention ========
        ln_k<<<BB * TT, 128>>>(x_, ln2_g + l * H, ln2_b + l * H, h_);
        gemm8<EPI_BIAS, true, true, false><<<gg128(BB * TT, H), 256, SMEM_G8>>>(
            h_, wt_ + WOFF_CAIN + (long)l * 3 * H * H, ca_in_b + (long)l * 3 * H, nullptr, qkv_, nullptr,
            BB * TT, H, H, H, H, 3 * H, 0L, 1);
        gemm8<EPI_BIAS, true, false, false><<<gg128(BB * TT, 2 * H), 256, SMEM_G8>>>(
            mem_, wt_ + WOFF_CAIN + (long)l * 3 * H * H + (long)H * H,
            ca_in_b + (long)l * 3 * H + H, nullptr, qkv_ + H, nullptr,
            BB * TT, 2 * H, H, H, H, 3 * H, 0L, 1);
        fattn_k<<<fa_grid, 256, FA_BYTES>>>(qkv_, att_);
        gemm8<EPI_BIAS_RES, false, false, false><<<gg128(BB * TT, H), 256, SMEM_G8>>>(
            att_, wt_ + WOFF_CAOUT + (long)l * H * H, ca_out_b + (long)l * H, x_, x_, nullptr,
            BB * TT, H, H, H, H, H, 0L, 1);

        // ======== FFN ========
        ln_k<<<BB * TT, 128>>>(x_, ln3_g + l * H, ln3_b + l * H, h_);
        gemm8<EPI_BIAS_GELU, true, false, false><<<gg128(BB * TT, FF), 256, SMEM_G8>>>(
            h_, wt_ + WOFF_FF1 + (long)l * FF * H, ff1_b + (long)l * FF, nullptr, ff_, nullptr,
            BB * TT, FF, H, H, H, FF, 0L, 1);
        if (l < NL - 1) {
            gemm8<EPI_BIAS_RES, false, false, false><<<gg128(BB * TT, H), 256, SMEM_G8>>>(
                ff_, wt_ + WOFF_FF2 + (long)l * H * FF, ff2_b + (long)l * H, x_, x_, nullptr,
                BB * TT, H, FF, FF, FF, H, 0L, 1);
        } else {
            // last layer: also emit fp16 copy for the head GEMM (no separate cvth)
            gemm8<EPI_BIAS_RES, false, false, true><<<gg128(BB * TT, H), 256, SMEM_G8>>>(
                ff_, wt_ + WOFF_FF2 + (long)l * H * FF, ff2_b + (long)l * H, x_, x_, xh_,
                BB * TT, H, FF, FF, FF, H, 0L, 1);
        }
    }

    // head
    gemm8<EPI_BIAS, false, false, false><<<gg128(BB * TT, NOUT), 256, SMEM_G8>>>(
        xh_, outwh_, out_b, nullptr, ho_, nullptr,
        BB * TT, NOUT, H, H, H, NOUT, 0L, 1);

    kin_k<<<(BB * TT + 255) / 256, 256>>>(ho_, (float*)d_out);
}

// round 14
// speedup vs baseline: 1.0653x; 1.0324x over previous
#include <cuda_runtime.h>
#include <cuda_fp16.h>
#include <math.h>
#include <stdint.h>

#define H 512
#define BB 32
#define SS 128
#define TT 512
#define NHEAD 8
#define DHD 64
#define NL 4
#define FF 2048
#define NOUT 102
#define NJ 50

// ---------------- scratch ----------------
__device__ __half g_memh[BB * SS * H];
__device__ __half g_m[BB * SS * H];
__device__ __half g_mem[BB * TT * H];
__device__ float  g_x[BB * TT * H];
__device__ __half g_xh[BB * TT * H];
__device__ __half g_h[BB * TT * H];
__device__ __half g_qkv[BB * TT * 3 * H];
__device__ __half g_att[BB * TT * H];
__device__ __half g_ff[BB * TT * FF];
__device__ float  g_head[BB * TT * NOUT];
__device__ float  g_pe[TT * H];
__device__ __half g_convTh[4 * H * H];
__device__ __half g_inwh[H * H];
__device__ __half g_outwh[NOUT * H];
__device__ __half g_wth[16777216];

#define WOFF_SAIN  0
#define WOFF_SAOUT 3145728
#define WOFF_CAIN  4194304
#define WOFF_CAOUT 7340032
#define WOFF_FF1   8388608
#define WOFF_FF2   12582912

__constant__ int PAR[NJ] = {
    -1, 0, 1, 2, 3, 1, 5, 6, 1,
    4, 9, 10, 11,  4, 13, 14, 15,  4, 17, 18, 19,  4, 21, 22, 23,  4, 25, 26, 27,
    7, 29, 30, 31, 7, 33, 34, 35,  7, 37, 38, 39,  7, 41, 42, 43,  7, 45, 46, 47,
    8
};

#define EPI_BIAS 2
#define EPI_BIAS_RES 3
#define EPI_BIAS_GELU 4
#define EPI_CONV 5

// ---------------- ptx helpers ----------------
__device__ __forceinline__ void cp16(uint32_t dst, const void* src)
{
    asm volatile("cp.async.cg.shared.global [%0], [%1], 16;\n" :: "r"(dst), "l"(src));
}
__device__ __forceinline__ void cp16z(uint32_t dst, const void* src, bool p)
{
    int sz = p ? 16 : 0;
    asm volatile("cp.async.cg.shared.global [%0], [%1], 16, %2;\n"
                 :: "r"(dst), "l"(src), "r"(sz));
}
__device__ __forceinline__ void cpcommit()
{
    asm volatile("cp.async.commit_group;\n" ::: "memory");
}
template <int W>
__device__ __forceinline__ void cpwait()
{
    asm volatile("cp.async.wait_group %0;\n" :: "n"(W) : "memory");
}
__device__ __forceinline__ void mma16(float* d, const uint32_t* a, const uint32_t* b)
{
    asm volatile(
        "mma.sync.aligned.m16n8k16.row.col.f32.f16.f16.f32 "
        "{%0,%1,%2,%3}, {%4,%5,%6,%7}, {%8,%9}, {%0,%1,%2,%3};\n"
        : "+f"(d[0]), "+f"(d[1]), "+f"(d[2]), "+f"(d[3])
        : "r"(a[0]), "r"(a[1]), "r"(a[2]), "r"(a[3]), "r"(b[0]), "r"(b[1]));
}
__device__ __forceinline__ void ldsm4(uint32_t* r, uint32_t addr)
{
    asm volatile("ldmatrix.sync.aligned.m8n8.x4.shared.b16 {%0,%1,%2,%3}, [%4];\n"
                 : "=r"(r[0]), "=r"(r[1]), "=r"(r[2]), "=r"(r[3]) : "r"(addr));
}
__device__ __forceinline__ void ldsm2t(uint32_t* r, uint32_t addr)
{
    asm volatile("ldmatrix.sync.aligned.m8n8.x2.trans.shared.b16 {%0,%1}, [%2];\n"
                 : "=r"(r[0]), "=r"(r[1]) : "r"(addr));
}

// ---------------- fp16 tensor-core GEMM: 3-stage, m16n8k16, 256 thr ----------------
template <int EPI, bool HOUT, bool QS, bool DUAL>
__global__ void __launch_bounds__(256, 2) gemm8(
    const __half* __restrict__ A, const __half* __restrict__ Bm,
    const float* __restrict__ bias, const float* __restrict__ resid,
    void* __restrict__ C, __half* __restrict__ C2,
    int M, int N, int K, int lda, int ldb, int ldc,
    long sBh, int nh)
{
    constexpr int BM = 128, BN_ = 128, BK = 32;
    constexpr int LDE = BK + 8;
    constexpr int STGH = BM * LDE * 2;
    constexpr int CH = BM * BK / 8 / 256;

    extern __shared__ char smc[];
    const uint32_t smu = (uint32_t)__cvta_generic_to_shared(smc);

    const int z = blockIdx.z;
    const int hh = z % nh;
    Bm += (long)hh * sBh;

    const int row0 = blockIdx.y * BM;
    const int col0 = blockIdx.x * BN_;
    const int tid = threadIdx.x;
    const int warp = tid >> 5;
    const int lane = tid & 31;
    const int wm = warp >> 2;
    const int wn = warp & 3;
    const int gid = lane >> 2;
    const int tig = lane & 3;
    const int l15 = lane & 15;
    const int ah = (lane >> 4) << 3;

    float acc[4][4][4];
#pragma unroll
    for (int i = 0; i < 4; i++)
#pragma unroll
        for (int j = 0; j < 4; j++)
#pragma unroll
            for (int q = 0; q < 4; q++) acc[i][j][q] = 0.f;

    auto cpTile = [&](int k0, int st) {
        uint32_t abase = smu + (uint32_t)(st * STGH) * 2;
#pragma unroll
        for (int l = 0; l < CH; l++) {
            int idx = l * 256 + tid;
            int r = idx >> 2;
            int cq = (idx & 3) * 8;
            cp16(abase + (uint32_t)(r * LDE + cq) * 2,
                 A + (long)(row0 + r) * lda + k0 + cq);
        }
        uint32_t bbase = abase + (uint32_t)(BM * LDE) * 2;
#pragma unroll
        for (int l = 0; l < CH; l++) {
            int idx = l * 256 + tid;
            int n = idx >> 2;
            int cq = (idx & 3) * 8;
            cp16z(bbase + (uint32_t)(n * LDE + cq) * 2,
                  Bm + (long)(col0 + n) * ldb + k0 + cq,
                  (col0 + n) < N);
        }
        cpcommit();
    };

    auto compute = [&](int st) {
        const uint32_t pAu = smu + (uint32_t)(st * STGH) * 2;
        const uint32_t pBu = pAu + (uint32_t)(BM * LDE) * 2;
#pragma unroll
        for (int ks = 0; ks < 2; ks++) {
            const int k = ks * 16;
            uint32_t af[4][4], bf[4][2];
#pragma unroll
            for (int mi = 0; mi < 4; mi++) {
                int r0 = wm * 64 + mi * 16 + l15;
                ldsm4(af[mi], pAu + (uint32_t)(r0 * LDE + k + ah) * 2);
            }
#pragma unroll
            for (int pb = 0; pb < 2; pb++) {
                uint32_t q[4];
                int n0 = wn * 32 + pb * 16 + l15;
                ldsm4(q, pBu + (uint32_t)(n0 * LDE + k + ah) * 2);
                bf[pb * 2][0] = q[0];     bf[pb * 2][1] = q[2];
                bf[pb * 2 + 1][0] = q[1]; bf[pb * 2 + 1][1] = q[3];
            }
#pragma unroll
            for (int mi = 0; mi < 4; mi++)
#pragma unroll
                for (int ni = 0; ni < 4; ni++)
                    mma16(acc[mi][ni], af[mi], bf[ni]);
        }
    };

    const int nt = K / BK;
    cpTile(0, 0);
    cpTile(BK, 1);
    int st = 0;
    for (int t = 0; t < nt; t++) {
        if (t < nt - 1) cpwait<1>(); else cpwait<0>();
        __syncthreads();
        if (t + 2 < nt) {
            int st2 = st + 2; if (st2 >= 3) st2 -= 3;
            cpTile((t + 2) * BK, st2);
        }
        compute(st);
        if (++st == 3) st = 0;
    }

    auto emit2 = [&](int r, int c, float v0, float v1) {
        v0 += bias[c];
        v1 += bias[c + 1];
        if (QS && c < H) { v0 *= 0.125f; v1 *= 0.125f; }
        if (EPI == EPI_BIAS_GELU) {
            v0 = 0.5f * v0 * (1.f + erff(v0 * 0.70710678118654752f));
            v1 = 0.5f * v1 * (1.f + erff(v1 * 0.70710678118654752f));
        }
        long idx;
        if (EPI == EPI_CONV) {
            int b_ = r >> 7;
            int s_ = r & 127;
            int t_ = s_ * 4 + hh;
            float2 rv = *(const float2*)&resid[t_ * H + c];
            v0 += rv.x; v1 += rv.y;
            idx = ((long)b_ * TT + t_) * ldc + c;
        } else {
            idx = (long)r * ldc + c;
            if (EPI == EPI_BIAS_RES) {
                float2 rv = *(const float2*)&resid[idx];
                v0 += rv.x; v1 += rv.y;
            }
        }
        if (HOUT) *(__half2*)((__half*)C + idx) = __floats2half2_rn(v0, v1);
        else      *(float2*)((float*)C + idx) = make_float2(v0, v1);
        if (DUAL) *(__half2*)(C2 + idx) = __floats2half2_rn(v0, v1);
    };

#pragma unroll
    for (int mi = 0; mi < 4; mi++) {
        int r0 = row0 + wm * 64 + mi * 16 + gid;
#pragma unroll
        for (int ni = 0; ni < 4; ni++) {
            int c0 = col0 + wn * 32 + ni * 8 + tig * 2;
            if (c0 < N) {
                emit2(r0,     c0, acc[mi][ni][0], acc[mi][ni][1]);
                emit2(r0 + 8, c0, acc[mi][ni][2], acc[mi][ni][3]);
            }
        }
    }
}

// ---------------- fused flash attention: single KV buffer, 2 CTAs/SM ----------------
// q arrives pre-scaled by 1/8 from the q projection GEMM.
#define FAB_Q 0
#define FAB_K 18432
#define FAB_V 36864
#define FAB_P 55296
#define FAB_RED 90112
#define FAB_M 92160
#define FAB_L 92672
#define FAB_AL 93184
#define FA_BYTES 93696

__global__ void __launch_bounds__(256, 2) fattn_k(
    const __half* __restrict__ qkv, __half* __restrict__ att)
{
    extern __shared__ char smc[];
    __half* sP = (__half*)(smc + FAB_P);
    float* sRed = (float*)(smc + FAB_RED);
    float* sM = (float*)(smc + FAB_M);
    float* sL = (float*)(smc + FAB_L);
    float* sAl = (float*)(smc + FAB_AL);
    const uint32_t smu = (uint32_t)__cvta_generic_to_shared(smc);

    const int z = blockIdx.y;
    const int bb = z >> 3, hh = z & 7;
    const int q0 = blockIdx.x * 128;
    const long base = (long)bb * TT * 3 * H + (long)hh * DHD;

    const int tid = threadIdx.x;
    const int warp = tid >> 5, lane = tid & 31;
    const int wm = warp >> 2, wn = warp & 3;
    const int gid = lane >> 2, tig = lane & 3;
    const int l15 = lane & 15;
    const int ah = (lane >> 4) << 3;

    // load Q (128 x 64 halves, pitch 72)
#pragma unroll
    for (int l = 0; l < 4; l++) {
        int idx = l * 256 + tid;
        int r = idx >> 3, c8 = (idx & 7) * 8;
        cp16(smu + FAB_Q + (uint32_t)(r * 72 + c8) * 2,
             qkv + base + (long)(q0 + r) * (3 * H) + c8);
    }
    cpcommit();
    cpwait<0>();

    if (tid < 128) { sM[tid] = -1e30f; sL[tid] = 0.f; }

    float oacc[4][2][4];
#pragma unroll
    for (int mi = 0; mi < 4; mi++)
#pragma unroll
        for (int ni = 0; ni < 2; ni++)
#pragma unroll
            for (int q = 0; q < 4; q++) oacc[mi][ni][q] = 0.f;

    for (int j = 0; j < 4; j++) {
        __syncthreads();   // prior reads of sK/sV done; also publishes Q/init on j=0
#pragma unroll
        for (int l = 0; l < 4; l++) {
            int idx = l * 256 + tid;
            int r = idx >> 3, c8 = (idx & 7) * 8;
            long row = (long)(j * 128 + r) * (3 * H);
            cp16(smu + FAB_K + (uint32_t)(r * 72 + c8) * 2, qkv + base + H + row + c8);
            cp16(smu + FAB_V + (uint32_t)(r * 72 + c8) * 2, qkv + base + 2 * H + row + c8);
        }
        cpcommit();
        cpwait<0>();
        __syncthreads();

        // ---- S = Q K^T (128x128, k=64) ----
        float sacc[4][4][4];
#pragma unroll
        for (int mi = 0; mi < 4; mi++)
#pragma unroll
            for (int ni = 0; ni < 4; ni++)
#pragma unroll
                for (int q = 0; q < 4; q++) sacc[mi][ni][q] = 0.f;
#pragma unroll
        for (int ks = 0; ks < 4; ks++) {
            const int k = ks * 16;
            uint32_t af[4][4], bf[4][2];
#pragma unroll
            for (int mi = 0; mi < 4; mi++) {
                int r0 = wm * 64 + mi * 16 + l15;
                ldsm4(af[mi], smu + FAB_Q + (uint32_t)(r0 * 72 + k + ah) * 2);
            }
#pragma unroll
            for (int pb = 0; pb < 2; pb++) {
                uint32_t q[4];
                int n0 = wn * 32 + pb * 16 + l15;
                ldsm4(q, smu + FAB_K + (uint32_t)(n0 * 72 + k + ah) * 2);
                bf[pb * 2][0] = q[0];     bf[pb * 2][1] = q[2];
                bf[pb * 2 + 1][0] = q[1]; bf[pb * 2 + 1][1] = q[3];
            }
#pragma unroll
            for (int mi = 0; mi < 4; mi++)
#pragma unroll
                for (int ni = 0; ni < 4; ni++)
                    mma16(sacc[mi][ni], af[mi], bf[ni]);
        }

        // ---- row max ----
#pragma unroll
        for (int mi = 0; mi < 4; mi++) {
            float r0m = -1e30f, r1m = -1e30f;
#pragma unroll
            for (int ni = 0; ni < 4; ni++) {
                r0m = fmaxf(r0m, fmaxf(sacc[mi][ni][0], sacc[mi][ni][1]));
                r1m = fmaxf(r1m, fmaxf(sacc[mi][ni][2], sacc[mi][ni][3]));
            }
            r0m = fmaxf(r0m, __shfl_xor_sync(0xffffffffu, r0m, 1));
            r0m = fmaxf(r0m, __shfl_xor_sync(0xffffffffu, r0m, 2));
            r1m = fmaxf(r1m, __shfl_xor_sync(0xffffffffu, r1m, 1));
            r1m = fmaxf(r1m, __shfl_xor_sync(0xffffffffu, r1m, 2));
            if (tig == 0) {
                int r0 = wm * 64 + mi * 16 + gid;
                sRed[wn * 128 + r0] = r0m;
                sRed[wn * 128 + r0 + 8] = r1m;
            }
        }
        __syncthreads();
        if (tid < 128) {
            float mt = fmaxf(fmaxf(sRed[tid], sRed[128 + tid]),
                             fmaxf(sRed[256 + tid], sRed[384 + tid]));
            float mo = sM[tid];
            float mn = fmaxf(mo, mt);
            sAl[tid] = __expf(mo - mn);
            sM[tid] = mn;
        }
        __syncthreads();

        // ---- P = exp(S-m), rowsum, store P half ----
#pragma unroll
        for (int mi = 0; mi < 4; mi++) {
            int r0 = wm * 64 + mi * 16 + gid;
            float m0 = sM[r0], m1 = sM[r0 + 8];
            float rs0 = 0.f, rs1 = 0.f;
#pragma unroll
            for (int ni = 0; ni < 4; ni++) {
                int c0 = wn * 32 + ni * 8 + tig * 2;
                float p00 = __expf(sacc[mi][ni][0] - m0);
                float p01 = __expf(sacc[mi][ni][1] - m0);
                float p10 = __expf(sacc[mi][ni][2] - m1);
                float p11 = __expf(sacc[mi][ni][3] - m1);
                rs0 += p00 + p01;
                rs1 += p10 + p11;
                *(__half2*)&sP[r0 * 136 + c0] = __floats2half2_rn(p00, p01);
                *(__half2*)&sP[(r0 + 8) * 136 + c0] = __floats2half2_rn(p10, p11);
            }
            rs0 += __shfl_xor_sync(0xffffffffu, rs0, 1);
            rs0 += __shfl_xor_sync(0xffffffffu, rs0, 2);
            rs1 += __shfl_xor_sync(0xffffffffu, rs1, 1);
            rs1 += __shfl_xor_sync(0xffffffffu, rs1, 2);
            if (tig == 0) {
                sRed[wn * 128 + r0] = rs0;
                sRed[wn * 128 + r0 + 8] = rs1;
            }
        }
        __syncthreads();
        if (tid < 128) {
            sL[tid] = sL[tid] * sAl[tid] +
                      (sRed[tid] + sRed[128 + tid]) + (sRed[256 + tid] + sRed[384 + tid]);
        }

        // ---- rescale O ----
#pragma unroll
        for (int mi = 0; mi < 4; mi++) {
            int r0 = wm * 64 + mi * 16 + gid;
            float a0 = sAl[r0], a1 = sAl[r0 + 8];
#pragma unroll
            for (int ni = 0; ni < 2; ni++) {
                oacc[mi][ni][0] *= a0;
                oacc[mi][ni][1] *= a0;
                oacc[mi][ni][2] *= a1;
                oacc[mi][ni][3] *= a1;
            }
        }

        // ---- O += P @ V (128x64, k=128); V via ldmatrix.trans ----
#pragma unroll
        for (int ks = 0; ks < 8; ks++) {
            const int k = ks * 16;
            uint32_t af[4][4], bf[2][2];
#pragma unroll
            for (int mi = 0; mi < 4; mi++) {
                int r0 = wm * 64 + mi * 16 + l15;
                ldsm4(af[mi], smu + FAB_P + (uint32_t)(r0 * 136 + k + ah) * 2);
            }
#pragma unroll
            for (int ni = 0; ni < 2; ni++) {
                int n0 = wn * 16 + ni * 8;
                ldsm2t(bf[ni], smu + FAB_V + (uint32_t)((k + l15) * 72 + n0) * 2);
            }
#pragma unroll
            for (int mi = 0; mi < 4; mi++)
#pragma unroll
                for (int ni = 0; ni < 2; ni++)
                    mma16(oacc[mi][ni], af[mi], bf[ni]);
        }
    }
    __syncthreads();

    // ---- O /= l, write half ----
#pragma unroll
    for (int mi = 0; mi < 4; mi++) {
        int r0 = wm * 64 + mi * 16 + gid;
        float i0 = 1.f / sL[r0], i1 = 1.f / sL[r0 + 8];
        long o0 = ((long)bb * TT + q0 + r0) * H + hh * DHD;
        long o1 = ((long)bb * TT + q0 + r0 + 8) * H + hh * DHD;
#pragma unroll
        for (int ni = 0; ni < 2; ni++) {
            int c0 = wn * 16 + ni * 8 + tig * 2;
            *(__half2*)&att[o0 + c0] = __floats2half2_rn(oacc[mi][ni][0] * i0, oacc[mi][ni][1] * i0);
            *(__half2*)&att[o1 + c0] = __floats2half2_rn(oacc[mi][ni][2] * i1, oacc[mi][ni][3] * i1);
        }
    }
}

// ---------------- LayerNorm: fp32 in, fp16 out ----------------
__global__ void ln_k(const float* __restrict__ x, const float* __restrict__ g,
                     const float* __restrict__ b, __half* __restrict__ o)
{
    long row = blockIdx.x;
    int t = threadIdx.x;
    float4 v = ((const float4*)(x + row * H))[t];
    float s = v.x + v.y + v.z + v.w;
    float ss = v.x * v.x + v.y * v.y + v.z * v.z + v.w * v.w;
#pragma unroll
    for (int off = 16; off; off >>= 1) {
        s += __shfl_xor_sync(0xffffffffu, s, off);
        ss += __shfl_xor_sync(0xffffffffu, ss, off);
    }
    __shared__ float sm0[4], sm1[4];
    int w = t >> 5;
    if ((t & 31) == 0) { sm0[w] = s; sm1[w] = ss; }
    __syncthreads();
    s = sm0[0] + sm0[1] + sm0[2] + sm0[3];
    ss = sm1[0] + sm1[1] + sm1[2] + sm1[3];
    float mean = s * (1.f / H);
    float var = ss * (1.f / H) - mean * mean;
    float rstd = rsqrtf(var + 1e-5f);
    float4 gg = ((const float4*)g)[t];
    float4 bb4 = ((const float4*)b)[t];
    __half2* op = (__half2*)(o + row * H);
    op[t * 2]     = __floats2half2_rn((v.x - mean) * rstd * gg.x + bb4.x,
                                      (v.y - mean) * rstd * gg.y + bb4.y);
    op[t * 2 + 1] = __floats2half2_rn((v.z - mean) * rstd * gg.z + bb4.z,
                                      (v.w - mean) * rstd * gg.w + bb4.w);
}

// ---------------- misc kernels ----------------
__global__ void cvth_k(const float* __restrict__ in, __half* __restrict__ out, int n4)
{
    int stride = gridDim.x * blockDim.x;
    for (int i = blockIdx.x * blockDim.x + threadIdx.x; i < n4; i += stride) {
        float4 v = ((const float4*)in)[i];
        ((__half2*)out)[i * 2]     = __floats2half2_rn(v.x, v.y);
        ((__half2*)out)[i * 2 + 1] = __floats2half2_rn(v.z, v.w);
    }
}

__global__ void pe_k(float* __restrict__ pe)
{
    int t = blockIdx.x;
    int i = threadIdx.x;
    float div = expf(-(float)(2 * i) * (logf(10000.f) / (float)H));
    float a = (float)t * div;
    pe[t * H + 2 * i] = sinf(a);
    pe[t * H + 2 * i + 1] = cosf(a);
}

__global__ void convT_k(const float* __restrict__ w, __half* __restrict__ o)
{
    int idx = blockIdx.x * blockDim.x + threadIdx.x;
    if (idx >= 4 * H * H) return;
    int k = idx / (H * H);
    int d = (idx / H) % H;
    int c = idx % H;
    o[idx] = __float2half_rn(w[c * H * 4 + d * 4 + k]);
}

__global__ void xinit_k(const float* __restrict__ qe, const float* __restrict__ pe,
                        float* __restrict__ x)
{
    long i = blockIdx.x * (long)blockDim.x + threadIdx.x;
    if (i >= (long)BB * TT * H) return;
    int td = (int)(i % (TT * H));
    x[i] = qe[td] + pe[td];
}

__global__ void kin_k(const float* __restrict__ ho, float* __restrict__ out)
{
    int row = blockIdx.x * blockDim.x + threadIdx.x;
    if (row >= BB * TT) return;
    const float* r = ho + (long)row * NOUT;
    float* o = out + (long)row * (3 * NJ);
    float gx[NJ], px[NJ], py[NJ];
    gx[0] = 0.f;
    px[0] = r[100];
    py[0] = r[101];
    o[0] = px[0]; o[1] = py[0]; o[2] = 1.f;
    for (int j = 1; j < NJ; j++) {
        int pa = PAR[j];
        float gg = gx[pa] + r[j];
        gx[j] = gg;
        float s = r[50 + j];
        float sn, cs;
        sincosf(gg, &sn, &cs);
        px[j] = px[pa] + cs * s;
        py[j] = py[pa] + sn * s;
        o[j * 3 + 0] = px[j];
        o[j * 3 + 1] = py[j];
        o[j * 3 + 2] = 1.f;
    }
}

// ---------------- launcher ----------------
static inline dim3 gg128(int M, int N, int bz = 1)
{
    return dim3((N + 127) / 128, (M + 127) / 128, bz);
}

#define SMEM_G8 61440

extern "C" void kernel_launch(void* const* d_in, const int* in_sizes, int n_in,
                              void* d_out, int out_size)
{
    const float* memory   = (const float*)d_in[0];
    const float* in_w     = (const float*)d_in[1];
    const float* in_b     = (const float*)d_in[2];
    const float* conv_w   = (const float*)d_in[3];
    const float* conv_b   = (const float*)d_in[4];
    const float* qemb     = (const float*)d_in[5];
    const float* sa_in_w  = (const float*)d_in[6];
    const float* sa_in_b  = (const float*)d_in[7];
    const float* sa_out_w = (const float*)d_in[8];
    const float* sa_out_b = (const float*)d_in[9];
    const float* ca_in_w  = (const float*)d_in[10];
    const float* ca_in_b  = (const float*)d_in[11];
    const float* ca_out_w = (const float*)d_in[12];
    const float* ca_out_b = (const float*)d_in[13];
    const float* ln1_g    = (const float*)d_in[14];
    const float* ln1_b    = (const float*)d_in[15];
    const float* ln2_g    = (const float*)d_in[16];
    const float* ln2_b    = (const float*)d_in[17];
    const float* ln3_g    = (const float*)d_in[18];
    const float* ln3_b    = (const float*)d_in[19];
    const float* ff1_w    = (const float*)d_in[20];
    const float* ff1_b    = (const float*)d_in[21];
    const float* ff2_w    = (const float*)d_in[22];
    const float* ff2_b    = (const float*)d_in[23];
    const float* out_w    = (const float*)d_in[24];
    const float* out_b    = (const float*)d_in[25];

    __half *memh_, *m_, *mem_, *xh_, *h_, *qkv_, *att_, *ff_, *cT_, *inwh_, *outwh_, *wt_;
    float *x_, *ho_, *pe_;
    cudaGetSymbolAddress((void**)&memh_, g_memh);
    cudaGetSymbolAddress((void**)&m_,    g_m);
    cudaGetSymbolAddress((void**)&mem_,  g_mem);
    cudaGetSymbolAddress((void**)&x_,    g_x);
    cudaGetSymbolAddress((void**)&xh_,   g_xh);
    cudaGetSymbolAddress((void**)&h_,    g_h);
    cudaGetSymbolAddress((void**)&qkv_,  g_qkv);
    cudaGetSymbolAddress((void**)&att_,  g_att);
    cudaGetSymbolAddress((void**)&ff_,   g_ff);
    cudaGetSymbolAddress((void**)&ho_,   g_head);
    cudaGetSymbolAddress((void**)&pe_,   g_pe);
    cudaGetSymbolAddress((void**)&cT_,   g_convTh);
    cudaGetSymbolAddress((void**)&inwh_, g_inwh);
    cudaGetSymbolAddress((void**)&outwh_,g_outwh);
    cudaGetSymbolAddress((void**)&wt_,   g_wth);

    cudaFuncSetAttribute(gemm8<EPI_BIAS,      true,  true,  false>, cudaFuncAttributeMaxDynamicSharedMemorySize, SMEM_G8);
    cudaFuncSetAttribute(gemm8<EPI_BIAS,      true,  false, false>, cudaFuncAttributeMaxDynamicSharedMemorySize, SMEM_G8);
    cudaFuncSetAttribute(gemm8<EPI_CONV,      true,  false, false>, cudaFuncAttributeMaxDynamicSharedMemorySize, SMEM_G8);
    cudaFuncSetAttribute(gemm8<EPI_BIAS_RES,  false, false, false>, cudaFuncAttributeMaxDynamicSharedMemorySize, SMEM_G8);
    cudaFuncSetAttribute(gemm8<EPI_BIAS_RES,  false, false, true >, cudaFuncAttributeMaxDynamicSharedMemorySize, SMEM_G8);
    cudaFuncSetAttribute(gemm8<EPI_BIAS_GELU, true,  false, false>, cudaFuncAttributeMaxDynamicSharedMemorySize, SMEM_G8);
    cudaFuncSetAttribute(gemm8<EPI_BIAS,      false, false, false>, cudaFuncAttributeMaxDynamicSharedMemorySize, SMEM_G8);
    cudaFuncSetAttribute(fattn_k, cudaFuncAttributeMaxDynamicSharedMemorySize, FA_BYTES);

    // prep
    pe_k<<<TT, 256>>>(pe_);
    convT_k<<<(4 * H * H + 255) / 256, 256>>>(conv_w, cT_);
    cvth_k<<<1024, 512>>>(memory,   memh_,  2097152 / 4);
    cvth_k<<<512, 512>>>(in_w,      inwh_,  262144 / 4);
    cvth_k<<<32, 512>>>(out_w,      outwh_, 52224 / 4);
    cvth_k<<<1536, 512>>>(sa_in_w,  wt_ + WOFF_SAIN,  3145728 / 4);
    cvth_k<<<512, 512>>>(sa_out_w,  wt_ + WOFF_SAOUT, 1048576 / 4);
    cvth_k<<<1536, 512>>>(ca_in_w,  wt_ + WOFF_CAIN,  3145728 / 4);
    cvth_k<<<512, 512>>>(ca_out_w,  wt_ + WOFF_CAOUT, 1048576 / 4);
    cvth_k<<<2048, 512>>>(ff1_w,    wt_ + WOFF_FF1,   4194304 / 4);
    cvth_k<<<2048, 512>>>(ff2_w,    wt_ + WOFF_FF2,   4194304 / 4);

    // m = memory @ in_w^T + in_b
    gemm8<EPI_BIAS, true, false, false><<<gg128(BB * SS, H), 256, SMEM_G8>>>(
        memh_, inwh_, in_b, nullptr, m_, nullptr,
        BB * SS, H, H, H, H, H, 0L, 1);

    // conv upsample (4 taps batched over z; tap = hh)
    gemm8<EPI_CONV, true, false, false><<<gg128(BB * SS, H, 4), 256, SMEM_G8>>>(
        m_, cT_, conv_b, pe_, mem_, nullptr,
        BB * SS, H, H, H, H, H, (long)H * H, 4);

    xinit_k<<<(BB * TT * H + 255) / 256, 256>>>(qemb, pe_, x_);

    const dim3 fa_grid(TT / 128, BB * NHEAD);

    for (int l = 0; l < NL; l++) {
        // ======== self-attention ========
        ln_k<<<BB * TT, 128>>>(x_, ln1_g + l * H, ln1_b + l * H, h_);
        gemm8<EPI_BIAS, true, true, false><<<gg128(BB * TT, 3 * H), 256, SMEM_G8>>>(
            h_, wt_ + WOFF_SAIN + (long)l * 3 * H * H, sa_in_b + (long)l * 3 * H, nullptr, qkv_, nullptr,
            BB * TT, 3 * H, H, H, H, 3 * H, 0L, 1);
        fattn_k<<<fa_grid, 256, FA_BYTES>>>(qkv_, att_);
        gemm8<EPI_BIAS_RES, false, false, false><<<gg128(BB * TT, H), 256, SMEM_G8>>>(
            att_, wt_ + WOFF_SAOUT + (long)l * H * H, sa_out_b + (long)l * H, x_, x_, nullptr,
            BB * TT, H, H, H, H, H, 0L, 1);

        // ======== cross-attention ========
        ln_k<<<BB * TT, 128>>>(x_, ln2_g + l * H, ln2_b + l * H, h_);
        gemm8<EPI_BIAS, true, true, false><<<gg128(BB * TT, H), 256, SMEM_G8>>>(
            h_, wt_ + WOFF_CAIN + (long)l * 3 * H * H, ca_in_b + (long)l * 3 * H, nullptr, qkv_, nullptr,
            BB * TT, H, H, H, H, 3 * H, 0L, 1);
        gemm8<EPI_BIAS, true, false, false><<<gg128(BB * TT, 2 * H), 256, SMEM_G8>>>(
            mem_, wt_ + WOFF_CAIN + (long)l * 3 * H * H + (long)H * H,
            ca_in_b + (long)l * 3 * H + H, nullptr, qkv_ + H, nullptr,
            BB * TT, 2 * H, H, H, H, 3 * H, 0L, 1);
        fattn_k<<<fa_grid, 256, FA_BYTES>>>(qkv_, att_);
        gemm8<EPI_BIAS_RES, false, false, false><<<gg128(BB * TT, H), 256, SMEM_G8>>>(
            att_, wt_ + WOFF_CAOUT + (long)l * H * H, ca_out_b + (long)l * H, x_, x_, nullptr,
            BB * TT, H, H, H, H, H, 0L, 1);

        // ======== FFN ========
        ln_k<<<BB * TT, 128>>>(x_, ln3_g + l * H, ln3_b + l * H, h_);
        gemm8<EPI_BIAS_GELU, true, false, false><<<gg128(BB * TT, FF), 256, SMEM_G8>>>(
            h_, wt_ + WOFF_FF1 + (long)l * FF * H, ff1_b + (long)l * FF, nullptr, ff_, nullptr,
            BB * TT, FF, H, H, H, FF, 0L, 1);
        if (l < NL - 1) {
            gemm8<EPI_BIAS_RES, false, false, false><<<gg128(BB * TT, H), 256, SMEM_G8>>>(
                ff_, wt_ + WOFF_FF2 + (long)l * H * FF, ff2_b + (long)l * H, x_, x_, nullptr,
                BB * TT, H, FF, FF, FF, H, 0L, 1);
        } else {
            gemm8<EPI_BIAS_RES, false, false, true><<<gg128(BB * TT, H), 256, SMEM_G8>>>(
                ff_, wt_ + WOFF_FF2 + (long)l * H * FF, ff2_b + (long)l * H, x_, x_, xh_,
                BB * TT, H, FF, FF, FF, H, 0L, 1);
        }
    }

    // head
    gemm8<EPI_BIAS, false, false, false><<<gg128(BB * TT, NOUT), 256, SMEM_G8>>>(
        xh_, outwh_, out_b, nullptr, ho_, nullptr,
        BB * TT, NOUT, H, H, H, NOUT, 0L, 1);

    kin_k<<<(BB * TT + 255) / 256, 256>>>(ho_, (float*)d_out);
}

// round 15
// speedup vs baseline: 1.0688x; 1.0033x over previous
#include <cuda_runtime.h>
#include <cuda_fp16.h>
#include <math.h>
#include <stdint.h>

#define H 512
#define BB 32
#define SS 128
#define TT 512
#define NHEAD 8
#define DHD 64
#define NL 4
#define FF 2048
#define NOUT 102
#define NJ 50

// ---------------- scratch ----------------
__device__ __half g_memh[BB * SS * H];
__device__ __half g_m[BB * SS * H];
__device__ __half g_mem[BB * TT * H];
__device__ float  g_x[BB * TT * H];
__device__ __half g_xh[BB * TT * H];
__device__ __half g_h[BB * TT * H];
__device__ __half g_qkv[BB * TT * 3 * H];
__device__ __half g_att[BB * TT * H];
__device__ __half g_ff[BB * TT * FF];
__device__ float  g_head[BB * TT * NOUT];
__device__ float  g_pe[TT * H];
__device__ __half g_convTh[4 * H * H];
__device__ __half g_inwh[H * H];
__device__ __half g_outwh[NOUT * H];
__device__ __half g_wth[16777216];

#define WOFF_SAIN  0
#define WOFF_SAOUT 3145728
#define WOFF_CAIN  4194304
#define WOFF_CAOUT 7340032
#define WOFF_FF1   8388608
#define WOFF_FF2   12582912

__constant__ int PAR[NJ] = {
    -1, 0, 1, 2, 3, 1, 5, 6, 1,
    4, 9, 10, 11,  4, 13, 14, 15,  4, 17, 18, 19,  4, 21, 22, 23,  4, 25, 26, 27,
    7, 29, 30, 31, 7, 33, 34, 35,  7, 37, 38, 39,  7, 41, 42, 43,  7, 45, 46, 47,
    8
};

#define EPI_BIAS 2
#define EPI_BIAS_RES 3
#define EPI_BIAS_GELU 4
#define EPI_CONV 5

// ---------------- ptx helpers ----------------
__device__ __forceinline__ void cp16(uint32_t dst, const void* src)
{
    asm volatile("cp.async.cg.shared.global [%0], [%1], 16;\n" :: "r"(dst), "l"(src));
}
__device__ __forceinline__ void cp16z(uint32_t dst, const void* src, bool p)
{
    int sz = p ? 16 : 0;
    asm volatile("cp.async.cg.shared.global [%0], [%1], 16, %2;\n"
                 :: "r"(dst), "l"(src), "r"(sz));
}
__device__ __forceinline__ void cpcommit()
{
    asm volatile("cp.async.commit_group;\n" ::: "memory");
}
template <int W>
__device__ __forceinline__ void cpwait()
{
    asm volatile("cp.async.wait_group %0;\n" :: "n"(W) : "memory");
}
__device__ __forceinline__ void mma16(float* d, const uint32_t* a, const uint32_t* b)
{
    asm volatile(
        "mma.sync.aligned.m16n8k16.row.col.f32.f16.f16.f32 "
        "{%0,%1,%2,%3}, {%4,%5,%6,%7}, {%8,%9}, {%0,%1,%2,%3};\n"
        : "+f"(d[0]), "+f"(d[1]), "+f"(d[2]), "+f"(d[3])
        : "r"(a[0]), "r"(a[1]), "r"(a[2]), "r"(a[3]), "r"(b[0]), "r"(b[1]));
}
__device__ __forceinline__ void ldsm4(uint32_t* r, uint32_t addr)
{
    asm volatile("ldmatrix.sync.aligned.m8n8.x4.shared.b16 {%0,%1,%2,%3}, [%4];\n"
                 : "=r"(r[0]), "=r"(r[1]), "=r"(r[2]), "=r"(r[3]) : "r"(addr));
}
__device__ __forceinline__ void ldsm2t(uint32_t* r, uint32_t addr)
{
    asm volatile("ldmatrix.sync.aligned.m8n8.x2.trans.shared.b16 {%0,%1}, [%2];\n"
                 : "=r"(r[0]), "=r"(r[1]) : "r"(addr));
}

// ---------------- fp16 tensor-core GEMM: 4-stage, m16n8k16, 256 thr ----------------
// C[r,c] = sum_k Asel[r,k] * B[c,k]
// QS: scale cols < H by 1/8. DUAL: extra fp16 copy to C2.
// MIX: column blocks with col0 < H read A, others read A2 (merged cross-attn proj).
template <int EPI, bool HOUT, bool QS, bool DUAL, bool MIX>
__global__ void __launch_bounds__(256, 2) gemm8(
    const __half* __restrict__ A, const __half* __restrict__ A2,
    const __half* __restrict__ Bm,
    const float* __restrict__ bias, const float* __restrict__ resid,
    void* __restrict__ C, __half* __restrict__ C2,
    int M, int N, int K, int lda, int ldb, int ldc,
    long sBh, int nh)
{
    constexpr int BM = 128, BN_ = 128, BK = 32;
    constexpr int LDE = BK + 8;
    constexpr int STGH = BM * LDE * 2;
    constexpr int CH = BM * BK / 8 / 256;
    constexpr int NST = 4;

    extern __shared__ char smc[];
    const uint32_t smu = (uint32_t)__cvta_generic_to_shared(smc);

    const int z = blockIdx.z;
    const int hh = z % nh;
    Bm += (long)hh * sBh;

    const int row0 = blockIdx.y * BM;
    const int col0 = blockIdx.x * BN_;
    const __half* Ause = (MIX && col0 >= H) ? A2 : A;

    const int tid = threadIdx.x;
    const int warp = tid >> 5;
    const int lane = tid & 31;
    const int wm = warp >> 2;
    const int wn = warp & 3;
    const int gid = lane >> 2;
    const int tig = lane & 3;
    const int l15 = lane & 15;
    const int ah = (lane >> 4) << 3;

    float acc[4][4][4];
#pragma unroll
    for (int i = 0; i < 4; i++)
#pragma unroll
        for (int j = 0; j < 4; j++)
#pragma unroll
            for (int q = 0; q < 4; q++) acc[i][j][q] = 0.f;

    auto cpTile = [&](int k0, int st) {
        uint32_t abase = smu + (uint32_t)(st * STGH) * 2;
#pragma unroll
        for (int l = 0; l < CH; l++) {
            int idx = l * 256 + tid;
            int r = idx >> 2;
            int cq = (idx & 3) * 8;
            cp16(abase + (uint32_t)(r * LDE + cq) * 2,
                 Ause + (long)(row0 + r) * lda + k0 + cq);
        }
        uint32_t bbase = abase + (uint32_t)(BM * LDE) * 2;
#pragma unroll
        for (int l = 0; l < CH; l++) {
            int idx = l * 256 + tid;
            int n = idx >> 2;
            int cq = (idx & 3) * 8;
            cp16z(bbase + (uint32_t)(n * LDE + cq) * 2,
                  Bm + (long)(col0 + n) * ldb + k0 + cq,
                  (col0 + n) < N);
        }
        cpcommit();
    };

    auto compute = [&](int st) {
        const uint32_t pAu = smu + (uint32_t)(st * STGH) * 2;
        const uint32_t pBu = pAu + (uint32_t)(BM * LDE) * 2;
#pragma unroll
        for (int ks = 0; ks < 2; ks++) {
            const int k = ks * 16;
            uint32_t af[4][4], bf[4][2];
#pragma unroll
            for (int mi = 0; mi < 4; mi++) {
                int r0 = wm * 64 + mi * 16 + l15;
                ldsm4(af[mi], pAu + (uint32_t)(r0 * LDE + k + ah) * 2);
            }
#pragma unroll
            for (int pb = 0; pb < 2; pb++) {
                uint32_t q[4];
                int n0 = wn * 32 + pb * 16 + l15;
                ldsm4(q, pBu + (uint32_t)(n0 * LDE + k + ah) * 2);
                bf[pb * 2][0] = q[0];     bf[pb * 2][1] = q[2];
                bf[pb * 2 + 1][0] = q[1]; bf[pb * 2 + 1][1] = q[3];
            }
#pragma unroll
            for (int mi = 0; mi < 4; mi++)
#pragma unroll
                for (int ni = 0; ni < 4; ni++)
                    mma16(acc[mi][ni], af[mi], bf[ni]);
        }
    };

    const int nt = K / BK;                  // >= 16 for all shapes used
    cpTile(0, 0);
    cpTile(BK, 1);
    cpTile(2 * BK, 2);
    int st = 0;
    for (int t = 0; t < nt; t++) {
        if (t <= nt - 3)      cpwait<2>();
        else if (t == nt - 2) cpwait<1>();
        else                  cpwait<0>();
        __syncthreads();
        if (t + 3 < nt) {
            int st3 = st + 3; if (st3 >= NST) st3 -= NST;
            cpTile((t + 3) * BK, st3);
        }
        compute(st);
        if (++st == NST) st = 0;
    }

    auto emit2 = [&](int r, int c, float v0, float v1) {
        v0 += bias[c];
        v1 += bias[c + 1];
        if (QS && c < H) { v0 *= 0.125f; v1 *= 0.125f; }
        if (EPI == EPI_BIAS_GELU) {
            v0 = 0.5f * v0 * (1.f + erff(v0 * 0.70710678118654752f));
            v1 = 0.5f * v1 * (1.f + erff(v1 * 0.70710678118654752f));
        }
        long idx;
        if (EPI == EPI_CONV) {
            int b_ = r >> 7;
            int s_ = r & 127;
            int t_ = s_ * 4 + hh;
            float2 rv = *(const float2*)&resid[t_ * H + c];
            v0 += rv.x; v1 += rv.y;
            idx = ((long)b_ * TT + t_) * ldc + c;
        } else {
            idx = (long)r * ldc + c;
            if (EPI == EPI_BIAS_RES) {
                float2 rv = *(const float2*)&resid[idx];
                v0 += rv.x; v1 += rv.y;
            }
        }
        if (HOUT) *(__half2*)((__half*)C + idx) = __floats2half2_rn(v0, v1);
        else      *(float2*)((float*)C + idx) = make_float2(v0, v1);
        if (DUAL) *(__half2*)(C2 + idx) = __floats2half2_rn(v0, v1);
    };

#pragma unroll
    for (int mi = 0; mi < 4; mi++) {
        int r0 = row0 + wm * 64 + mi * 16 + gid;
#pragma unroll
        for (int ni = 0; ni < 4; ni++) {
            int c0 = col0 + wn * 32 + ni * 8 + tig * 2;
            if (c0 < N) {
                emit2(r0,     c0, acc[mi][ni][0], acc[mi][ni][1]);
                emit2(r0 + 8, c0, acc[mi][ni][2], acc[mi][ni][3]);
            }
        }
    }
}

// ---------------- fused flash attention: single KV buffer, 2 CTAs/SM ----------------
#define FAB_Q 0
#define FAB_K 18432
#define FAB_V 36864
#define FAB_P 55296
#define FAB_RED 90112
#define FAB_M 92160
#define FAB_L 92672
#define FAB_AL 93184
#define FA_BYTES 93696

__global__ void __launch_bounds__(256, 2) fattn_k(
    const __half* __restrict__ qkv, __half* __restrict__ att)
{
    extern __shared__ char smc[];
    __half* sP = (__half*)(smc + FAB_P);
    float* sRed = (float*)(smc + FAB_RED);
    float* sM = (float*)(smc + FAB_M);
    float* sL = (float*)(smc + FAB_L);
    float* sAl = (float*)(smc + FAB_AL);
    const uint32_t smu = (uint32_t)__cvta_generic_to_shared(smc);

    const int z = blockIdx.y;
    const int bb = z >> 3, hh = z & 7;
    const int q0 = blockIdx.x * 128;
    const long base = (long)bb * TT * 3 * H + (long)hh * DHD;

    const int tid = threadIdx.x;
    const int warp = tid >> 5, lane = tid & 31;
    const int wm = warp >> 2, wn = warp & 3;
    const int gid = lane >> 2, tig = lane & 3;
    const int l15 = lane & 15;
    const int ah = (lane >> 4) << 3;

#pragma unroll
    for (int l = 0; l < 4; l++) {
        int idx = l * 256 + tid;
        int r = idx >> 3, c8 = (idx & 7) * 8;
        cp16(smu + FAB_Q + (uint32_t)(r * 72 + c8) * 2,
             qkv + base + (long)(q0 + r) * (3 * H) + c8);
    }
    cpcommit();
    cpwait<0>();

    if (tid < 128) { sM[tid] = -1e30f; sL[tid] = 0.f; }

    float oacc[4][2][4];
#pragma unroll
    for (int mi = 0; mi < 4; mi++)
#pragma unroll
        for (int ni = 0; ni < 2; ni++)
#pragma unroll
            for (int q = 0; q < 4; q++) oacc[mi][ni][q] = 0.f;

    for (int j = 0; j < 4; j++) {
        __syncthreads();
#pragma unroll
        for (int l = 0; l < 4; l++) {
            int idx = l * 256 + tid;
            int r = idx >> 3, c8 = (idx & 7) * 8;
            long row = (long)(j * 128 + r) * (3 * H);
            cp16(smu + FAB_K + (uint32_t)(r * 72 + c8) * 2, qkv + base + H + row + c8);
            cp16(smu + FAB_V + (uint32_t)(r * 72 + c8) * 2, qkv + base + 2 * H + row + c8);
        }
        cpcommit();
        cpwait<0>();
        __syncthreads();

        float sacc[4][4][4];
#pragma unroll
        for (int mi = 0; mi < 4; mi++)
#pragma unroll
            for (int ni = 0; ni < 4; ni++)
#pragma unroll
                for (int q = 0; q < 4; q++) sacc[mi][ni][q] = 0.f;
#pragma unroll
        for (int ks = 0; ks < 4; ks++) {
            const int k = ks * 16;
            uint32_t af[4][4], bf[4][2];
#pragma unroll
            for (int mi = 0; mi < 4; mi++) {
                int r0 = wm * 64 + mi * 16 + l15;
                ldsm4(af[mi], smu + FAB_Q + (uint32_t)(r0 * 72 + k + ah) * 2);
            }
#pragma unroll
            for (int pb = 0; pb < 2; pb++) {
                uint32_t q[4];
                int n0 = wn * 32 + pb * 16 + l15;
                ldsm4(q, smu + FAB_K + (uint32_t)(n0 * 72 + k + ah) * 2);
                bf[pb * 2][0] = q[0];     bf[pb * 2][1] = q[2];
                bf[pb * 2 + 1][0] = q[1]; bf[pb * 2 + 1][1] = q[3];
            }
#pragma unroll
            for (int mi = 0; mi < 4; mi++)
#pragma unroll
                for (int ni = 0; ni < 4; ni++)
                    mma16(sacc[mi][ni], af[mi], bf[ni]);
        }

#pragma unroll
        for (int mi = 0; mi < 4; mi++) {
            float r0m = -1e30f, r1m = -1e30f;
#pragma unroll
            for (int ni = 0; ni < 4; ni++) {
                r0m = fmaxf(r0m, fmaxf(sacc[mi][ni][0], sacc[mi][ni][1]));
                r1m = fmaxf(r1m, fmaxf(sacc[mi][ni][2], sacc[mi][ni][3]));
            }
            r0m = fmaxf(r0m, __shfl_xor_sync(0xffffffffu, r0m, 1));
            r0m = fmaxf(r0m, __shfl_xor_sync(0xffffffffu, r0m, 2));
            r1m = fmaxf(r1m, __shfl_xor_sync(0xffffffffu, r1m, 1));
            r1m = fmaxf(r1m, __shfl_xor_sync(0xffffffffu, r1m, 2));
            if (tig == 0) {
                int r0 = wm * 64 + mi * 16 + gid;
                sRed[wn * 128 + r0] = r0m;
                sRed[wn * 128 + r0 + 8] = r1m;
            }
        }
        __syncthreads();
        if (tid < 128) {
            float mt = fmaxf(fmaxf(sRed[tid], sRed[128 + tid]),
                             fmaxf(sRed[256 + tid], sRed[384 + tid]));
            float mo = sM[tid];
            float mn = fmaxf(mo, mt);
            sAl[tid] = __expf(mo - mn);
            sM[tid] = mn;
        }
        __syncthreads();

#pragma unroll
        for (int mi = 0; mi < 4; mi++) {
            int r0 = wm * 64 + mi * 16 + gid;
            float m0 = sM[r0], m1 = sM[r0 + 8];
            float rs0 = 0.f, rs1 = 0.f;
#pragma unroll
            for (int ni = 0; ni < 4; ni++) {
                int c0 = wn * 32 + ni * 8 + tig * 2;
                float p00 = __expf(sacc[mi][ni][0] - m0);
                float p01 = __expf(sacc[mi][ni][1] - m0);
                float p10 = __expf(sacc[mi][ni][2] - m1);
                float p11 = __expf(sacc[mi][ni][3] - m1);
                rs0 += p00 + p01;
                rs1 += p10 + p11;
                *(__half2*)&sP[r0 * 136 + c0] = __floats2half2_rn(p00, p01);
                *(__half2*)&sP[(r0 + 8) * 136 + c0] = __floats2half2_rn(p10, p11);
            }
            rs0 += __shfl_xor_sync(0xffffffffu, rs0, 1);
            rs0 += __shfl_xor_sync(0xffffffffu, rs0, 2);
            rs1 += __shfl_xor_sync(0xffffffffu, rs1, 1);
            rs1 += __shfl_xor_sync(0xffffffffu, rs1, 2);
            if (tig == 0) {
                sRed[wn * 128 + r0] = rs0;
                sRed[wn * 128 + r0 + 8] = rs1;
            }
        }
        __syncthreads();
        if (tid < 128) {
            sL[tid] = sL[tid] * sAl[tid] +
                      (sRed[tid] + sRed[128 + tid]) + (sRed[256 + tid] + sRed[384 + tid]);
        }

#pragma unroll
        for (int mi = 0; mi < 4; mi++) {
            int r0 = wm * 64 + mi * 16 + gid;
            float a0 = sAl[r0], a1 = sAl[r0 + 8];
#pragma unroll
            for (int ni = 0; ni < 2; ni++) {
                oacc[mi][ni][0] *= a0;
                oacc[mi][ni][1] *= a0;
                oacc[mi][ni][2] *= a1;
                oacc[mi][ni][3] *= a1;
            }
        }

#pragma unroll
        for (int ks = 0; ks < 8; ks++) {
            const int k = ks * 16;
            uint32_t af[4][4], bf[2][2];
#pragma unroll
            for (int mi = 0; mi < 4; mi++) {
                int r0 = wm * 64 + mi * 16 + l15;
                ldsm4(af[mi], smu + FAB_P + (uint32_t)(r0 * 136 + k + ah) * 2);
            }
#pragma unroll
            for (int ni = 0; ni < 2; ni++) {
                int n0 = wn * 16 + ni * 8;
                ldsm2t(bf[ni], smu + FAB_V + (uint32_t)((k + l15) * 72 + n0) * 2);
            }
#pragma unroll
            for (int mi = 0; mi < 4; mi++)
#pragma unroll
                for (int ni = 0; ni < 2; ni++)
                    mma16(oacc[mi][ni], af[mi], bf[ni]);
        }
    }
    __syncthreads();

#pragma unroll
    for (int mi = 0; mi < 4; mi++) {
        int r0 = wm * 64 + mi * 16 + gid;
        float i0 = 1.f / sL[r0], i1 = 1.f / sL[r0 + 8];
        long o0 = ((long)bb * TT + q0 + r0) * H + hh * DHD;
        long o1 = ((long)bb * TT + q0 + r0 + 8) * H + hh * DHD;
#pragma unroll
        for (int ni = 0; ni < 2; ni++) {
            int c0 = wn * 16 + ni * 8 + tig * 2;
            *(__half2*)&att[o0 + c0] = __floats2half2_rn(oacc[mi][ni][0] * i0, oacc[mi][ni][1] * i0);
            *(__half2*)&att[o1 + c0] = __floats2half2_rn(oacc[mi][ni][2] * i1, oacc[mi][ni][3] * i1);
        }
    }
}

// ---------------- LayerNorm: fp32 in, fp16 out ----------------
__global__ void ln_k(const float* __restrict__ x, const float* __restrict__ g,
                     const float* __restrict__ b, __half* __restrict__ o)
{
    long row = blockIdx.x;
    int t = threadIdx.x;
    float4 v = ((const float4*)(x + row * H))[t];
    float s = v.x + v.y + v.z + v.w;
    float ss = v.x * v.x + v.y * v.y + v.z * v.z + v.w * v.w;
#pragma unroll
    for (int off = 16; off; off >>= 1) {
        s += __shfl_xor_sync(0xffffffffu, s, off);
        ss += __shfl_xor_sync(0xffffffffu, ss, off);
    }
    __shared__ float sm0[4], sm1[4];
    int w = t >> 5;
    if ((t & 31) == 0) { sm0[w] = s; sm1[w] = ss; }
    __syncthreads();
    s = sm0[0] + sm0[1] + sm0[2] + sm0[3];
    ss = sm1[0] + sm1[1] + sm1[2] + sm1[3];
    float mean = s * (1.f / H);
    float var = ss * (1.f / H) - mean * mean;
    float rstd = rsqrtf(var + 1e-5f);
    float4 gg = ((const float4*)g)[t];
    float4 bb4 = ((const float4*)b)[t];
    __half2* op = (__half2*)(o + row * H);
    op[t * 2]     = __floats2half2_rn((v.x - mean) * rstd * gg.x + bb4.x,
                                      (v.y - mean) * rstd * gg.y + bb4.y);
    op[t * 2 + 1] = __floats2half2_rn((v.z - mean) * rstd * gg.z + bb4.z,
                                      (v.w - mean) * rstd * gg.w + bb4.w);
}

// ---------------- misc kernels ----------------
__global__ void cvth_k(const float* __restrict__ in, __half* __restrict__ out, int n4)
{
    int stride = gridDim.x * blockDim.x;
    for (int i = blockIdx.x * blockDim.x + threadIdx.x; i < n4; i += stride) {
        float4 v = ((const float4*)in)[i];
        ((__half2*)out)[i * 2]     = __floats2half2_rn(v.x, v.y);
        ((__half2*)out)[i * 2 + 1] = __floats2half2_rn(v.z, v.w);
    }
}

__global__ void pe_k(float* __restrict__ pe)
{
    int t = blockIdx.x;
    int i = threadIdx.x;
    float div = expf(-(float)(2 * i) * (logf(10000.f) / (float)H));
    float a = (float)t * div;
    pe[t * H + 2 * i] = sinf(a);
    pe[t * H + 2 * i + 1] = cosf(a);
}

__global__ void convT_k(const float* __restrict__ w, __half* __restrict__ o)
{
    int idx = blockIdx.x * blockDim.x + threadIdx.x;
    if (idx >= 4 * H * H) return;
    int k = idx / (H * H);
    int d = (idx / H) % H;
    int c = idx % H;
    o[idx] = __float2half_rn(w[c * H * 4 + d * 4 + k]);
}

__global__ void xinit_k(const float* __restrict__ qe, const float* __restrict__ pe,
                        float* __restrict__ x)
{
    long i = blockIdx.x * (long)blockDim.x + threadIdx.x;
    if (i >= (long)BB * TT * H) return;
    int td = (int)(i % (TT * H));
    x[i] = qe[td] + pe[td];
}

__global__ void kin_k(const float* __restrict__ ho, float* __restrict__ out)
{
    int row = blockIdx.x * blockDim.x + threadIdx.x;
    if (row >= BB * TT) return;
    const float* r = ho + (long)row * NOUT;
    float* o = out + (long)row * (3 * NJ);
    float gx[NJ], px[NJ], py[NJ];
    gx[0] = 0.f;
    px[0] = r[100];
    py[0] = r[101];
    o[0] = px[0]; o[1] = py[0]; o[2] = 1.f;
    for (int j = 1; j < NJ; j++) {
        int pa = PAR[j];
        float gg = gx[pa] + r[j];
        gx[j] = gg;
        float s = r[50 + j];
        float sn, cs;
        sincosf(gg, &sn, &cs);
        px[j] = px[pa] + cs * s;
        py[j] = py[pa] + sn * s;
        o[j * 3 + 0] = px[j];
        o[j * 3 + 1] = py[j];
        o[j * 3 + 2] = 1.f;
    }
}

// ---------------- launcher ----------------
static inline dim3 gg128(int M, int N, int bz = 1)
{
    return dim3((N + 127) / 128, (M + 127) / 128, bz);
}

#define SMEM_G8 81920   // 4 stages x 20480 B

extern "C" void kernel_launch(void* const* d_in, const int* in_sizes, int n_in,
                              void* d_out, int out_size)
{
    const float* memory   = (const float*)d_in[0];
    const float* in_w     = (const float*)d_in[1];
    const float* in_b     = (const float*)d_in[2];
    const float* conv_w   = (const float*)d_in[3];
    const float* conv_b   = (const float*)d_in[4];
    const float* qemb     = (const float*)d_in[5];
    const float* sa_in_w  = (const float*)d_in[6];
    const float* sa_in_b  = (const float*)d_in[7];
    const float* sa_out_w = (const float*)d_in[8];
    const float* sa_out_b = (const float*)d_in[9];
    const float* ca_in_w  = (const float*)d_in[10];
    const float* ca_in_b  = (const float*)d_in[11];
    const float* ca_out_w = (const float*)d_in[12];
    const float* ca_out_b = (const float*)d_in[13];
    const float* ln1_g    = (const float*)d_in[14];
    const float* ln1_b    = (const float*)d_in[15];
    const float* ln2_g    = (const float*)d_in[16];
    const float* ln2_b    = (const float*)d_in[17];
    const float* ln3_g    = (const float*)d_in[18];
    const float* ln3_b    = (const float*)d_in[19];
    const float* ff1_w    = (const float*)d_in[20];
    const float* ff1_b    = (const float*)d_in[21];
    const float* ff2_w    = (const float*)d_in[22];
    const float* ff2_b    = (const float*)d_in[23];
    const float* out_w    = (const float*)d_in[24];
    const float* out_b    = (const float*)d_in[25];

    __half *memh_, *m_, *mem_, *xh_, *h_, *qkv_, *att_, *ff_, *cT_, *inwh_, *outwh_, *wt_;
    float *x_, *ho_, *pe_;
    cudaGetSymbolAddress((void**)&memh_, g_memh);
    cudaGetSymbolAddress((void**)&m_,    g_m);
    cudaGetSymbolAddress((void**)&mem_,  g_mem);
    cudaGetSymbolAddress((void**)&x_,    g_x);
    cudaGetSymbolAddress((void**)&xh_,   g_xh);
    cudaGetSymbolAddress((void**)&h_,    g_h);
    cudaGetSymbolAddress((void**)&qkv_,  g_qkv);
    cudaGetSymbolAddress((void**)&att_,  g_att);
    cudaGetSymbolAddress((void**)&ff_,   g_ff);
    cudaGetSymbolAddress((void**)&ho_,   g_head);
    cudaGetSymbolAddress((void**)&pe_,   g_pe);
    cudaGetSymbolAddress((void**)&cT_,   g_convTh);
    cudaGetSymbolAddress((void**)&inwh_, g_inwh);
    cudaGetSymbolAddress((void**)&outwh_,g_outwh);
    cudaGetSymbolAddress((void**)&wt_,   g_wth);

    cudaFuncSetAttribute(gemm8<EPI_BIAS,      true,  true,  false, false>, cudaFuncAttributeMaxDynamicSharedMemorySize, SMEM_G8);
    cudaFuncSetAttribute(gemm8<EPI_BIAS,      true,  true,  false, true >, cudaFuncAttributeMaxDynamicSharedMemorySize, SMEM_G8);
    cudaFuncSetAttribute(gemm8<EPI_BIAS,      true,  false, false, false>, cudaFuncAttributeMaxDynamicSharedMemorySize, SMEM_G8);
    cudaFuncSetAttribute(gemm8<EPI_CONV,      true,  false, false, false>, cudaFuncAttributeMaxDynamicSharedMemorySize, SMEM_G8);
    cudaFuncSetAttribute(gemm8<EPI_BIAS_RES,  false, false, false, false>, cudaFuncAttributeMaxDynamicSharedMemorySize, SMEM_G8);
    cudaFuncSetAttribute(gemm8<EPI_BIAS_RES,  false, false, true,  false>, cudaFuncAttributeMaxDynamicSharedMemorySize, SMEM_G8);
    cudaFuncSetAttribute(gemm8<EPI_BIAS_GELU, true,  false, false, false>, cudaFuncAttributeMaxDynamicSharedMemorySize, SMEM_G8);
    cudaFuncSetAttribute(gemm8<EPI_BIAS,      false, false, false, false>, cudaFuncAttributeMaxDynamicSharedMemorySize, SMEM_G8);
    cudaFuncSetAttribute(fattn_k, cudaFuncAttributeMaxDynamicSharedMemorySize, FA_BYTES);

    // prep
    pe_k<<<TT, 256>>>(pe_);
    convT_k<<<(4 * H * H + 255) / 256, 256>>>(conv_w, cT_);
    cvth_k<<<1024, 512>>>(memory,   memh_,  2097152 / 4);
    cvth_k<<<512, 512>>>(in_w,      inwh_,  262144 / 4);
    cvth_k<<<32, 512>>>(out_w,      outwh_, 52224 / 4);
    cvth_k<<<1536, 512>>>(sa_in_w,  wt_ + WOFF_SAIN,  3145728 / 4);
    cvth_k<<<512, 512>>>(sa_out_w,  wt_ + WOFF_SAOUT, 1048576 / 4);
    cvth_k<<<1536, 512>>>(ca_in_w,  wt_ + WOFF_CAIN,  3145728 / 4);
    cvth_k<<<512, 512>>>(ca_out_w,  wt_ + WOFF_CAOUT, 1048576 / 4);
    cvth_k<<<2048, 512>>>(ff1_w,    wt_ + WOFF_FF1,   4194304 / 4);
    cvth_k<<<2048, 512>>>(ff2_w,    wt_ + WOFF_FF2,   4194304 / 4);

    // m = memory @ in_w^T + in_b
    gemm8<EPI_BIAS, true, false, false, false><<<gg128(BB * SS, H), 256, SMEM_G8>>>(
        memh_, nullptr, inwh_, in_b, nullptr, m_, nullptr,
        BB * SS, H, H, H, H, H, 0L, 1);

    // conv upsample (4 taps batched over z; tap = hh)
    gemm8<EPI_CONV, true, false, false, false><<<gg128(BB * SS, H, 4), 256, SMEM_G8>>>(
        m_, nullptr, cT_, conv_b, pe_, mem_, nullptr,
        BB * SS, H, H, H, H, H, (long)H * H, 4);

    xinit_k<<<(BB * TT * H + 255) / 256, 256>>>(qemb, pe_, x_);

    const dim3 fa_grid(TT / 128, BB * NHEAD);

    for (int l = 0; l < NL; l++) {
        // ======== self-attention ========
        ln_k<<<BB * TT, 128>>>(x_, ln1_g + l * H, ln1_b + l * H, h_);
        gemm8<EPI_BIAS, true, true, false, false><<<gg128(BB * TT, 3 * H), 256, SMEM_G8>>>(
            h_, nullptr, wt_ + WOFF_SAIN + (long)l * 3 * H * H, sa_in_b + (long)l * 3 * H,
            nullptr, qkv_, nullptr,
            BB * TT, 3 * H, H, H, H, 3 * H, 0L, 1);
        fattn_k<<<fa_grid, 256, FA_BYTES>>>(qkv_, att_);
        gemm8<EPI_BIAS_RES, false, false, false, false><<<gg128(BB * TT, H), 256, SMEM_G8>>>(
            att_, nullptr, wt_ + WOFF_SAOUT + (long)l * H * H, sa_out_b + (long)l * H,
            x_, x_, nullptr,
            BB * TT, H, H, H, H, H, 0L, 1);

        // ======== cross-attention (merged q + kv projection) ========
        ln_k<<<BB * TT, 128>>>(x_, ln2_g + l * H, ln2_b + l * H, h_);
        gemm8<EPI_BIAS, true, true, false, true><<<gg128(BB * TT, 3 * H), 256, SMEM_G8>>>(
            h_, mem_, wt_ + WOFF_CAIN + (long)l * 3 * H * H, ca_in_b + (long)l * 3 * H,
            nullptr, qkv_, nullptr,
            BB * TT, 3 * H, H, H, H, 3 * H, 0L, 1);
        fattn_k<<<fa_grid, 256, FA_BYTES>>>(qkv_, att_);
        gemm8<EPI_BIAS_RES, false, false, false, false><<<gg128(BB * TT, H), 256, SMEM_G8>>>(
            att_, nullptr, wt_ + WOFF_CAOUT + (long)l * H * H, ca_out_b + (long)l * H,
            x_, x_, nullptr,
            BB * TT, H, H, H, H, H, 0L, 1);

        // ======== FFN ========
        ln_k<<<BB * TT, 128>>>(x_, ln3_g + l * H, ln3_b + l * H, h_);
        gemm8<EPI_BIAS_GELU, true, false, false, false><<<gg128(BB * TT, FF), 256, SMEM_G8>>>(
            h_, nullptr, wt_ + WOFF_FF1 + (long)l * FF * H, ff1_b + (long)l * FF,
            nullptr, ff_, nullptr,
            BB * TT, FF, H, H, H, FF, 0L, 1);
        if (l < NL - 1) {
            gemm8<EPI_BIAS_RES, false, false, false, false><<<gg128(BB * TT, H), 256, SMEM_G8>>>(
                ff_, nullptr, wt_ + WOFF_FF2 + (long)l * H * FF, ff2_b + (long)l * H,
                x_, x_, nullptr,
                BB * TT, H, FF, FF, FF, H, 0L, 1);
        } else {
            gemm8<EPI_BIAS_RES, false, false, true, false><<<gg128(BB * TT, H), 256, SMEM_G8>>>(
                ff_, nullptr, wt_ + WOFF_FF2 + (long)l * H * FF, ff2_b + (long)l * H,
                x_, x_, xh_,
                BB * TT, H, FF, FF, FF, H, 0L, 1);
        }
    }

    // head
    gemm8<EPI_BIAS, false, false, false, false><<<gg128(BB * TT, NOUT), 256, SMEM_G8>>>(
        xh_, nullptr, outwh_, out_b, nullptr, ho_, nullptr,
        BB * TT, NOUT, H, H, H, NOUT, 0L, 1);

    kin_k<<<(BB * TT + 255) / 256, 256>>>(ho_, (float*)d_out);
}

// round 16
// speedup vs baseline: 1.1478x; 1.0738x over previous
#include <cuda_runtime.h>
#include <cuda_fp16.h>
#include <math.h>
#include <stdint.h>

#define H 512
#define BB 32
#define SS 128
#define TT 512
#define NHEAD 8
#define DHD 64
#define NL 4
#define FF 2048
#define NOUT 102
#define NJ 50

// ---------------- scratch ----------------
__device__ __half g_memh[BB * SS * H];
__device__ __half g_m[BB * SS * H];
__device__ __half g_mem[BB * TT * H];
__device__ float  g_x[BB * TT * H];
__device__ __half g_xh[BB * TT * H];
__device__ __half g_h[BB * TT * H];
__device__ __half g_qkv[BB * TT * 3 * H];
__device__ __half g_att[BB * TT * H];
__device__ __half g_ff[BB * TT * FF];
__device__ float  g_head[BB * TT * NOUT];
__device__ float  g_pe[TT * H];
__device__ __half g_convTh[4 * H * H];
__device__ __half g_inwh[H * H];
__device__ __half g_outwh[NOUT * H];
__device__ __half g_wth[16777216];

#define WOFF_SAIN  0
#define WOFF_SAOUT 3145728
#define WOFF_CAIN  4194304
#define WOFF_CAOUT 7340032
#define WOFF_FF1   8388608
#define WOFF_FF2   12582912

__constant__ int PAR[NJ] = {
    -1, 0, 1, 2, 3, 1, 5, 6, 1,
    4, 9, 10, 11,  4, 13, 14, 15,  4, 17, 18, 19,  4, 21, 22, 23,  4, 25, 26, 27,
    7, 29, 30, 31, 7, 33, 34, 35,  7, 37, 38, 39,  7, 41, 42, 43,  7, 45, 46, 47,
    8
};

#define EPI_BIAS 2
#define EPI_BIAS_RES 3
#define EPI_BIAS_GELU 4
#define EPI_CONV 5

// ---------------- ptx helpers ----------------
__device__ __forceinline__ void cp16(uint32_t dst, const void* src)
{
    asm volatile("cp.async.cg.shared.global [%0], [%1], 16;\n" :: "r"(dst), "l"(src));
}
__device__ __forceinline__ void cp16z(uint32_t dst, const void* src, bool p)
{
    int sz = p ? 16 : 0;
    asm volatile("cp.async.cg.shared.global [%0], [%1], 16, %2;\n"
                 :: "r"(dst), "l"(src), "r"(sz));
}
__device__ __forceinline__ void cpcommit()
{
    asm volatile("cp.async.commit_group;\n" ::: "memory");
}
template <int W>
__device__ __forceinline__ void cpwait()
{
    asm volatile("cp.async.wait_group %0;\n" :: "n"(W) : "memory");
}
__device__ __forceinline__ void mma16(float* d, const uint32_t* a, const uint32_t* b)
{
    asm volatile(
        "mma.sync.aligned.m16n8k16.row.col.f32.f16.f16.f32 "
        "{%0,%1,%2,%3}, {%4,%5,%6,%7}, {%8,%9}, {%0,%1,%2,%3};\n"
        : "+f"(d[0]), "+f"(d[1]), "+f"(d[2]), "+f"(d[3])
        : "r"(a[0]), "r"(a[1]), "r"(a[2]), "r"(a[3]), "r"(b[0]), "r"(b[1]));
}
__device__ __forceinline__ void ldsm4(uint32_t* r, uint32_t addr)
{
    asm volatile("ldmatrix.sync.aligned.m8n8.x4.shared.b16 {%0,%1,%2,%3}, [%4];\n"
                 : "=r"(r[0]), "=r"(r[1]), "=r"(r[2]), "=r"(r[3]) : "r"(addr));
}
__device__ __forceinline__ void ldsm2t(uint32_t* r, uint32_t addr)
{
    asm volatile("ldmatrix.sync.aligned.m8n8.x2.trans.shared.b16 {%0,%1}, [%2];\n"
                 : "=r"(r[0]), "=r"(r[1]) : "r"(addr));
}

// ---------------- fp16 tensor-core GEMM: BK=64, 3-stage, m16n8k16, 256 thr ----------------
// C[r,c] = sum_k Asel[r,k] * B[c,k]
// QS: scale cols < H by 1/8. DUAL: extra fp16 copy to C2.
// MIX: column blocks with col0 < H read A, others read A2 (merged cross-attn proj).
template <int EPI, bool HOUT, bool QS, bool DUAL, bool MIX>
__global__ void __launch_bounds__(256, 2) gemm8(
    const __half* __restrict__ A, const __half* __restrict__ A2,
    const __half* __restrict__ Bm,
    const float* __restrict__ bias, const float* __restrict__ resid,
    void* __restrict__ C, __half* __restrict__ C2,
    int M, int N, int K, int lda, int ldb, int ldc,
    long sBh, int nh)
{
    constexpr int BM = 128, BN_ = 128, BK = 64;
    constexpr int LDE = BK + 8;               // 72 halves pitch
    constexpr int STGH = BM * LDE * 2;        // halves per stage (A+B) = 18432
    constexpr int CH = BM * BK / 8 / 256;     // 4 chunks per thread per operand
    constexpr int NST = 3;

    extern __shared__ char smc[];
    const uint32_t smu = (uint32_t)__cvta_generic_to_shared(smc);

    const int z = blockIdx.z;
    const int hh = z % nh;
    Bm += (long)hh * sBh;

    const int row0 = blockIdx.y * BM;
    const int col0 = blockIdx.x * BN_;
    const __half* Ause = (MIX && col0 >= H) ? A2 : A;

    const int tid = threadIdx.x;
    const int warp = tid >> 5;
    const int lane = tid & 31;
    const int wm = warp >> 2;
    const int wn = warp & 3;
    const int gid = lane >> 2;
    const int tig = lane & 3;
    const int l15 = lane & 15;
    const int ah = (lane >> 4) << 3;

    float acc[4][4][4];
#pragma unroll
    for (int i = 0; i < 4; i++)
#pragma unroll
        for (int j = 0; j < 4; j++)
#pragma unroll
            for (int q = 0; q < 4; q++) acc[i][j][q] = 0.f;

    auto cpTile = [&](int k0, int st) {
        uint32_t abase = smu + (uint32_t)(st * STGH) * 2;
#pragma unroll
        for (int l = 0; l < CH; l++) {
            int idx = l * 256 + tid;
            int r = idx >> 3;
            int cq = (idx & 7) * 8;
            cp16(abase + (uint32_t)(r * LDE + cq) * 2,
                 Ause + (long)(row0 + r) * lda + k0 + cq);
        }
        uint32_t bbase = abase + (uint32_t)(BM * LDE) * 2;
#pragma unroll
        for (int l = 0; l < CH; l++) {
            int idx = l * 256 + tid;
            int n = idx >> 3;
            int cq = (idx & 7) * 8;
            cp16z(bbase + (uint32_t)(n * LDE + cq) * 2,
                  Bm + (long)(col0 + n) * ldb + k0 + cq,
                  (col0 + n) < N);
        }
        cpcommit();
    };

    auto compute = [&](int st) {
        const uint32_t pAu = smu + (uint32_t)(st * STGH) * 2;
        const uint32_t pBu = pAu + (uint32_t)(BM * LDE) * 2;
#pragma unroll
        for (int ks = 0; ks < 4; ks++) {
            const int k = ks * 16;
            uint32_t af[4][4], bf[4][2];
#pragma unroll
            for (int mi = 0; mi < 4; mi++) {
                int r0 = wm * 64 + mi * 16 + l15;
                ldsm4(af[mi], pAu + (uint32_t)(r0 * LDE + k + ah) * 2);
            }
#pragma unroll
            for (int pb = 0; pb < 2; pb++) {
                uint32_t q[4];
                int n0 = wn * 32 + pb * 16 + l15;
                ldsm4(q, pBu + (uint32_t)(n0 * LDE + k + ah) * 2);
                bf[pb * 2][0] = q[0];     bf[pb * 2][1] = q[2];
                bf[pb * 2 + 1][0] = q[1]; bf[pb * 2 + 1][1] = q[3];
            }
#pragma unroll
            for (int mi = 0; mi < 4; mi++)
#pragma unroll
                for (int ni = 0; ni < 4; ni++)
                    mma16(acc[mi][ni], af[mi], bf[ni]);
        }
    };

    const int nt = K / BK;                  // 8 for K=512, 32 for K=2048
    cpTile(0, 0);
    cpTile(BK, 1);
    int st = 0;
    for (int t = 0; t < nt; t++) {
        if (t < nt - 1) cpwait<1>(); else cpwait<0>();
        __syncthreads();
        if (t + 2 < nt) {
            int st2 = st + 2; if (st2 >= NST) st2 -= NST;
            cpTile((t + 2) * BK, st2);
        }
        compute(st);
        if (++st == NST) st = 0;
    }

    auto emit2 = [&](int r, int c, float v0, float v1) {
        v0 += bias[c];
        v1 += bias[c + 1];
        if (QS && c < H) { v0 *= 0.125f; v1 *= 0.125f; }
        if (EPI == EPI_BIAS_GELU) {
            v0 = 0.5f * v0 * (1.f + erff(v0 * 0.70710678118654752f));
            v1 = 0.5f * v1 * (1.f + erff(v1 * 0.70710678118654752f));
        }
        long idx;
        if (EPI == EPI_CONV) {
            int b_ = r >> 7;
            int s_ = r & 127;
            int t_ = s_ * 4 + hh;
            float2 rv = *(const float2*)&resid[t_ * H + c];
            v0 += rv.x; v1 += rv.y;
            idx = ((long)b_ * TT + t_) * ldc + c;
        } else {
            idx = (long)r * ldc + c;
            if (EPI == EPI_BIAS_RES) {
                float2 rv = *(const float2*)&resid[idx];
                v0 += rv.x; v1 += rv.y;
            }
        }
        if (HOUT) *(__half2*)((__half*)C + idx) = __floats2half2_rn(v0, v1);
        else      *(float2*)((float*)C + idx) = make_float2(v0, v1);
        if (DUAL) *(__half2*)(C2 + idx) = __floats2half2_rn(v0, v1);
    };

#pragma unroll
    for (int mi = 0; mi < 4; mi++) {
        int r0 = row0 + wm * 64 + mi * 16 + gid;
#pragma unroll
        for (int ni = 0; ni < 4; ni++) {
            int c0 = col0 + wn * 32 + ni * 8 + tig * 2;
            if (c0 < N) {
                emit2(r0,     c0, acc[mi][ni][0], acc[mi][ni][1]);
                emit2(r0 + 8, c0, acc[mi][ni][2], acc[mi][ni][3]);
            }
        }
    }
}

// ---------------- fused flash attention: single KV buffer, 2 CTAs/SM ----------------
#define FAB_Q 0
#define FAB_K 18432
#define FAB_V 36864
#define FAB_P 55296
#define FAB_RED 90112
#define FAB_M 92160
#define FAB_L 92672
#define FAB_AL 93184
#define FA_BYTES 93696

__global__ void __launch_bounds__(256, 2) fattn_k(
    const __half* __restrict__ qkv, __half* __restrict__ att)
{
    extern __shared__ char smc[];
    __half* sP = (__half*)(smc + FAB_P);
    float* sRed = (float*)(smc + FAB_RED);
    float* sM = (float*)(smc + FAB_M);
    float* sL = (float*)(smc + FAB_L);
    float* sAl = (float*)(smc + FAB_AL);
    const uint32_t smu = (uint32_t)__cvta_generic_to_shared(smc);

    const int z = blockIdx.y;
    const int bb = z >> 3, hh = z & 7;
    const int q0 = blockIdx.x * 128;
    const long base = (long)bb * TT * 3 * H + (long)hh * DHD;

    const int tid = threadIdx.x;
    const int warp = tid >> 5, lane = tid & 31;
    const int wm = warp >> 2, wn = warp & 3;
    const int gid = lane >> 2, tig = lane & 3;
    const int l15 = lane & 15;
    const int ah = (lane >> 4) << 3;

#pragma unroll
    for (int l = 0; l < 4; l++) {
        int idx = l * 256 + tid;
        int r = idx >> 3, c8 = (idx & 7) * 8;
        cp16(smu + FAB_Q + (uint32_t)(r * 72 + c8) * 2,
             qkv + base + (long)(q0 + r) * (3 * H) + c8);
    }
    cpcommit();
    cpwait<0>();

    if (tid < 128) { sM[tid] = -1e30f; sL[tid] = 0.f; }

    float oacc[4][2][4];
#pragma unroll
    for (int mi = 0; mi < 4; mi++)
#pragma unroll
        for (int ni = 0; ni < 2; ni++)
#pragma unroll
            for (int q = 0; q < 4; q++) oacc[mi][ni][q] = 0.f;

    for (int j = 0; j < 4; j++) {
        __syncthreads();
#pragma unroll
        for (int l = 0; l < 4; l++) {
            int idx = l * 256 + tid;
            int r = idx >> 3, c8 = (idx & 7) * 8;
            long row = (long)(j * 128 + r) * (3 * H);
            cp16(smu + FAB_K + (uint32_t)(r * 72 + c8) * 2, qkv + base + H + row + c8);
            cp16(smu + FAB_V + (uint32_t)(r * 72 + c8) * 2, qkv + base + 2 * H + row + c8);
        }
        cpcommit();
        cpwait<0>();
        __syncthreads();

        float sacc[4][4][4];
#pragma unroll
        for (int mi = 0; mi < 4; mi++)
#pragma unroll
            for (int ni = 0; ni < 4; ni++)
#pragma unroll
                for (int q = 0; q < 4; q++) sacc[mi][ni][q] = 0.f;
#pragma unroll
        for (int ks = 0; ks < 4; ks++) {
            const int k = ks * 16;
            uint32_t af[4][4], bf[4][2];
#pragma unroll
            for (int mi = 0; mi < 4; mi++) {
                int r0 = wm * 64 + mi * 16 + l15;
                ldsm4(af[mi], smu + FAB_Q + (uint32_t)(r0 * 72 + k + ah) * 2);
            }
#pragma unroll
            for (int pb = 0; pb < 2; pb++) {
                uint32_t q[4];
                int n0 = wn * 32 + pb * 16 + l15;
                ldsm4(q, smu + FAB_K + (uint32_t)(n0 * 72 + k + ah) * 2);
                bf[pb * 2][0] = q[0];     bf[pb * 2][1] = q[2];
                bf[pb * 2 + 1][0] = q[1]; bf[pb * 2 + 1][1] = q[3];
            }
#pragma unroll
            for (int mi = 0; mi < 4; mi++)
#pragma unroll
                for (int ni = 0; ni < 4; ni++)
                    mma16(sacc[mi][ni], af[mi], bf[ni]);
        }

#pragma unroll
        for (int mi = 0; mi < 4; mi++) {
            float r0m = -1e30f, r1m = -1e30f;
#pragma unroll
            for (int ni = 0; ni < 4; ni++) {
                r0m = fmaxf(r0m, fmaxf(sacc[mi][ni][0], sacc[mi][ni][1]));
                r1m = fmaxf(r1m, fmaxf(sacc[mi][ni][2], sacc[mi][ni][3]));
            }
            r0m = fmaxf(r0m, __shfl_xor_sync(0xffffffffu, r0m, 1));
            r0m = fmaxf(r0m, __shfl_xor_sync(0xffffffffu, r0m, 2));
            r1m = fmaxf(r1m, __shfl_xor_sync(0xffffffffu, r1m, 1));
            r1m = fmaxf(r1m, __shfl_xor_sync(0xffffffffu, r1m, 2));
            if (tig == 0) {
                int r0 = wm * 64 + mi * 16 + gid;
                sRed[wn * 128 + r0] = r0m;
                sRed[wn * 128 + r0 + 8] = r1m;
            }
        }
        __syncthreads();
        if (tid < 128) {
            float mt = fmaxf(fmaxf(sRed[tid], sRed[128 + tid]),
                             fmaxf(sRed[256 + tid], sRed[384 + tid]));
            float mo = sM[tid];
            float mn = fmaxf(mo, mt);
            sAl[tid] = __expf(mo - mn);
            sM[tid] = mn;
        }
        __syncthreads();

#pragma unroll
        for (int mi = 0; mi < 4; mi++) {
            int r0 = wm * 64 + mi * 16 + gid;
            float m0 = sM[r0], m1 = sM[r0 + 8];
            float rs0 = 0.f, rs1 = 0.f;
#pragma unroll
            for (int ni = 0; ni < 4; ni++) {
                int c0 = wn * 32 + ni * 8 + tig * 2;
                float p00 = __expf(sacc[mi][ni][0] - m0);
                float p01 = __expf(sacc[mi][ni][1] - m0);
                float p10 = __expf(sacc[mi][ni][2] - m1);
                float p11 = __expf(sacc[mi][ni][3] - m1);
                rs0 += p00 + p01;
                rs1 += p10 + p11;
                *(__half2*)&sP[r0 * 136 + c0] = __floats2half2_rn(p00, p01);
                *(__half2*)&sP[(r0 + 8) * 136 + c0] = __floats2half2_rn(p10, p11);
            }
            rs0 += __shfl_xor_sync(0xffffffffu, rs0, 1);
            rs0 += __shfl_xor_sync(0xffffffffu, rs0, 2);
            rs1 += __shfl_xor_sync(0xffffffffu, rs1, 1);
            rs1 += __shfl_xor_sync(0xffffffffu, rs1, 2);
            if (tig == 0) {
                sRed[wn * 128 + r0] = rs0;
                sRed[wn * 128 + r0 + 8] = rs1;
            }
        }
        __syncthreads();
        if (tid < 128) {
            sL[tid] = sL[tid] * sAl[tid] +
                      (sRed[tid] + sRed[128 + tid]) + (sRed[256 + tid] + sRed[384 + tid]);
        }

#pragma unroll
        for (int mi = 0; mi < 4; mi++) {
            int r0 = wm * 64 + mi * 16 + gid;
            float a0 = sAl[r0], a1 = sAl[r0 + 8];
#pragma unroll
            for (int ni = 0; ni < 2; ni++) {
                oacc[mi][ni][0] *= a0;
                oacc[mi][ni][1] *= a0;
                oacc[mi][ni][2] *= a1;
                oacc[mi][ni][3] *= a1;
            }
        }

#pragma unroll
        for (int ks = 0; ks < 8; ks++) {
            const int k = ks * 16;
            uint32_t af[4][4], bf[2][2];
#pragma unroll
            for (int mi = 0; mi < 4; mi++) {
                int r0 = wm * 64 + mi * 16 + l15;
                ldsm4(af[mi], smu + FAB_P + (uint32_t)(r0 * 136 + k + ah) * 2);
            }
#pragma unroll
            for (int ni = 0; ni < 2; ni++) {
                int n0 = wn * 16 + ni * 8;
                ldsm2t(bf[ni], smu + FAB_V + (uint32_t)((k + l15) * 72 + n0) * 2);
            }
#pragma unroll
            for (int mi = 0; mi < 4; mi++)
#pragma unroll
                for (int ni = 0; ni < 2; ni++)
                    mma16(oacc[mi][ni], af[mi], bf[ni]);
        }
    }
    __syncthreads();

#pragma unroll
    for (int mi = 0; mi < 4; mi++) {
        int r0 = wm * 64 + mi * 16 + gid;
        float i0 = 1.f / sL[r0], i1 = 1.f / sL[r0 + 8];
        long o0 = ((long)bb * TT + q0 + r0) * H + hh * DHD;
        long o1 = ((long)bb * TT + q0 + r0 + 8) * H + hh * DHD;
#pragma unroll
        for (int ni = 0; ni < 2; ni++) {
            int c0 = wn * 16 + ni * 8 + tig * 2;
            *(__half2*)&att[o0 + c0] = __floats2half2_rn(oacc[mi][ni][0] * i0, oacc[mi][ni][1] * i0);
            *(__half2*)&att[o1 + c0] = __floats2half2_rn(oacc[mi][ni][2] * i1, oacc[mi][ni][3] * i1);
        }
    }
}

// ---------------- LayerNorm: fp32 in, fp16 out ----------------
__global__ void ln_k(const float* __restrict__ x, const float* __restrict__ g,
                     const float* __restrict__ b, __half* __restrict__ o)
{
    long row = blockIdx.x;
    int t = threadIdx.x;
    float4 v = ((const float4*)(x + row * H))[t];
    float s = v.x + v.y + v.z + v.w;
    float ss = v.x * v.x + v.y * v.y + v.z * v.z + v.w * v.w;
#pragma unroll
    for (int off = 16; off; off >>= 1) {
        s += __shfl_xor_sync(0xffffffffu, s, off);
        ss += __shfl_xor_sync(0xffffffffu, ss, off);
    }
    __shared__ float sm0[4], sm1[4];
    int w = t >> 5;
    if ((t & 31) == 0) { sm0[w] = s; sm1[w] = ss; }
    __syncthreads();
    s = sm0[0] + sm0[1] + sm0[2] + sm0[3];
    ss = sm1[0] + sm1[1] + sm1[2] + sm1[3];
    float mean = s * (1.f / H);
    float var = ss * (1.f / H) - mean * mean;
    float rstd = rsqrtf(var + 1e-5f);
    float4 gg = ((const float4*)g)[t];
    float4 bb4 = ((const float4*)b)[t];
    __half2* op = (__half2*)(o + row * H);
    op[t * 2]     = __floats2half2_rn((v.x - mean) * rstd * gg.x + bb4.x,
                                      (v.y - mean) * rstd * gg.y + bb4.y);
    op[t * 2 + 1] = __floats2half2_rn((v.z - mean) * rstd * gg.z + bb4.z,
                                      (v.w - mean) * rstd * gg.w + bb4.w);
}

// ---------------- misc kernels ----------------
__global__ void cvth_k(const float* __restrict__ in, __half* __restrict__ out, int n4)
{
    int stride = gridDim.x * blockDim.x;
    for (int i = blockIdx.x * blockDim.x + threadIdx.x; i < n4; i += stride) {
        float4 v = ((const float4*)in)[i];
        ((__half2*)out)[i * 2]     = __floats2half2_rn(v.x, v.y);
        ((__half2*)out)[i * 2 + 1] = __floats2half2_rn(v.z, v.w);
    }
}

__global__ void pe_k(float* __restrict__ pe)
{
    int t = blockIdx.x;
    int i = threadIdx.x;
    float div = expf(-(float)(2 * i) * (logf(10000.f) / (float)H));
    float a = (float)t * div;
    pe[t * H + 2 * i] = sinf(a);
    pe[t * H + 2 * i + 1] = cosf(a);
}

__global__ void convT_k(const float* __restrict__ w, __half* __restrict__ o)
{
    int idx = blockIdx.x * blockDim.x + threadIdx.x;
    if (idx >= 4 * H * H) return;
    int k = idx / (H * H);
    int d = (idx / H) % H;
    int c = idx % H;
    o[idx] = __float2half_rn(w[c * H * 4 + d * 4 + k]);
}

__global__ void xinit_k(const float* __restrict__ qe, const float* __restrict__ pe,
                        float* __restrict__ x)
{
    long i = blockIdx.x * (long)blockDim.x + threadIdx.x;
    if (i >= (long)BB * TT * H) return;
    int td = (int)(i % (TT * H));
    x[i] = qe[td] + pe[td];
}

__global__ void kin_k(const float* __restrict__ ho, float* __restrict__ out)
{
    int row = blockIdx.x * blockDim.x + threadIdx.x;
    if (row >= BB * TT) return;
    const float* r = ho + (long)row * NOUT;
    float* o = out + (long)row * (3 * NJ);
    float gx[NJ], px[NJ], py[NJ];
    gx[0] = 0.f;
    px[0] = r[100];
    py[0] = r[101];
    o[0] = px[0]; o[1] = py[0]; o[2] = 1.f;
    for (int j = 1; j < NJ; j++) {
        int pa = PAR[j];
        float gg = gx[pa] + r[j];
        gx[j] = gg;
        float s = r[50 + j];
        float sn, cs;
        sincosf(gg, &sn, &cs);
        px[j] = px[pa] + cs * s;
        py[j] = py[pa] + sn * s;
        o[j * 3 + 0] = px[j];
        o[j * 3 + 1] = py[j];
        o[j * 3 + 2] = 1.f;
    }
}

// ---------------- launcher ----------------
static inline dim3 gg128(int M, int N, int bz = 1)
{
    return dim3((N + 127) / 128, (M + 127) / 128, bz);
}

#define SMEM_G8 110592   // 3 stages x 36864 B

extern "C" void kernel_launch(void* const* d_in, const int* in_sizes, int n_in,
                              void* d_out, int out_size)
{
    const float* memory   = (const float*)d_in[0];
    const float* in_w     = (const float*)d_in[1];
    const float* in_b     = (const float*)d_in[2];
    const float* conv_w   = (const float*)d_in[3];
    const float* conv_b   = (const float*)d_in[4];
    const float* qemb     = (const float*)d_in[5];
    const float* sa_in_w  = (const float*)d_in[6];
    const float* sa_in_b  = (const float*)d_in[7];
    const float* sa_out_w = (const float*)d_in[8];
    const float* sa_out_b = (const float*)d_in[9];
    const float* ca_in_w  = (const float*)d_in[10];
    const float* ca_in_b  = (const float*)d_in[11];
    const float* ca_out_w = (const float*)d_in[12];
    const float* ca_out_b = (const float*)d_in[13];
    const float* ln1_g    = (const float*)d_in[14];
    const float* ln1_b    = (const float*)d_in[15];
    const float* ln2_g    = (const float*)d_in[16];
    const float* ln2_b    = (const float*)d_in[17];
    const float* ln3_g    = (const float*)d_in[18];
    const float* ln3_b    = (const float*)d_in[19];
    const float* ff1_w    = (const float*)d_in[20];
    const float* ff1_b    = (const float*)d_in[21];
    const float* ff2_w    = (const float*)d_in[22];
    const float* ff2_b    = (const float*)d_in[23];
    const float* out_w    = (const float*)d_in[24];
    const float* out_b    = (const float*)d_in[25];

    __half *memh_, *m_, *mem_, *xh_, *h_, *qkv_, *att_, *ff_, *cT_, *inwh_, *outwh_, *wt_;
    float *x_, *ho_, *pe_;
    cudaGetSymbolAddress((void**)&memh_, g_memh);
    cudaGetSymbolAddress((void**)&m_,    g_m);
    cudaGetSymbolAddress((void**)&mem_,  g_mem);
    cudaGetSymbolAddress((void**)&x_,    g_x);
    cudaGetSymbolAddress((void**)&xh_,   g_xh);
    cudaGetSymbolAddress((void**)&h_,    g_h);
    cudaGetSymbolAddress((void**)&qkv_,  g_qkv);
    cudaGetSymbolAddress((void**)&att_,  g_att);
    cudaGetSymbolAddress((void**)&ff_,   g_ff);
    cudaGetSymbolAddress((void**)&ho_,   g_head);
    cudaGetSymbolAddress((void**)&pe_,   g_pe);
    cudaGetSymbolAddress((void**)&cT_,   g_convTh);
    cudaGetSymbolAddress((void**)&inwh_, g_inwh);
    cudaGetSymbolAddress((void**)&outwh_,g_outwh);
    cudaGetSymbolAddress((void**)&wt_,   g_wth);

    cudaFuncSetAttribute(gemm8<EPI_BIAS,      true,  true,  false, false>, cudaFuncAttributeMaxDynamicSharedMemorySize, SMEM_G8);
    cudaFuncSetAttribute(gemm8<EPI_BIAS,      true,  true,  false, true >, cudaFuncAttributeMaxDynamicSharedMemorySize, SMEM_G8);
    cudaFuncSetAttribute(gemm8<EPI_BIAS,      true,  false, false, false>, cudaFuncAttributeMaxDynamicSharedMemorySize, SMEM_G8);
    cudaFuncSetAttribute(gemm8<EPI_CONV,      true,  false, false, false>, cudaFuncAttributeMaxDynamicSharedMemorySize, SMEM_G8);
    cudaFuncSetAttribute(gemm8<EPI_BIAS_RES,  false, false, false, false>, cudaFuncAttributeMaxDynamicSharedMemorySize, SMEM_G8);
    cudaFuncSetAttribute(gemm8<EPI_BIAS_RES,  false, false, true,  false>, cudaFuncAttributeMaxDynamicSharedMemorySize, SMEM_G8);
    cudaFuncSetAttribute(gemm8<EPI_BIAS_GELU, true,  false, false, false>, cudaFuncAttributeMaxDynamicSharedMemorySize, SMEM_G8);
    cudaFuncSetAttribute(gemm8<EPI_BIAS,      false, false, false, false>, cudaFuncAttributeMaxDynamicSharedMemorySize, SMEM_G8);
    cudaFuncSetAttribute(fattn_k, cudaFuncAttributeMaxDynamicSharedMemorySize, FA_BYTES);

    // prep
    pe_k<<<TT, 256>>>(pe_);
    convT_k<<<(4 * H * H + 255) / 256, 256>>>(conv_w, cT_);
    cvth_k<<<1024, 512>>>(memory,   memh_,  2097152 / 4);
    cvth_k<<<512, 512>>>(in_w,      inwh_,  262144 / 4);
    cvth_k<<<32, 512>>>(out_w,      outwh_, 52224 / 4);
    cvth_k<<<1536, 512>>>(sa_in_w,  wt_ + WOFF_SAIN,  3145728 / 4);
    cvth_k<<<512, 512>>>(sa_out_w,  wt_ + WOFF_SAOUT, 1048576 / 4);
    cvth_k<<<1536, 512>>>(ca_in_w,  wt_ + WOFF_CAIN,  3145728 / 4);
    cvth_k<<<512, 512>>>(ca_out_w,  wt_ + WOFF_CAOUT, 1048576 / 4);
    cvth_k<<<2048, 512>>>(ff1_w,    wt_ + WOFF_FF1,   4194304 / 4);
    cvth_k<<<2048, 512>>>(ff2_w,    wt_ + WOFF_FF2,   4194304 / 4);

    // m = memory @ in_w^T + in_b
    gemm8<EPI_BIAS, true, false, false, false><<<gg128(BB * SS, H), 256, SMEM_G8>>>(
        memh_, nullptr, inwh_, in_b, nullptr, m_, nullptr,
        BB * SS, H, H, H, H, H, 0L, 1);

    // conv upsample (4 taps batched over z; tap = hh)
    gemm8<EPI_CONV, true, false, false, false><<<gg128(BB * SS, H, 4), 256, SMEM_G8>>>(
        m_, nullptr, cT_, conv_b, pe_, mem_, nullptr,
        BB * SS, H, H, H, H, H, (long)H * H, 4);

    xinit_k<<<(BB * TT * H + 255) / 256, 256>>>(qemb, pe_, x_);

    const dim3 fa_grid(TT / 128, BB * NHEAD);

    for (int l = 0; l < NL; l++) {
        // ======== self-attention ========
        ln_k<<<BB * TT, 128>>>(x_, ln1_g + l * H, ln1_b + l * H, h_);
        gemm8<EPI_BIAS, true, true, false, false><<<gg128(BB * TT, 3 * H), 256, SMEM_G8>>>(
            h_, nullptr, wt_ + WOFF_SAIN + (long)l * 3 * H * H, sa_in_b + (long)l * 3 * H,
            nullptr, qkv_, nullptr,
            BB * TT, 3 * H, H, H, H, 3 * H, 0L, 1);
        fattn_k<<<fa_grid, 256, FA_BYTES>>>(qkv_, att_);
        gemm8<EPI_BIAS_RES, false, false, false, false><<<gg128(BB * TT, H), 256, SMEM_G8>>>(
            att_, nullptr, wt_ + WOFF_SAOUT + (long)l * H * H, sa_out_b + (long)l * H,
            x_, x_, nullptr,
            BB * TT, H, H, H, H, H, 0L, 1);

        // ======== cross-attention (merged q + kv projection) ========
        ln_k<<<BB * TT, 128>>>(x_, ln2_g + l * H, ln2_b + l * H, h_);
        gemm8<EPI_BIAS, true, true, false, true><<<gg128(BB * TT, 3 * H), 256, SMEM_G8>>>(
            h_, mem_, wt_ + WOFF_CAIN + (long)l * 3 * H * H, ca_in_b + (long)l * 3 * H,
            nullptr, qkv_, nullptr,
            BB * TT, 3 * H, H, H, H, 3 * H, 0L, 1);
        fattn_k<<<fa_grid, 256, FA_BYTES>>>(qkv_, att_);
        gemm8<EPI_BIAS_RES, false, false, false, false><<<gg128(BB * TT, H), 256, SMEM_G8>>>(
            att_, nullptr, wt_ + WOFF_CAOUT + (long)l * H * H, ca_out_b + (long)l * H,
            x_, x_, nullptr,
            BB * TT, H, H, H, H, H, 0L, 1);

        // ======== FFN ========
        ln_k<<<BB * TT, 128>>>(x_, ln3_g + l * H, ln3_b + l * H, h_);
        gemm8<EPI_BIAS_GELU, true, false, false, false><<<gg128(BB * TT, FF), 256, SMEM_G8>>>(
            h_, nullptr, wt_ + WOFF_FF1 + (long)l * FF * H, ff1_b + (long)l * FF,
            nullptr, ff_, nullptr,
            BB * TT, FF, H, H, H, FF, 0L, 1);
        if (l < NL - 1) {
            gemm8<EPI_BIAS_RES, false, false, false, false><<<gg128(BB * TT, H), 256, SMEM_G8>>>(
                ff_, nullptr, wt_ + WOFF_FF2 + (long)l * H * FF, ff2_b + (long)l * H,
                x_, x_, nullptr,
                BB * TT, H, FF, FF, FF, H, 0L, 1);
        } else {
            gemm8<EPI_BIAS_RES, false, false, true, false><<<gg128(BB * TT, H), 256, SMEM_G8>>>(
                ff_, nullptr, wt_ + WOFF_FF2 + (long)l * H * FF, ff2_b + (long)l * H,
                x_, x_, xh_,
                BB * TT, H, FF, FF, FF, H, 0L, 1);
        }
    }

    // head
    gemm8<EPI_BIAS, false, false, false, false><<<gg128(BB * TT, NOUT), 256, SMEM_G8>>>(
        xh_, nullptr, outwh_, out_b, nullptr, ho_, nullptr,
        BB * TT, NOUT, H, H, H, NOUT, 0L, 1);

    kin_k<<<(BB * TT + 255) / 256, 256>>>(ho_, (float*)d_out);
}

// round 17
// speedup vs baseline: 1.1991x; 1.0447x over previous
#include <cuda_runtime.h>
#include <cuda_fp16.h>
#include <math.h>
#include <stdint.h>

#define H 512
#define BB 32
#define SS 128
#define TT 512
#define NHEAD 8
#define DHD 64
#define NL 4
#define FF 2048
#define NOUT 102
#define NJ 50

// ---------------- scratch ----------------
__device__ __half g_memh[BB * SS * H];
__device__ __half g_m[BB * SS * H];
__device__ __half g_mem[BB * TT * H];
__device__ float  g_x[BB * TT * H];
__device__ __half g_xh[BB * TT * H];
__device__ __half g_h[BB * TT * H];
__device__ __half g_qkv[BB * TT * 3 * H];
__device__ __half g_att[BB * TT * H];
__device__ __half g_ff[BB * TT * FF];
__device__ float  g_head[BB * TT * NOUT];
__device__ float  g_pe[TT * H];
__device__ __half g_convTh[4 * H * H];
__device__ __half g_inwh[H * H];
__device__ __half g_outwh[NOUT * H];
__device__ __half g_wth[16777216];

#define WOFF_SAIN  0
#define WOFF_SAOUT 3145728
#define WOFF_CAIN  4194304
#define WOFF_CAOUT 7340032
#define WOFF_FF1   8388608
#define WOFF_FF2   12582912

__constant__ int PAR[NJ] = {
    -1, 0, 1, 2, 3, 1, 5, 6, 1,
    4, 9, 10, 11,  4, 13, 14, 15,  4, 17, 18, 19,  4, 21, 22, 23,  4, 25, 26, 27,
    7, 29, 30, 31, 7, 33, 34, 35,  7, 37, 38, 39,  7, 41, 42, 43,  7, 45, 46, 47,
    8
};

#define EPI_BIAS 2
#define EPI_BIAS_RES 3
#define EPI_BIAS_GELU 4
#define EPI_CONV 5

// ---------------- ptx helpers ----------------
__device__ __forceinline__ void cp16(uint32_t dst, const void* src)
{
    asm volatile("cp.async.cg.shared.global [%0], [%1], 16;\n" :: "r"(dst), "l"(src));
}
__device__ __forceinline__ void cp16z(uint32_t dst, const void* src, bool p)
{
    int sz = p ? 16 : 0;
    asm volatile("cp.async.cg.shared.global [%0], [%1], 16, %2;\n"
                 :: "r"(dst), "l"(src), "r"(sz));
}
__device__ __forceinline__ void cpcommit()
{
    asm volatile("cp.async.commit_group;\n" ::: "memory");
}
template <int W>
__device__ __forceinline__ void cpwait()
{
    asm volatile("cp.async.wait_group %0;\n" :: "n"(W) : "memory");
}
__device__ __forceinline__ void mma16(float* d, const uint32_t* a, const uint32_t* b)
{
    asm volatile(
        "mma.sync.aligned.m16n8k16.row.col.f32.f16.f16.f32 "
        "{%0,%1,%2,%3}, {%4,%5,%6,%7}, {%8,%9}, {%0,%1,%2,%3};\n"
        : "+f"(d[0]), "+f"(d[1]), "+f"(d[2]), "+f"(d[3])
        : "r"(a[0]), "r"(a[1]), "r"(a[2]), "r"(a[3]), "r"(b[0]), "r"(b[1]));
}
__device__ __forceinline__ void ldsm4(uint32_t* r, uint32_t addr)
{
    asm volatile("ldmatrix.sync.aligned.m8n8.x4.shared.b16 {%0,%1,%2,%3}, [%4];\n"
                 : "=r"(r[0]), "=r"(r[1]), "=r"(r[2]), "=r"(r[3]) : "r"(addr));
}
__device__ __forceinline__ void ldsm4t(uint32_t* r, uint32_t addr)
{
    asm volatile("ldmatrix.sync.aligned.m8n8.x4.trans.shared.b16 {%0,%1,%2,%3}, [%4];\n"
                 : "=r"(r[0]), "=r"(r[1]), "=r"(r[2]), "=r"(r[3]) : "r"(addr));
}
__device__ __forceinline__ uint32_t pk2(float a, float b)
{
    __half2 h = __floats2half2_rn(a, b);
    return *(uint32_t*)&h;
}

// ---------------- fp16 tensor-core GEMM: BK=64, 3-stage, m16n8k16, 256 thr ----------------
template <int EPI, bool HOUT, bool QS, bool DUAL, bool MIX>
__global__ void __launch_bounds__(256, 2) gemm8(
    const __half* __restrict__ A, const __half* __restrict__ A2,
    const __half* __restrict__ Bm,
    const float* __restrict__ bias, const float* __restrict__ resid,
    void* __restrict__ C, __half* __restrict__ C2,
    int M, int N, int K, int lda, int ldb, int ldc,
    long sBh, int nh)
{
    constexpr int BM = 128, BN_ = 128, BK = 64;
    constexpr int LDE = BK + 8;
    constexpr int STGH = BM * LDE * 2;
    constexpr int CH = BM * BK / 8 / 256;
    constexpr int NST = 3;

    extern __shared__ char smc[];
    const uint32_t smu = (uint32_t)__cvta_generic_to_shared(smc);

    const int z = blockIdx.z;
    const int hh = z % nh;
    Bm += (long)hh * sBh;

    const int row0 = blockIdx.y * BM;
    const int col0 = blockIdx.x * BN_;
    const __half* Ause = (MIX && col0 >= H) ? A2 : A;

    const int tid = threadIdx.x;
    const int warp = tid >> 5;
    const int lane = tid & 31;
    const int wm = warp >> 2;
    const int wn = warp & 3;
    const int gid = lane >> 2;
    const int tig = lane & 3;
    const int l15 = lane & 15;
    const int ah = (lane >> 4) << 3;

    float acc[4][4][4];
#pragma unroll
    for (int i = 0; i < 4; i++)
#pragma unroll
        for (int j = 0; j < 4; j++)
#pragma unroll
            for (int q = 0; q < 4; q++) acc[i][j][q] = 0.f;

    auto cpTile = [&](int k0, int st) {
        uint32_t abase = smu + (uint32_t)(st * STGH) * 2;
#pragma unroll
        for (int l = 0; l < CH; l++) {
            int idx = l * 256 + tid;
            int r = idx >> 3;
            int cq = (idx & 7) * 8;
            cp16(abase + (uint32_t)(r * LDE + cq) * 2,
                 Ause + (long)(row0 + r) * lda + k0 + cq);
        }
        uint32_t bbase = abase + (uint32_t)(BM * LDE) * 2;
#pragma unroll
        for (int l = 0; l < CH; l++) {
            int idx = l * 256 + tid;
            int n = idx >> 3;
            int cq = (idx & 7) * 8;
            cp16z(bbase + (uint32_t)(n * LDE + cq) * 2,
                  Bm + (long)(col0 + n) * ldb + k0 + cq,
                  (col0 + n) < N);
        }
        cpcommit();
    };

    auto compute = [&](int st) {
        const uint32_t pAu = smu + (uint32_t)(st * STGH) * 2;
        const uint32_t pBu = pAu + (uint32_t)(BM * LDE) * 2;
#pragma unroll
        for (int ks = 0; ks < 4; ks++) {
            const int k = ks * 16;
            uint32_t af[4][4], bf[4][2];
#pragma unroll
            for (int mi = 0; mi < 4; mi++) {
                int r0 = wm * 64 + mi * 16 + l15;
                ldsm4(af[mi], pAu + (uint32_t)(r0 * LDE + k + ah) * 2);
            }
#pragma unroll
            for (int pb = 0; pb < 2; pb++) {
                uint32_t q[4];
                int n0 = wn * 32 + pb * 16 + l15;
                ldsm4(q, pBu + (uint32_t)(n0 * LDE + k + ah) * 2);
                bf[pb * 2][0] = q[0];     bf[pb * 2][1] = q[2];
                bf[pb * 2 + 1][0] = q[1]; bf[pb * 2 + 1][1] = q[3];
            }
#pragma unroll
            for (int mi = 0; mi < 4; mi++)
#pragma unroll
                for (int ni = 0; ni < 4; ni++)
                    mma16(acc[mi][ni], af[mi], bf[ni]);
        }
    };

    const int nt = K / BK;
    cpTile(0, 0);
    cpTile(BK, 1);
    int st = 0;
    for (int t = 0; t < nt; t++) {
        if (t < nt - 1) cpwait<1>(); else cpwait<0>();
        __syncthreads();
        if (t + 2 < nt) {
            int st2 = st + 2; if (st2 >= NST) st2 -= NST;
            cpTile((t + 2) * BK, st2);
        }
        compute(st);
        if (++st == NST) st = 0;
    }

    auto emit2 = [&](int r, int c, float v0, float v1) {
        v0 += bias[c];
        v1 += bias[c + 1];
        if (QS && c < H) { v0 *= 0.125f; v1 *= 0.125f; }
        if (EPI == EPI_BIAS_GELU) {
            v0 = 0.5f * v0 * (1.f + erff(v0 * 0.70710678118654752f));
            v1 = 0.5f * v1 * (1.f + erff(v1 * 0.70710678118654752f));
        }
        long idx;
        if (EPI == EPI_CONV) {
            int b_ = r >> 7;
            int s_ = r & 127;
            int t_ = s_ * 4 + hh;
            float2 rv = *(const float2*)&resid[t_ * H + c];
            v0 += rv.x; v1 += rv.y;
            idx = ((long)b_ * TT + t_) * ldc + c;
        } else {
            idx = (long)r * ldc + c;
            if (EPI == EPI_BIAS_RES) {
                float2 rv = *(const float2*)&resid[idx];
                v0 += rv.x; v1 += rv.y;
            }
        }
        if (HOUT) *(__half2*)((__half*)C + idx) = __floats2half2_rn(v0, v1);
        else      *(float2*)((float*)C + idx) = make_float2(v0, v1);
        if (DUAL) *(__half2*)(C2 + idx) = __floats2half2_rn(v0, v1);
    };

#pragma unroll
    for (int mi = 0; mi < 4; mi++) {
        int r0 = row0 + wm * 64 + mi * 16 + gid;
#pragma unroll
        for (int ni = 0; ni < 4; ni++) {
            int c0 = col0 + wn * 32 + ni * 8 + tig * 2;
            if (c0 < N) {
                emit2(r0,     c0, acc[mi][ni][0], acc[mi][ni][1]);
                emit2(r0 + 8, c0, acc[mi][ni][2], acc[mi][ni][3]);
            }
        }
    }
}

// ---------------- register-resident flash attention ----------------
// 8 warps x 16 rows each; softmax state in registers; P never touches smem.
// Q + double-buffered K/V. q arrives pre-scaled by 1/8.
#define FAB_Q 0
#define FAB_KV 18432          // K at 18432 + b*36864; V at 36864 + b*36864
#define FA_BYTES 92160

__global__ void __launch_bounds__(256, 2) fattn_k(
    const __half* __restrict__ qkv, __half* __restrict__ att)
{
    extern __shared__ char smc[];
    const uint32_t smu = (uint32_t)__cvta_generic_to_shared(smc);

    const int z = blockIdx.y;
    const int bb = z >> 3, hh = z & 7;
    const int q0 = blockIdx.x * 128;
    const long base = (long)bb * TT * 3 * H + (long)hh * DHD;

    const int tid = threadIdx.x;
    const int warp = tid >> 5, lane = tid & 31;
    const int gid = lane >> 2, tig = lane & 3;
    const int l15 = lane & 15;
    const int ah = (lane >> 4) << 3;

    // load Q (128 x 64 halves, pitch 72)
#pragma unroll
    for (int l = 0; l < 4; l++) {
        int idx = l * 256 + tid;
        int r = idx >> 3, c8 = (idx & 7) * 8;
        cp16(smu + FAB_Q + (uint32_t)(r * 72 + c8) * 2,
             qkv + base + (long)(q0 + r) * (3 * H) + c8);
    }
    cpcommit();
    // load KV tile 0 into buffer 0
#pragma unroll
    for (int l = 0; l < 4; l++) {
        int idx = l * 256 + tid;
        int r = idx >> 3, c8 = (idx & 7) * 8;
        long row = (long)r * (3 * H);
        cp16(smu + 18432 + (uint32_t)(r * 72 + c8) * 2, qkv + base + H + row + c8);
        cp16(smu + 36864 + (uint32_t)(r * 72 + c8) * 2, qkv + base + 2 * H + row + c8);
    }
    cpcommit();

    float m0 = -1e30f, m1 = -1e30f, l0 = 0.f, l1 = 0.f;
    float oacc[8][4];
#pragma unroll
    for (int ni = 0; ni < 8; ni++)
#pragma unroll
        for (int q = 0; q < 4; q++) oacc[ni][q] = 0.f;

    const uint32_t qaddr = smu + FAB_Q + (uint32_t)((warp * 16 + l15) * 72) * 2;

    for (int j = 0; j < 4; j++) {
        if (j > 0) __syncthreads();   // compute(j-1) done everywhere; buffer (j+1)&1 free
        if (j < 3) {
            const uint32_t dK = smu + 18432 + (uint32_t)(((j + 1) & 1) * 36864);
            const uint32_t dV = smu + 36864 + (uint32_t)(((j + 1) & 1) * 36864);
#pragma unroll
            for (int l = 0; l < 4; l++) {
                int idx = l * 256 + tid;
                int r = idx >> 3, c8 = (idx & 7) * 8;
                long row = (long)((j + 1) * 128 + r) * (3 * H);
                cp16(dK + (uint32_t)(r * 72 + c8) * 2, qkv + base + H + row + c8);
                cp16(dV + (uint32_t)(r * 72 + c8) * 2, qkv + base + 2 * H + row + c8);
            }
            cpcommit();
            cpwait<1>();   // tile j resident; j+1 in flight
        } else {
            cpwait<0>();
        }
        __syncthreads();   // tile j (and Q on j=0) visible

        const uint32_t KB = smu + 18432 + (uint32_t)((j & 1) * 36864);
        const uint32_t VB = smu + 36864 + (uint32_t)((j & 1) * 36864);

        // ---- S = Q K^T : warp-local 16x128 ----
        float sacc[16][4];
#pragma unroll
        for (int ni = 0; ni < 16; ni++)
#pragma unroll
            for (int q = 0; q < 4; q++) sacc[ni][q] = 0.f;
#pragma unroll
        for (int ks = 0; ks < 4; ks++) {
            const int k = ks * 16;
            uint32_t af[4];
            ldsm4(af, qaddr + (uint32_t)(k + ah) * 2);
#pragma unroll
            for (int pb = 0; pb < 8; pb++) {
                uint32_t q[4];
                ldsm4(q, KB + (uint32_t)((pb * 16 + l15) * 72 + k + ah) * 2);
                uint32_t bfA[2] = { q[0], q[2] };
                mma16(sacc[pb * 2], af, bfA);
                uint32_t bfB[2] = { q[1], q[3] };
                mma16(sacc[pb * 2 + 1], af, bfB);
            }
        }

        // ---- online softmax (registers + 2 shfl) ----
        float tm0 = -1e30f, tm1 = -1e30f;
#pragma unroll
        for (int ni = 0; ni < 16; ni++) {
            tm0 = fmaxf(tm0, fmaxf(sacc[ni][0], sacc[ni][1]));
            tm1 = fmaxf(tm1, fmaxf(sacc[ni][2], sacc[ni][3]));
        }
        tm0 = fmaxf(tm0, __shfl_xor_sync(0xffffffffu, tm0, 1));
        tm0 = fmaxf(tm0, __shfl_xor_sync(0xffffffffu, tm0, 2));
        tm1 = fmaxf(tm1, __shfl_xor_sync(0xffffffffu, tm1, 1));
        tm1 = fmaxf(tm1, __shfl_xor_sync(0xffffffffu, tm1, 2));
        float nm0 = fmaxf(m0, tm0), nm1 = fmaxf(m1, tm1);
        float al0 = __expf(m0 - nm0), al1 = __expf(m1 - nm1);
        m0 = nm0; m1 = nm1;

        float rs0 = 0.f, rs1 = 0.f;
#pragma unroll
        for (int ni = 0; ni < 16; ni++) {
            sacc[ni][0] = __expf(sacc[ni][0] - m0);
            sacc[ni][1] = __expf(sacc[ni][1] - m0);
            sacc[ni][2] = __expf(sacc[ni][2] - m1);
            sacc[ni][3] = __expf(sacc[ni][3] - m1);
            rs0 += sacc[ni][0] + sacc[ni][1];
            rs1 += sacc[ni][2] + sacc[ni][3];
        }
        rs0 += __shfl_xor_sync(0xffffffffu, rs0, 1);
        rs0 += __shfl_xor_sync(0xffffffffu, rs0, 2);
        rs1 += __shfl_xor_sync(0xffffffffu, rs1, 1);
        rs1 += __shfl_xor_sync(0xffffffffu, rs1, 2);
        l0 = l0 * al0 + rs0;
        l1 = l1 * al1 + rs1;

#pragma unroll
        for (int ni = 0; ni < 8; ni++) {
            oacc[ni][0] *= al0;
            oacc[ni][1] *= al0;
            oacc[ni][2] *= al1;
            oacc[ni][3] *= al1;
        }

        // ---- O += P @ V : P fragments straight from sacc registers ----
#pragma unroll
        for (int kk = 0; kk < 8; kk++) {
            const int k = kk * 16;
            uint32_t af2[4];
            af2[0] = pk2(sacc[2 * kk][0],     sacc[2 * kk][1]);
            af2[1] = pk2(sacc[2 * kk][2],     sacc[2 * kk][3]);
            af2[2] = pk2(sacc[2 * kk + 1][0], sacc[2 * kk + 1][1]);
            af2[3] = pk2(sacc[2 * kk + 1][2], sacc[2 * kk + 1][3]);
#pragma unroll
            for (int nb = 0; nb < 4; nb++) {
                uint32_t q[4];
                ldsm4t(q, VB + (uint32_t)((k + l15) * 72 + nb * 16 + ah) * 2);
                uint32_t bfA[2] = { q[0], q[1] };
                mma16(oacc[2 * nb], af2, bfA);
                uint32_t bfB[2] = { q[2], q[3] };
                mma16(oacc[2 * nb + 1], af2, bfB);
            }
        }
    }

    // ---- O /= l, write half ----
    const float i0 = 1.f / l0, i1 = 1.f / l1;
    const int r0 = q0 + warp * 16 + gid;
    const long o0 = ((long)bb * TT + r0) * H + hh * DHD;
    const long o1 = o0 + 8L * H;
#pragma unroll
    for (int ni = 0; ni < 8; ni++) {
        int c0 = ni * 8 + tig * 2;
        *(__half2*)&att[o0 + c0] = __floats2half2_rn(oacc[ni][0] * i0, oacc[ni][1] * i0);
        *(__half2*)&att[o1 + c0] = __floats2half2_rn(oacc[ni][2] * i1, oacc[ni][3] * i1);
    }
}

// ---------------- LayerNorm: fp32 in, fp16 out ----------------
__global__ void ln_k(const float* __restrict__ x, const float* __restrict__ g,
                     const float* __restrict__ b, __half* __restrict__ o)
{
    long row = blockIdx.x;
    int t = threadIdx.x;
    float4 v = ((const float4*)(x + row * H))[t];
    float s = v.x + v.y + v.z + v.w;
    float ss = v.x * v.x + v.y * v.y + v.z * v.z + v.w * v.w;
#pragma unroll
    for (int off = 16; off; off >>= 1) {
        s += __shfl_xor_sync(0xffffffffu, s, off);
        ss += __shfl_xor_sync(0xffffffffu, ss, off);
    }
    __shared__ float sm0[4], sm1[4];
    int w = t >> 5;
    if ((t & 31) == 0) { sm0[w] = s; sm1[w] = ss; }
    __syncthreads();
    s = sm0[0] + sm0[1] + sm0[2] + sm0[3];
    ss = sm1[0] + sm1[1] + sm1[2] + sm1[3];
    float mean = s * (1.f / H);
    float var = ss * (1.f / H) - mean * mean;
    float rstd = rsqrtf(var + 1e-5f);
    float4 gg = ((const float4*)g)[t];
    float4 bb4 = ((const float4*)b)[t];
    __half2* op = (__half2*)(o + row * H);
    op[t * 2]     = __floats2half2_rn((v.x - mean) * rstd * gg.x + bb4.x,
                                      (v.y - mean) * rstd * gg.y + bb4.y);
    op[t * 2 + 1] = __floats2half2_rn((v.z - mean) * rstd * gg.z + bb4.z,
                                      (v.w - mean) * rstd * gg.w + bb4.w);
}

// ---------------- misc kernels ----------------
__global__ void cvth_k(const float* __restrict__ in, __half* __restrict__ out, int n4)
{
    int stride = gridDim.x * blockDim.x;
    for (int i = blockIdx.x * blockDim.x + threadIdx.x; i < n4; i += stride) {
        float4 v = ((const float4*)in)[i];
        ((__half2*)out)[i * 2]     = __floats2half2_rn(v.x, v.y);
        ((__half2*)out)[i * 2 + 1] = __floats2half2_rn(v.z, v.w);
    }
}

__global__ void pe_k(float* __restrict__ pe)
{
    int t = blockIdx.x;
    int i = threadIdx.x;
    float div = expf(-(float)(2 * i) * (logf(10000.f) / (float)H));
    float a = (float)t * div;
    pe[t * H + 2 * i] = sinf(a);
    pe[t * H + 2 * i + 1] = cosf(a);
}

__global__ void convT_k(const float* __restrict__ w, __half* __restrict__ o)
{
    int idx = blockIdx.x * blockDim.x + threadIdx.x;
    if (idx >= 4 * H * H) return;
    int k = idx / (H * H);
    int d = (idx / H) % H;
    int c = idx % H;
    o[idx] = __float2half_rn(w[c * H * 4 + d * 4 + k]);
}

__global__ void xinit_k(const float* __restrict__ qe, const float* __restrict__ pe,
                        float* __restrict__ x)
{
    long i = blockIdx.x * (long)blockDim.x + threadIdx.x;
    if (i >= (long)BB * TT * H) return;
    int td = (int)(i % (TT * H));
    x[i] = qe[td] + pe[td];
}

__global__ void kin_k(const float* __restrict__ ho, float* __restrict__ out)
{
    int row = blockIdx.x * blockDim.x + threadIdx.x;
    if (row >= BB * TT) return;
    const float* r = ho + (long)row * NOUT;
    float* o = out + (long)row * (3 * NJ);
    float gx[NJ], px[NJ], py[NJ];
    gx[0] = 0.f;
    px[0] = r[100];
    py[0] = r[101];
    o[0] = px[0]; o[1] = py[0]; o[2] = 1.f;
    for (int j = 1; j < NJ; j++) {
        int pa = PAR[j];
        float gg = gx[pa] + r[j];
        gx[j] = gg;
        float s = r[50 + j];
        float sn, cs;
        sincosf(gg, &sn, &cs);
        px[j] = px[pa] + cs * s;
        py[j] = py[pa] + sn * s;
        o[j * 3 + 0] = px[j];
        o[j * 3 + 1] = py[j];
        o[j * 3 + 2] = 1.f;
    }
}

// ---------------- launcher ----------------
static inline dim3 gg128(int M, int N, int bz = 1)
{
    return dim3((N + 127) / 128, (M + 127) / 128, bz);
}

#define SMEM_G8 110592   // 3 stages x 36864 B

extern "C" void kernel_launch(void* const* d_in, const int* in_sizes, int n_in,
                              void* d_out, int out_size)
{
    const float* memory   = (const float*)d_in[0];
    const float* in_w     = (const float*)d_in[1];
    const float* in_b     = (const float*)d_in[2];
    const float* conv_w   = (const float*)d_in[3];
    const float* conv_b   = (const float*)d_in[4];
    const float* qemb     = (const float*)d_in[5];
    const float* sa_in_w  = (const float*)d_in[6];
    const float* sa_in_b  = (const float*)d_in[7];
    const float* sa_out_w = (const float*)d_in[8];
    const float* sa_out_b = (const float*)d_in[9];
    const float* ca_in_w  = (const float*)d_in[10];
    const float* ca_in_b  = (const float*)d_in[11];
    const float* ca_out_w = (const float*)d_in[12];
    const float* ca_out_b = (const float*)d_in[13];
    const float* ln1_g    = (const float*)d_in[14];
    const float* ln1_b    = (const float*)d_in[15];
    const float* ln2_g    = (const float*)d_in[16];
    const float* ln2_b    = (const float*)d_in[17];
    const float* ln3_g    = (const float*)d_in[18];
    const float* ln3_b    = (const float*)d_in[19];
    const float* ff1_w    = (const float*)d_in[20];
    const float* ff1_b    = (const float*)d_in[21];
    const float* ff2_w    = (const float*)d_in[22];
    const float* ff2_b    = (const float*)d_in[23];
    const float* out_w    = (const float*)d_in[24];
    const float* out_b    = (const float*)d_in[25];

    __half *memh_, *m_, *mem_, *xh_, *h_, *qkv_, *att_, *ff_, *cT_, *inwh_, *outwh_, *wt_;
    float *x_, *ho_, *pe_;
    cudaGetSymbolAddress((void**)&memh_, g_memh);
    cudaGetSymbolAddress((void**)&m_,    g_m);
    cudaGetSymbolAddress((void**)&mem_,  g_mem);
    cudaGetSymbolAddress((void**)&x_,    g_x);
    cudaGetSymbolAddress((void**)&xh_,   g_xh);
    cudaGetSymbolAddress((void**)&h_,    g_h);
    cudaGetSymbolAddress((void**)&qkv_,  g_qkv);
    cudaGetSymbolAddress((void**)&att_,  g_att);
    cudaGetSymbolAddress((void**)&ff_,   g_ff);
    cudaGetSymbolAddress((void**)&ho_,   g_head);
    cudaGetSymbolAddress((void**)&pe_,   g_pe);
    cudaGetSymbolAddress((void**)&cT_,   g_convTh);
    cudaGetSymbolAddress((void**)&inwh_, g_inwh);
    cudaGetSymbolAddress((void**)&outwh_,g_outwh);
    cudaGetSymbolAddress((void**)&wt_,   g_wth);

    cudaFuncSetAttribute(gemm8<EPI_BIAS,      true,  true,  false, false>, cudaFuncAttributeMaxDynamicSharedMemorySize, SMEM_G8);
    cudaFuncSetAttribute(gemm8<EPI_BIAS,      true,  true,  false, true >, cudaFuncAttributeMaxDynamicSharedMemorySize, SMEM_G8);
    cudaFuncSetAttribute(gemm8<EPI_BIAS,      true,  false, false, false>, cudaFuncAttributeMaxDynamicSharedMemorySize, SMEM_G8);
    cudaFuncSetAttribute(gemm8<EPI_CONV,      true,  false, false, false>, cudaFuncAttributeMaxDynamicSharedMemorySize, SMEM_G8);
    cudaFuncSetAttribute(gemm8<EPI_BIAS_RES,  false, false, false, false>, cudaFuncAttributeMaxDynamicSharedMemorySize, SMEM_G8);
    cudaFuncSetAttribute(gemm8<EPI_BIAS_RES,  false, false, true,  false>, cudaFuncAttributeMaxDynamicSharedMemorySize, SMEM_G8);
    cudaFuncSetAttribute(gemm8<EPI_BIAS_GELU, true,  false, false, false>, cudaFuncAttributeMaxDynamicSharedMemorySize, SMEM_G8);
    cudaFuncSetAttribute(gemm8<EPI_BIAS,      false, false, false, false>, cudaFuncAttributeMaxDynamicSharedMemorySize, SMEM_G8);
    cudaFuncSetAttribute(fattn_k, cudaFuncAttributeMaxDynamicSharedMemorySize, FA_BYTES);

    // prep
    pe_k<<<TT, 256>>>(pe_);
    convT_k<<<(4 * H * H + 255) / 256, 256>>>(conv_w, cT_);
    cvth_k<<<1024, 512>>>(memory,   memh_,  2097152 / 4);
    cvth_k<<<512, 512>>>(in_w,      inwh_,  262144 / 4);
    cvth_k<<<32, 512>>>(out_w,      outwh_, 52224 / 4);
    cvth_k<<<1536, 512>>>(sa_in_w,  wt_ + WOFF_SAIN,  3145728 / 4);
    cvth_k<<<512, 512>>>(sa_out_w,  wt_ + WOFF_SAOUT, 1048576 / 4);
    cvth_k<<<1536, 512>>>(ca_in_w,  wt_ + WOFF_CAIN,  3145728 / 4);
    cvth_k<<<512, 512>>>(ca_out_w,  wt_ + WOFF_CAOUT, 1048576 / 4);
    cvth_k<<<2048, 512>>>(ff1_w,    wt_ + WOFF_FF1,   4194304 / 4);
    cvth_k<<<2048, 512>>>(ff2_w,    wt_ + WOFF_FF2,   4194304 / 4);

    // m = memory @ in_w^T + in_b
    gemm8<EPI_BIAS, true, false, false, false><<<gg128(BB * SS, H), 256, SMEM_G8>>>(
        memh_, nullptr, inwh_, in_b, nullptr, m_, nullptr,
        BB * SS, H, H, H, H, H, 0L, 1);

    // conv upsample (4 taps batched over z; tap = hh)
    gemm8<EPI_CONV, true, false, false, false><<<gg128(BB * SS, H, 4), 256, SMEM_G8>>>(
        m_, nullptr, cT_, conv_b, pe_, mem_, nullptr,
        BB * SS, H, H, H, H, H, (long)H * H, 4);

    xinit_k<<<(BB * TT * H + 255) / 256, 256>>>(qemb, pe_, x_);

    const dim3 fa_grid(TT / 128, BB * NHEAD);

    for (int l = 0; l < NL; l++) {
        // ======== self-attention ========
        ln_k<<<BB * TT, 128>>>(x_, ln1_g + l * H, ln1_b + l * H, h_);
        gemm8<EPI_BIAS, true, true, false, false><<<gg128(BB * TT, 3 * H), 256, SMEM_G8>>>(
            h_, nullptr, wt_ + WOFF_SAIN + (long)l * 3 * H * H, sa_in_b + (long)l * 3 * H,
            nullptr, qkv_, nullptr,
            BB * TT, 3 * H, H, H, H, 3 * H, 0L, 1);
        fattn_k<<<fa_grid, 256, FA_BYTES>>>(qkv_, att_);
        gemm8<EPI_BIAS_RES, false, false, false, false><<<gg128(BB * TT, H), 256, SMEM_G8>>>(
            att_, nullptr, wt_ + WOFF_SAOUT + (long)l * H * H, sa_out_b + (long)l * H,
            x_, x_, nullptr,
            BB * TT, H, H, H, H, H, 0L, 1);

        // ======== cross-attention (merged q + kv projection) ========
        ln_k<<<BB * TT, 128>>>(x_, ln2_g + l * H, ln2_b + l * H, h_);
        gemm8<EPI_BIAS, true, true, false, true><<<gg128(BB * TT, 3 * H), 256, SMEM_G8>>>(
            h_, mem_, wt_ + WOFF_CAIN + (long)l * 3 * H * H, ca_in_b + (long)l * 3 * H,
            nullptr, qkv_, nullptr,
            BB * TT, 3 * H, H, H, H, 3 * H, 0L, 1);
        fattn_k<<<fa_grid, 256, FA_BYTES>>>(qkv_, att_);
        gemm8<EPI_BIAS_RES, false, false, false, false><<<gg128(BB * TT, H), 256, SMEM_G8>>>(
            att_, nullptr, wt_ + WOFF_CAOUT + (long)l * H * H, ca_out_b + (long)l * H,
            x_, x_, nullptr,
            BB * TT, H, H, H, H, H, 0L, 1);

        // ======== FFN ========
        ln_k<<<BB * TT, 128>>>(x_, ln3_g + l * H, ln3_b + l * H, h_);
        gemm8<EPI_BIAS_GELU, true, false, false, false><<<gg128(BB * TT, FF), 256, SMEM_G8>>>(
            h_, nullptr, wt_ + WOFF_FF1 + (long)l * FF * H, ff1_b + (long)l * FF,
            nullptr, ff_, nullptr,
            BB * TT, FF, H, H, H, FF, 0L, 1);
        if (l < NL - 1) {
            gemm8<EPI_BIAS_RES, false, false, false, false><<<gg128(BB * TT, H), 256, SMEM_G8>>>(
                ff_, nullptr, wt_ + WOFF_FF2 + (long)l * H * FF, ff2_b + (long)l * H,
                x_, x_, nullptr,
                BB * TT, H, FF, FF, FF, H, 0L, 1);
        } else {
            gemm8<EPI_BIAS_RES, false, false, true, false><<<gg128(BB * TT, H), 256, SMEM_G8>>>(
                ff_, nullptr, wt_ + WOFF_FF2 + (long)l * H * FF, ff2_b + (long)l * H,
                x_, x_, xh_,
                BB * TT, H, FF, FF, FF, H, 0L, 1);
        }
    }

    // head
    gemm8<EPI_BIAS, false, false, false, false><<<gg128(BB * TT, NOUT), 256, SMEM_G8>>>(
        xh_, nullptr, outwh_, out_b, nullptr, ho_, nullptr,
        BB * TT, NOUT, H, H, H, NOUT, 0L, 1);

    kin_k<<<(BB * TT + 255) / 256, 256>>>(ho_, (float*)d_out);
}